// round 5
// baseline (speedup 1.0000x reference)
#include <cuda_runtime.h>
#include <math.h>

#define BB 64
#define SS 256
#define II 512
#define HH 80
#define TT 600
#define CC 512
#define XD 592          /* HH + II */
#define KCAT 1104       /* XD + CC */
#define NCOLS 2048      /* gate-interleaved: 4 gates x 512 channels */
#define GRID 128
#define NTHR 256

// ---------------- device scratch ----------------
__device__ float g_xc[BB][XD];         // [frame 80 | prev 512]
__device__ float g_q[2][BB][CC];       // ping-pong GRU state
__device__ float g_wcat[NCOLS][KCAT];  // repacked, gate-interleaved GRU weights
__device__ float g_t1[BB][CC];
__device__ float g_dk[BB][168];
__device__ float g_energy[BB][SS];
__device__ float g_alpha[BB][SS];
__device__ unsigned g_bar, g_go;

__device__ __forceinline__ float sig_fast(float x) { return 1.f / (1.f + __expf(-x)); }
__device__ __forceinline__ float tanh_fast(float x) {
    float e = __expf(2.f * x);
    return 1.f - 2.f / (e + 1.f);
}
// packed f32x2 FMA (Blackwell): d = a*b + d  (2 independent fp32 FMAs)
__device__ __forceinline__ void fma2(unsigned long long& d, unsigned long long a,
                                     unsigned long long b) {
    asm("fma.rn.f32x2 %0, %1, %2, %0;" : "+l"(d) : "l"(a), "l"(b));
}

// grid barrier: release-arrive on counter, last arriver releases flag, acquire-poll
__device__ __forceinline__ void gsync(unsigned& gen) {
    gen++;
    __syncthreads();
    if (threadIdx.x == 0) {
        unsigned old;
        asm volatile("atom.add.release.gpu.global.u32 %0, [%1], 1;"
                     : "=r"(old) : "l"(&g_bar) : "memory");
        if (old == gen * GRID - 1u) {
            asm volatile("st.release.gpu.global.u32 [%0], %1;"
                         :: "l"(&g_go), "r"(gen) : "memory");
        } else {
            unsigned v;
            do {
                asm volatile("ld.acquire.gpu.global.u32 %0, [%1];"
                             : "=r"(v) : "l"(&g_go) : "memory");
            } while (v < gen);
        }
    }
    __syncthreads();
}

// ---------------- init: reset, zero state, gate-interleaved weight repack -----
__global__ void k_init(const float* __restrict__ wi, const float* __restrict__ wh) {
    int idx = blockIdx.x * blockDim.x + threadIdx.x;
    if (idx == 0) { g_bar = 0u; g_go = 0u; }
    if (idx < BB * CC) {
        int b = idx >> 9, c = idx & 511;
        g_q[0][b][c] = 0.f;
    }
    int stride = gridDim.x * blockDim.x;
    for (size_t i = idx; i < (size_t)NCOLS * KCAT; i += stride) {
        int n = (int)(i / KCAT), k = (int)(i % KCAT);
        int bq = n >> 4, v = n & 15, j = v >> 2, g = v & 3;
        int c = bq * 4 + j;
        float val;
        if (g == 0)      val = (k < XD) ? wi[(size_t)c * XD + k] : wh[(size_t)c * CC + (k - XD)];
        else if (g == 1) val = (k < XD) ? wi[(size_t)(512 + c) * XD + k] : wh[(size_t)(512 + c) * CC + (k - XD)];
        else if (g == 2) val = (k < XD) ? wi[(size_t)(1024 + c) * XD + k] : 0.f;
        else             val = (k < XD) ? 0.f : wh[(size_t)(1024 + c) * CC + (k - XD)];
        g_wcat[n][k] = val;
    }
}

// ---------------- the persistent kernel ----------------
__global__ void __launch_bounds__(NTHR)
k_persist(const float* __restrict__ enc, const float* __restrict__ gt,
          const float* __restrict__ mask,
          const float* __restrict__ bi, const float* __restrict__ bh,
          const float* __restrict__ w1, const float* __restrict__ b1,
          const float* __restrict__ w2,
          const float* __restrict__ lw, const float* __restrict__ lp,
          const float* __restrict__ dw, const float* __restrict__ db,
          const float* __restrict__ aw, const float* __restrict__ prior,
          float* __restrict__ out) {
    __shared__ __align__(16) float sm[9600];
    unsigned gen = 0;
    int bid = blockIdx.x, tid = threadIdx.x;
    int lane = tid & 31, wrp = tid >> 5;

    for (int t = 0;; t++) {
        int cur = t & 1, nxt = cur ^ 1;

        // ========== Phase A: softmax(energy) -> alpha -> out row t-1 -> prev ==
        {
            int b = bid >> 1, half = bid & 1;
            float* s_alpha = sm;         // 256
            float* s_red   = sm + 256;   // 8
            float* s_part  = sm + 272;   // 1024, 16B aligned

            float a;
            if (t == 0) {
                a = (tid == 0) ? 1.f : 0.f;
            } else {
                float e = __ldcg(&g_energy[b][tid]);
                float m = e;
                #pragma unroll
                for (int o = 16; o; o >>= 1) m = fmaxf(m, __shfl_xor_sync(0xffffffffu, m, o));
                if (lane == 0) s_red[wrp] = m;
                __syncthreads();
                float bm = s_red[0];
                #pragma unroll
                for (int i = 1; i < 8; i++) bm = fmaxf(bm, s_red[i]);
                float p = __expf(e - bm);
                float ws = p;
                #pragma unroll
                for (int o = 16; o; o >>= 1) ws += __shfl_xor_sync(0xffffffffu, ws, o);
                __syncthreads();
                if (lane == 0) s_red[wrp] = ws;
                __syncthreads();
                float tot = 0.f;
                #pragma unroll
                for (int i = 0; i < 8; i++) tot += s_red[i];
                a = p / tot;
                if (half == 0) out[((size_t)b * TT + (t - 1)) * SS + tid] = a;
            }
            s_alpha[tid] = a;
            if (half == 0) g_alpha[b][tid] = a;
            __syncthreads();

            if (t == TT) break;

            if (half == 0 && tid < HH)
                g_xc[b][tid] = gt[((size_t)b * TT + t) * HH + tid];

            int cs = tid & 63, sl = tid >> 6;
            int c = half * 256 + cs * 4;
            const float* ep = enc + (size_t)b * SS * II + c;
            float4 acc = make_float4(0.f, 0.f, 0.f, 0.f);
            #pragma unroll 8
            for (int s = sl * 64; s < sl * 64 + 64; s++) {
                float av = s_alpha[s];
                float4 ev = *(const float4*)&ep[(size_t)s * II];
                acc.x = fmaf(av, ev.x, acc.x);
                acc.y = fmaf(av, ev.y, acc.y);
                acc.z = fmaf(av, ev.z, acc.z);
                acc.w = fmaf(av, ev.w, acc.w);
            }
            *(float4*)&s_part[(sl * 64 + cs) * 4] = acc;
            __syncthreads();
            if (tid < 64) {
                float4 r = *(const float4*)&s_part[tid * 4];
                #pragma unroll
                for (int ks = 1; ks < 4; ks++) {
                    float4 v = *(const float4*)&s_part[(ks * 64 + tid) * 4];
                    r.x += v.x; r.y += v.y; r.z += v.z; r.w += v.w;
                }
                *(float4*)&g_xc[b][HH + half * 256 + tid * 4] = r;
            }
        }
        gsync(gen);

        // ========== Phase B: GRU GEMM (f32x2) + fused gates -> g_q[nxt] =======
        {
            int col0 = bid * 16;
            float*  sxs = sm;                      // 2 x 48*68 = 6528
            float2* sws = (float2*)&sm[6528];      // 2 x 48*16 float2 = 3072 floats
            int ks = tid >> 6, r = tid & 63, ty = r >> 2, tx = r & 3;
            unsigned long long a2[2][4] = {{0ull,0ull,0ull,0ull},{0ull,0ull,0ull,0ull}};

            float rx[12], rw[3];
            // prefetch chunk 0
            #pragma unroll
            for (int it = 0; it < 12; it++) {
                int idx = tid + it * 256;
                int rr = idx / 48, kk = idx - rr * 48;
                rx[it] = (kk < XD) ? __ldcg(&g_xc[rr][kk]) : __ldcg(&g_q[cur][rr][kk - XD]);
            }
            #pragma unroll
            for (int it = 0; it < 3; it++) {
                int idx = tid + it * 256;
                int rr = idx / 48, kk = idx - rr * 48;
                rw[it] = g_wcat[col0 + rr][kk];
            }
            for (int ch = 0; ch < 23; ch++) {
                int buf = ch & 1;
                float*  xb = sxs + buf * 3264;
                float2* wb = sws + buf * 768;
                #pragma unroll
                for (int it = 0; it < 12; it++) {
                    int idx = tid + it * 256;
                    int rr = idx / 48, kk = idx - rr * 48;
                    xb[kk * 68 + rr] = rx[it];
                }
                #pragma unroll
                for (int it = 0; it < 3; it++) {
                    int idx = tid + it * 256;
                    int rr = idx / 48, kk = idx - rr * 48;
                    wb[kk * 16 + rr] = make_float2(rw[it], rw[it]);
                }
                __syncthreads();
                if (ch + 1 < 23) {
                    int kc = (ch + 1) * 48;
                    #pragma unroll
                    for (int it = 0; it < 12; it++) {
                        int idx = tid + it * 256;
                        int rr = idx / 48, kk = kc + (idx - rr * 48);
                        rx[it] = (kk < XD) ? __ldcg(&g_xc[rr][kk]) : __ldcg(&g_q[cur][rr][kk - XD]);
                    }
                    #pragma unroll
                    for (int it = 0; it < 3; it++) {
                        int idx = tid + it * 256;
                        int rr = idx / 48, kk = idx - rr * 48;
                        rw[it] = g_wcat[col0 + rr][kc + kk];
                    }
                }
                #pragma unroll
                for (int kk = 0; kk < 12; kk++) {
                    int k = ks * 12 + kk;
                    ulonglong2 xp = *(const ulonglong2*)&xb[k * 68 + ty * 4];
                    const ulonglong2* wrow = (const ulonglong2*)&wb[k * 16 + tx * 4];
                    ulonglong2 wp0 = wrow[0];
                    ulonglong2 wp1 = wrow[1];
                    fma2(a2[0][0], xp.x, wp0.x); fma2(a2[1][0], xp.y, wp0.x);
                    fma2(a2[0][1], xp.x, wp0.y); fma2(a2[1][1], xp.y, wp0.y);
                    fma2(a2[0][2], xp.x, wp1.x); fma2(a2[1][2], xp.y, wp1.x);
                    fma2(a2[0][3], xp.x, wp1.y); fma2(a2[1][3], xp.y, wp1.y);
                }
            }
            __syncthreads();
            float* red = sm;  // 4*64*18 = 4608
            int base = (ks * 64 + r) * 18;
            #pragma unroll
            for (int g = 0; g < 4; g++) {
                *(unsigned long long*)&red[base + g * 4 + 0] = a2[0][g];
                *(unsigned long long*)&red[base + g * 4 + 2] = a2[1][g];
            }
            __syncthreads();
            {
                int b = tid & 63, j = tid >> 6;
                int rr = (b >> 2) * 4 + j, i = b & 3;
                float G[4];
                #pragma unroll
                for (int g = 0; g < 4; g++)
                    G[g] = red[(0 * 64 + rr) * 18 + g * 4 + i]
                         + red[(1 * 64 + rr) * 18 + g * 4 + i]
                         + red[(2 * 64 + rr) * 18 + g * 4 + i]
                         + red[(3 * 64 + rr) * 18 + g * 4 + i];
                int c = bid * 4 + j;
                float rg = sig_fast(G[0] + bi[c] + bh[c]);
                float zg = sig_fast(G[1] + bi[512 + c] + bh[512 + c]);
                float ng = tanh_fast(G[2] + bi[1024 + c] + rg * (G[3] + bh[1024 + c]));
                float st = __ldcg(&g_q[cur][b][c]);
                g_q[nxt][b][c] = (1.f - zg) * ng + zg * st;
            }
        }
        gsync(gen);

        // ========== Phase D: t1 = tanh(q_new @ W1^T + b1), 4 cols/block =======
        {
            int col0 = bid * 4;
            float* sxs = sm;            // 2 x 64*68 = 8704
            float* sws = sm + 8704;     // 2 x 64*4  = 512
            int ks = tid >> 6, r = tid & 63, ty = r >> 2, tx = r & 3;
            float a0 = 0, a1 = 0, a2_ = 0, a3 = 0;

            float px[16], pw;
            #pragma unroll
            for (int it = 0; it < 16; it++) {
                int idx = tid + it * 256;
                px[it] = __ldcg(&g_q[nxt][idx >> 6][idx & 63]);
            }
            pw = w1[(size_t)(col0 + (tid & 3)) * CC + (tid >> 2)];
            for (int ch = 0; ch < 8; ch++) {
                int buf = ch & 1;
                float* xb = sxs + buf * 4352;
                float* wb = sws + buf * 256;
                #pragma unroll
                for (int it = 0; it < 16; it++) {
                    int idx = tid + it * 256;
                    xb[(idx & 63) * 68 + (idx >> 6)] = px[it];
                }
                wb[(tid >> 2) * 4 + (tid & 3)] = pw;
                __syncthreads();
                if (ch + 1 < 8) {
                    int kc = (ch + 1) * 64;
                    #pragma unroll
                    for (int it = 0; it < 16; it++) {
                        int idx = tid + it * 256;
                        px[it] = __ldcg(&g_q[nxt][idx >> 6][kc + (idx & 63)]);
                    }
                    pw = w1[(size_t)(col0 + (tid & 3)) * CC + kc + (tid >> 2)];
                }
                #pragma unroll
                for (int kk = 0; kk < 16; kk++) {
                    int k = ks * 16 + kk;
                    float4 xv = *(const float4*)&xb[k * 68 + ty * 4];
                    float w = wb[k * 4 + tx];
                    a0 = fmaf(xv.x, w, a0); a1 = fmaf(xv.y, w, a1);
                    a2_ = fmaf(xv.z, w, a2_); a3 = fmaf(xv.w, w, a3);
                }
            }
            __syncthreads();
            float* red = sm;  // 4*64*5 = 1280
            int base = (ks * 64 + r) * 5;
            red[base] = a0; red[base + 1] = a1; red[base + 2] = a2_; red[base + 3] = a3;
            __syncthreads();
            {
                int rr = tid >> 2, i = tid & 3;
                float v = red[rr * 5 + i] + red[(64 + rr) * 5 + i]
                        + red[(128 + rr) * 5 + i] + red[(192 + rr) * 5 + i];
                int b = (rr >> 2) * 4 + i, c = col0 + (rr & 3);
                g_t1[b][c] = tanh_fast(v + b1[c]);
            }
        }
        gsync(gen);

        // ========== Phase E: dk = t1 @ W2^T, 2 cols/block (84 active) =========
        {
            int col0 = bid * 2;
            bool active = (col0 < 168);
            if (active) {
                float* sxs = sm;
                float* sws = sm + 8704;   // 2 x 64*2 = 256
                int ks = tid >> 6, r = tid & 63, ty = r >> 1, tx = r & 1;
                float a0 = 0, a1 = 0;

                float px[16], pw;
                #pragma unroll
                for (int it = 0; it < 16; it++) {
                    int idx = tid + it * 256;
                    px[it] = __ldcg(&g_t1[idx >> 6][idx & 63]);
                }
                pw = (tid < 128) ? w2[(size_t)(col0 + (tid & 1)) * CC + (tid >> 1)] : 0.f;
                for (int ch = 0; ch < 8; ch++) {
                    int buf = ch & 1;
                    float* xb = sxs + buf * 4352;
                    float* wb = sws + buf * 128;
                    #pragma unroll
                    for (int it = 0; it < 16; it++) {
                        int idx = tid + it * 256;
                        xb[(idx & 63) * 68 + (idx >> 6)] = px[it];
                    }
                    if (tid < 128) wb[(tid >> 1) * 2 + (tid & 1)] = pw;
                    __syncthreads();
                    if (ch + 1 < 8) {
                        int kc = (ch + 1) * 64;
                        #pragma unroll
                        for (int it = 0; it < 16; it++) {
                            int idx = tid + it * 256;
                            px[it] = __ldcg(&g_t1[idx >> 6][kc + (idx & 63)]);
                        }
                        if (tid < 128) pw = w2[(size_t)(col0 + (tid & 1)) * CC + kc + (tid >> 1)];
                    }
                    #pragma unroll
                    for (int kk = 0; kk < 16; kk++) {
                        int k = ks * 16 + kk;
                        float2 xv = *(const float2*)&xb[k * 68 + ty * 2];
                        float w = wb[k * 2 + tx];
                        a0 = fmaf(xv.x, w, a0); a1 = fmaf(xv.y, w, a1);
                    }
                }
                __syncthreads();
                float* red = sm;  // 4*64*3 = 768
                int base = (ks * 64 + r) * 3;
                red[base] = a0; red[base + 1] = a1;
                __syncthreads();
                if (tid < 128) {
                    int rr = tid >> 1, i = tid & 1;
                    float v = red[rr * 3 + i] + red[(64 + rr) * 3 + i]
                            + red[(128 + rr) * 3 + i] + red[(192 + rr) * 3 + i];
                    int b = (rr >> 1) * 2 + i, c = col0 + (rr & 1);
                    g_dk[b][c] = v;
                }
            }
        }
        gsync(gen);

        // ========== Phase F: convs + score (f32x2) + energy ====================
        {
            int b = bid >> 1, shalf = bid & 1, s0 = shalf * 128;
            float* s_a   = sm;          // 148
            float* s_lw  = sm + 148;    // 168
            float* s_dkk = sm + 316;    // 168
            float* s_ft  = sm + 484;    // 128*16 = 2048 (16B aligned)
            float* s_pri = sm + 2532;   // 128
            float* s_en  = sm + 2660;   // 8*128 = 1024

            if (tid < 148) {
                int s = s0 - 10 + tid;
                s_a[tid] = (s >= 0 && s < SS) ? __ldcg(&g_alpha[b][s]) : 0.f;
            }
            if (tid < 168) {
                s_lw[tid]  = lw[tid];
                s_dkk[tid] = __ldcg(&g_dk[b][tid]);
            }
            __syncthreads();

            #pragma unroll
            for (int it = 0; it < 8; it++) {
                int idx = tid + it * 256;
                int l = idx & 15, si = idx >> 4;
                const float* wv = (l < 8) ? &s_lw[l * 21] : &s_dkk[(l - 8) * 21];
                float a = 0.f;
                #pragma unroll
                for (int k = 0; k < 21; k++) a = fmaf(s_a[si + k], wv[k], a);
                s_ft[si * 16 + l] = a;
            }
            if (tid < 128) {
                float a = 0.f;
                #pragma unroll
                for (int k = 0; k < 11; k++) a = fmaf(s_a[tid + k], prior[k], a);
                s_pri[tid] = a;
            }
            __syncthreads();

            int c = tid;
            ulonglong2 lpa = *(const ulonglong2*)&lp[c * 8];
            ulonglong2 lpb = *(const ulonglong2*)&lp[c * 8 + 4];
            ulonglong2 dwa = *(const ulonglong2*)&dw[c * 8];
            ulonglong2 dwb = *(const ulonglong2*)&dw[c * 8 + 4];
            float dbc = db[c], awc = aw[c];
            unsigned long long dbc2 = (unsigned long long)__float_as_uint(dbc);
            for (int si = 0; si < 128; si++) {
                const ulonglong2* fp = (const ulonglong2*)&s_ft[si * 16];
                ulonglong2 f01 = fp[0], f23 = fp[1];
                unsigned long long acc = dbc2;
                fma2(acc, lpa.x, f01.x); fma2(acc, lpa.y, f01.y);
                fma2(acc, lpb.x, f23.x); fma2(acc, lpb.y, f23.y);
                const ulonglong2* fq = (const ulonglong2*)&s_ft[si * 16 + 8];
                ulonglong2 f45 = fq[0], f67 = fq[1];
                fma2(acc, dwa.x, f45.x); fma2(acc, dwa.y, f45.y);
                fma2(acc, dwb.x, f67.x); fma2(acc, dwb.y, f67.y);
                float sc = __uint_as_float((unsigned)acc) +
                           __uint_as_float((unsigned)(acc >> 32));
                float v = awc * tanh_fast(sc);
                #pragma unroll
                for (int o = 16; o; o >>= 1) v += __shfl_xor_sync(0xffffffffu, v, o);
                if (lane == 0) s_en[wrp * 128 + si] = v;
            }
            __syncthreads();
            if (tid < 128) {
                float e = 0.f;
                #pragma unroll
                for (int i = 0; i < 8; i++) e += s_en[i * 128 + tid];
                e += __logf(s_pri[tid] + 1e-5f);
                int s = s0 + tid;
                e = (mask[b * SS + s] > 0.f) ? e : -INFINITY;
                g_energy[b][s] = e;
            }
        }
        gsync(gen);
    }
}

extern "C" void kernel_launch(void* const* d_in, const int* in_sizes, int n_in,
                              void* d_out, int out_size) {
    const float* enc   = (const float*)d_in[0];
    const float* mask  = (const float*)d_in[1];
    const float* gt    = (const float*)d_in[2];
    const float* wi    = (const float*)d_in[3];
    const float* wh    = (const float*)d_in[4];
    const float* bi    = (const float*)d_in[5];
    const float* bh    = (const float*)d_in[6];
    const float* lw    = (const float*)d_in[7];
    const float* lp    = (const float*)d_in[8];
    const float* w1    = (const float*)d_in[9];
    const float* b1    = (const float*)d_in[10];
    const float* w2    = (const float*)d_in[11];
    const float* dw    = (const float*)d_in[12];
    const float* db    = (const float*)d_in[13];
    const float* aw    = (const float*)d_in[14];
    const float* prior = (const float*)d_in[15];
    float* out = (float*)d_out;

    k_init<<<512, 256>>>(wi, wh);
    k_persist<<<GRID, NTHR>>>(enc, gt, mask, bi, bh, w1, b1, w2,
                              lw, lp, dw, db, aw, prior, out);
}

// round 6
// speedup vs baseline: 1.5465x; 1.5465x over previous
#include <cuda_runtime.h>
#include <math.h>

#define BB 64
#define SS 256
#define HH 80
#define TT 600
#define CC 512
#define KGRU 1104
#define GRID 128
#define NTHR 512

__device__ float g_xT[2][KGRU][BB];   // rows: [0,80) frame, [80,592) prev, [592,1104) q
__device__ float g_wT[KGRU][2048];    // k-major, col n = ch*4+gate
__device__ float g_w1T[CC][CC];
__device__ float g_w2T[CC][176];
__device__ float g_t1T[CC][BB];
__device__ float g_dk[BB][176];
__device__ float g_sp[256][20];       // [lp8 | dw8 | db | aw | pad2]
__device__ float g_energy[BB][SS];
__device__ float g_alpha[BB][SS];
__device__ unsigned g_fl[GRID * 8];
__device__ unsigned g_pf[GRID * 8];

__device__ __forceinline__ float sig_fast(float x) {
    return __fdividef(1.f, 1.f + __expf(-x));
}
__device__ __forceinline__ float tanh_fast(float x) {
    float e = __expf(2.f * x);
    return 1.f - __fdividef(2.f, e + 1.f);
}
__device__ __forceinline__ void st_rel(unsigned* p, unsigned v) {
    asm volatile("st.release.gpu.global.u32 [%0],%1;" :: "l"(p), "r"(v) : "memory");
}
__device__ __forceinline__ unsigned ld_acq(const unsigned* p) {
    unsigned v;
    asm volatile("ld.acquire.gpu.global.u32 %0,[%1];" : "=r"(v) : "l"(p) : "memory");
    return v;
}
__device__ __forceinline__ void gbar(int bid, int tid, unsigned gen) {
    __syncthreads();
    if (tid == 0) st_rel(&g_fl[bid * 8], gen);
    if (tid < GRID) { while (ld_acq(&g_fl[tid * 8]) < gen) {} }
    __syncthreads();
}
__device__ __forceinline__ void pbar(int bid, int tid, unsigned gen) {
    __syncthreads();
    if (tid == 0) {
        st_rel(&g_pf[bid * 8], gen);
        while (ld_acq(&g_pf[(bid ^ 1) * 8]) < gen) {}
    }
    __syncthreads();
}

__global__ void k_init(const float* wi, const float* wh, const float* w1,
                       const float* w2, const float* lp, const float* dw,
                       const float* db, const float* aw) {
    int idx = blockIdx.x * blockDim.x + threadIdx.x;
    int stride = gridDim.x * blockDim.x;
    for (int i = idx; i < KGRU * 2048; i += stride) {
        int k = i >> 11, n = i & 2047, ch = n >> 2, g = n & 3;
        float v = 0.f;
        if (k < 592) {
            if (g == 0) v = wi[ch * 592 + k];
            else if (g == 1) v = wi[(512 + ch) * 592 + k];
            else if (g == 2) v = wi[(1024 + ch) * 592 + k];
        } else {
            int kk = k - 592;
            if (g == 0) v = wh[ch * 512 + kk];
            else if (g == 1) v = wh[(512 + ch) * 512 + kk];
            else if (g == 3) v = wh[(1024 + ch) * 512 + kk];
        }
        g_wT[k][n] = v;
    }
    for (int i = idx; i < CC * CC; i += stride) {
        int k = i >> 9, c = i & 511;
        g_w1T[k][c] = w1[c * CC + k];
    }
    for (int i = idx; i < CC * 176; i += stride) {
        int k = i / 176, c = i % 176;
        g_w2T[k][c] = (c < 168) ? w2[c * CC + k] : 0.f;
    }
    for (int i = idx; i < 256 * 20; i += stride) {
        int c = i / 20, j = i % 20;
        float v = 0.f;
        if (j < 8) v = lp[c * 8 + j];
        else if (j < 16) v = dw[c * 8 + (j - 8)];
        else if (j == 16) v = db[c];
        else if (j == 17) v = aw[c];
        g_sp[c][j] = v;
    }
    for (int i = idx; i < 512 * 64; i += stride) g_xT[0][592 + i / 64][i % 64] = 0.f;
    for (int i = idx; i < GRID * 8; i += stride) { g_fl[i] = 0u; g_pf[i] = 0u; }
}

// generic small GEMM: dst = act(X^T @ W + bias), tile 64b x 4c, K=512, ksplit 8
__device__ __forceinline__ void gemm_ne(const float* __restrict__ X,
                                        const float* __restrict__ W, int wstride,
                                        int c0, const float* __restrict__ bias,
                                        float* __restrict__ dst, int dcs, int dbs,
                                        int act, float* sm, int tid) {
    float* xs = sm;            // [64][64]
    float* ws = sm + 4096;     // [64][4]
    int kz = tid >> 6, r = tid & 63, ty = r >> 2, tx = r & 3;
    float a0 = 0.f, a1 = 0.f, a2 = 0.f, a3 = 0.f;
    for (int kc = 0; kc < 512; kc += 64) {
        __syncthreads();
        #pragma unroll
        for (int it = 0; it < 2; it++) {
            int u = tid + it * 512;
            *(float4*)&xs[(u >> 4) * 64 + (u & 15) * 4] =
                *(const float4*)&X[(size_t)(kc + (u >> 4)) * 64 + (u & 15) * 4];
        }
        if (tid < 64)
            *(float4*)&ws[tid * 4] = *(const float4*)&W[(size_t)(kc + tid) * wstride + c0];
        __syncthreads();
        #pragma unroll
        for (int kk = 0; kk < 8; kk++) {
            int k = kz * 8 + kk;
            float4 xv = *(const float4*)&xs[k * 64 + ty * 4];
            float wv = ws[k * 4 + tx];
            a0 = fmaf(xv.x, wv, a0); a1 = fmaf(xv.y, wv, a1);
            a2 = fmaf(xv.z, wv, a2); a3 = fmaf(xv.w, wv, a3);
        }
    }
    __syncthreads();
    float* red = sm;  // [8][64][4]
    red[(kz * 64 + ty * 4 + 0) * 4 + tx] = a0;
    red[(kz * 64 + ty * 4 + 1) * 4 + tx] = a1;
    red[(kz * 64 + ty * 4 + 2) * 4 + tx] = a2;
    red[(kz * 64 + ty * 4 + 3) * 4 + tx] = a3;
    __syncthreads();
    if (tid < 256) {
        int b = tid >> 2, c4 = tid & 3;
        float v = 0.f;
        #pragma unroll
        for (int z = 0; z < 8; z++) v += red[(z * 64 + b) * 4 + c4];
        int c = c0 + c4;
        if (bias) v += bias[c];
        if (act) v = tanh_fast(v);
        dst[(size_t)c * dcs + (size_t)b * dbs] = v;
    }
}

__global__ void __launch_bounds__(NTHR)
k_persist(const float* __restrict__ enc, const float* __restrict__ gt,
          const float* __restrict__ mask,
          const float* __restrict__ bi, const float* __restrict__ bh,
          const float* __restrict__ b1,
          const float* __restrict__ lw, const float* __restrict__ prior,
          float* __restrict__ out) {
    __shared__ __align__(16) float sm[8704];
    int bid = blockIdx.x, tid = threadIdx.x;
    int lane = tid & 31, wrp = tid >> 5;

    for (int t = 0;; t++) {
        int buf = t & 1, nbuf = buf ^ 1;
        if (t > 0) pbar(bid, tid, (unsigned)t);

        // ===== Phase A: softmax(energy) -> alpha, out[t-1], frame+prev ========
        {
            int b = bid >> 1, half = bid & 1;
            float* s_al  = sm;          // 256
            float* s_red = sm + 256;    // 8
            float* s_pt  = sm + 768;    // 512

            float a = 0.f;
            if (t == 0) {
                if (tid < 256) a = (tid == 0) ? 1.f : 0.f;
            } else if (tid < 256) {
                float e = g_energy[b][tid];
                float m = e;
                #pragma unroll
                for (int o = 16; o; o >>= 1) m = fmaxf(m, __shfl_xor_sync(0xffffffffu, m, o));
                if (lane == 0) s_red[wrp] = m;
            }
            __syncthreads();
            if (t > 0 && tid < 256) {
                float bm = s_red[0];
                #pragma unroll
                for (int i = 1; i < 8; i++) bm = fmaxf(bm, s_red[i]);
                float p = __expf(g_energy[b][tid] - bm);
                float ws = p;
                #pragma unroll
                for (int o = 16; o; o >>= 1) ws += __shfl_xor_sync(0xffffffffu, ws, o);
                if (lane == 0) s_red[wrp] = ws;
                a = p;
            }
            __syncthreads();
            if (tid < 256) {
                if (t > 0) {
                    float tot = 0.f;
                    #pragma unroll
                    for (int i = 0; i < 8; i++) tot += s_red[i];
                    a = __fdividef(a, tot);
                    if (half == 0) out[((size_t)b * TT + (t - 1)) * SS + tid] = a;
                }
                s_al[tid] = a;
                if (half == 0) g_alpha[b][tid] = a;
            }
            __syncthreads();
            if (t == TT) break;

            if (half == 0 && tid < HH)
                g_xT[buf][tid][b] = gt[((size_t)b * TT + t) * HH + tid];

            int col = tid & 255, slab = tid >> 8;
            int c = half * 256 + col;
            const float* ep = enc + ((size_t)b * SS + slab * 128) * 512 + c;
            float acc = 0.f;
            #pragma unroll 4
            for (int s = 0; s < 128; s++)
                acc = fmaf(s_al[slab * 128 + s], ep[(size_t)s * 512], acc);
            s_pt[tid] = acc;
            __syncthreads();
            if (tid < 256)
                g_xT[buf][HH + c][b] = s_pt[tid] + s_pt[256 + tid];
        }
        gbar(bid, tid, (unsigned)t * 4u + 1u);

        // ===== Phase B: GRU GEMM 32b x 32c x 1104k + fused gates ==============
        {
            int cg = bid >> 1, bt = bid & 1, b0 = bt * 32, c0 = cg * 32;
            float* xs = sm;          // [2][48][32]
            float* ws = sm + 3072;   // [2][48][32]
            int kz = tid >> 6, r = tid & 63, ty = r >> 3, tx = r & 7;
            float acc[4][4];
            #pragma unroll
            for (int i = 0; i < 4; i++)
                #pragma unroll
                for (int j = 0; j < 4; j++) acc[i][j] = 0.f;

            float4 rx, rw;
            if (tid < 384) rx = *(const float4*)&g_xT[buf][tid >> 3][b0 + (tid & 7) * 4];
            if (tid >= 128) {
                int u = tid - 128;
                rw = *(const float4*)&g_wT[u >> 3][c0 + (u & 7) * 4];
            }
            for (int ch = 0; ch < 23; ch++) {
                float* xb = xs + (ch & 1) * 1536;
                float* wb = ws + (ch & 1) * 1536;
                if (tid < 384) *(float4*)&xb[(tid >> 3) * 32 + (tid & 7) * 4] = rx;
                if (tid >= 128) {
                    int u = tid - 128;
                    *(float4*)&wb[(u >> 3) * 32 + (u & 7) * 4] = rw;
                }
                __syncthreads();
                if (ch + 1 < 23) {
                    int kc = (ch + 1) * 48;
                    if (tid < 384)
                        rx = *(const float4*)&g_xT[buf][kc + (tid >> 3)][b0 + (tid & 7) * 4];
                    if (tid >= 128) {
                        int u = tid - 128;
                        rw = *(const float4*)&g_wT[kc + (u >> 3)][c0 + (u & 7) * 4];
                    }
                }
                #pragma unroll
                for (int kk = 0; kk < 6; kk++) {
                    int k = kz * 6 + kk;
                    float4 xv = *(const float4*)&xb[k * 32 + ty * 4];
                    float4 wv = *(const float4*)&wb[k * 32 + tx * 4];
                    acc[0][0] = fmaf(xv.x, wv.x, acc[0][0]);
                    acc[0][1] = fmaf(xv.x, wv.y, acc[0][1]);
                    acc[0][2] = fmaf(xv.x, wv.z, acc[0][2]);
                    acc[0][3] = fmaf(xv.x, wv.w, acc[0][3]);
                    acc[1][0] = fmaf(xv.y, wv.x, acc[1][0]);
                    acc[1][1] = fmaf(xv.y, wv.y, acc[1][1]);
                    acc[1][2] = fmaf(xv.y, wv.z, acc[1][2]);
                    acc[1][3] = fmaf(xv.y, wv.w, acc[1][3]);
                    acc[2][0] = fmaf(xv.z, wv.x, acc[2][0]);
                    acc[2][1] = fmaf(xv.z, wv.y, acc[2][1]);
                    acc[2][2] = fmaf(xv.z, wv.z, acc[2][2]);
                    acc[2][3] = fmaf(xv.z, wv.w, acc[2][3]);
                    acc[3][0] = fmaf(xv.w, wv.x, acc[3][0]);
                    acc[3][1] = fmaf(xv.w, wv.y, acc[3][1]);
                    acc[3][2] = fmaf(xv.w, wv.z, acc[3][2]);
                    acc[3][3] = fmaf(xv.w, wv.w, acc[3][3]);
                }
            }
            __syncthreads();
            float* red = sm;  // [8][32][32]
            #pragma unroll
            for (int i = 0; i < 4; i++)
                *(float4*)&red[(kz * 32 + ty * 4 + i) * 32 + tx * 4] =
                    make_float4(acc[i][0], acc[i][1], acc[i][2], acc[i][3]);
            __syncthreads();
            if (tid < 256) {
                int bl = tid & 31, chn = tid >> 5;
                float G[4] = {0.f, 0.f, 0.f, 0.f};
                #pragma unroll
                for (int z = 0; z < 8; z++) {
                    float4 v = *(const float4*)&red[(z * 32 + bl) * 32 + chn * 4];
                    G[0] += v.x; G[1] += v.y; G[2] += v.z; G[3] += v.w;
                }
                int ch2 = cg * 8 + chn, bb2 = b0 + bl;
                float qold = g_xT[buf][592 + ch2][bb2];
                float rg = sig_fast(G[0] + bi[ch2] + bh[ch2]);
                float zg = sig_fast(G[1] + bi[512 + ch2] + bh[512 + ch2]);
                float ng = tanh_fast(G[2] + bi[1024 + ch2] + rg * (G[3] + bh[1024 + ch2]));
                g_xT[nbuf][592 + ch2][bb2] = (1.f - zg) * ng + zg * qold;
            }
        }
        gbar(bid, tid, (unsigned)t * 4u + 2u);

        // ===== Phase D: t1T = tanh(q @ w1^T + b1), 4 cols/block (128 blocks) ==
        gemm_ne(&g_xT[nbuf][592][0], &g_w1T[0][0], 512, bid * 4, b1,
                &g_t1T[0][0], 64, 1, 1, sm, tid);
        gbar(bid, tid, (unsigned)t * 4u + 3u);

        // ===== Phase E: dk = t1 @ w2^T, 4 cols/block (42 blocks) ===============
        if (bid < 42)
            gemm_ne(&g_t1T[0][0], &g_w2T[0][0], 176, bid * 4, (const float*)0,
                    &g_dk[0][0], 1, 176, 0, sm, tid);
        gbar(bid, tid, (unsigned)t * 4u + 4u);

        // ===== Phase F: convs + score + energy =================================
        {
            int b = bid >> 1, half = bid & 1, s0 = half * 128;
            float* s_a   = sm;          // 148 (pad 160)
            float* s_lw  = sm + 160;    // 168
            float* s_dkk = sm + 336;    // 168 (pad to 512)
            float* s_ft  = sm + 512;    // 128*16
            float* s_pri = sm + 2560;   // 128
            float* s_sp  = sm + 2688;   // 256*20
            float* s_ps  = sm + 7808;   // 4*128

            if (tid < 148) {
                int s = s0 - 10 + tid;
                s_a[tid] = (s >= 0 && s < SS) ? g_alpha[b][s] : 0.f;
            }
            if (tid >= 160 && tid < 328) s_lw[tid - 160] = lw[tid - 160];
            if (tid >= 328 && tid < 496) s_dkk[tid - 328] = g_dk[b][tid - 328];
            #pragma unroll
            for (int it = 0; it < 10; it++)
                s_sp[tid + it * 512] = ((const float*)g_sp)[tid + it * 512];
            __syncthreads();

            #pragma unroll
            for (int it = 0; it < 4; it++) {
                int u = tid + it * 512;
                int l = u & 15, si = u >> 4;
                const float* wv = (l < 8) ? &s_lw[l * 21] : &s_dkk[(l - 8) * 21];
                float a = 0.f;
                #pragma unroll
                for (int k = 0; k < 21; k++) a = fmaf(s_a[si + k], wv[k], a);
                s_ft[si * 16 + l] = a;
            }
            if (tid < 128) {
                float a = 0.f;
                #pragma unroll
                for (int k = 0; k < 11; k++) a = fmaf(s_a[tid + k], prior[k], a);
                s_pri[tid] = a;
            }
            __syncthreads();

            int si = tid & 127, sl = tid >> 7;
            float4 f0 = *(const float4*)&s_ft[si * 16];
            float4 f1 = *(const float4*)&s_ft[si * 16 + 4];
            float4 f2 = *(const float4*)&s_ft[si * 16 + 8];
            float4 f3 = *(const float4*)&s_ft[si * 16 + 12];
            float part = 0.f;
            for (int c = sl * 64; c < sl * 64 + 64; c++) {
                const float* P = &s_sp[c * 20];
                float4 p0 = *(const float4*)P, p1 = *(const float4*)(P + 4);
                float4 p2 = *(const float4*)(P + 8), p3 = *(const float4*)(P + 12);
                float sc = P[16];
                sc = fmaf(p0.x, f0.x, sc); sc = fmaf(p0.y, f0.y, sc);
                sc = fmaf(p0.z, f0.z, sc); sc = fmaf(p0.w, f0.w, sc);
                sc = fmaf(p1.x, f1.x, sc); sc = fmaf(p1.y, f1.y, sc);
                sc = fmaf(p1.z, f1.z, sc); sc = fmaf(p1.w, f1.w, sc);
                sc = fmaf(p2.x, f2.x, sc); sc = fmaf(p2.y, f2.y, sc);
                sc = fmaf(p2.z, f2.z, sc); sc = fmaf(p2.w, f2.w, sc);
                sc = fmaf(p3.x, f3.x, sc); sc = fmaf(p3.y, f3.y, sc);
                sc = fmaf(p3.z, f3.z, sc); sc = fmaf(p3.w, f3.w, sc);
                part = fmaf(P[17], tanh_fast(sc), part);
            }
            s_ps[sl * 128 + si] = part;
            __syncthreads();
            if (tid < 128) {
                float e = s_ps[tid] + s_ps[128 + tid] + s_ps[256 + tid] + s_ps[384 + tid];
                e += __logf(s_pri[tid] + 1e-5f);
                int s = s0 + tid;
                e = (mask[b * SS + s] > 0.f) ? e : -INFINITY;
                g_energy[b][s] = e;
            }
        }
    }
}

extern "C" void kernel_launch(void* const* d_in, const int* in_sizes, int n_in,
                              void* d_out, int out_size) {
    const float* enc   = (const float*)d_in[0];
    const float* mask  = (const float*)d_in[1];
    const float* gt    = (const float*)d_in[2];
    const float* wi    = (const float*)d_in[3];
    const float* wh    = (const float*)d_in[4];
    const float* bi    = (const float*)d_in[5];
    const float* bh    = (const float*)d_in[6];
    const float* lw    = (const float*)d_in[7];
    const float* lp    = (const float*)d_in[8];
    const float* w1    = (const float*)d_in[9];
    const float* b1    = (const float*)d_in[10];
    const float* w2    = (const float*)d_in[11];
    const float* dw    = (const float*)d_in[12];
    const float* db    = (const float*)d_in[13];
    const float* aw    = (const float*)d_in[14];
    const float* prior = (const float*)d_in[15];
    float* out = (float*)d_out;

    k_init<<<512, 256>>>(wi, wh, w1, w2, lp, dw, db, aw);
    k_persist<<<GRID, NTHR>>>(enc, gt, mask, bi, bh, b1, lw, prior, out);
}

// round 9
// speedup vs baseline: 1.6499x; 1.0668x over previous
#include <cuda_runtime.h>
#include <math.h>

#define BB 64
#define SS 256
#define HH 80
#define TT 600
#define CC 512
#define KGRU 1104
#define GRID 128
#define NTHR 1024

__device__ float g_xT[2][KGRU][BB];   // rows: [0,80) frame, [80,592) prev, [592,1104) q
__device__ float g_wT[KGRU][2048];    // k-major, col n = ch*4+gate
__device__ float g_w1T[CC][CC];
__device__ float g_w2T[CC][176];
__device__ float g_t1T[CC][BB];
__device__ float g_dk[BB][176];
__device__ float g_sp[256][20];       // [lp8 | dw8 | db | aw | pad2]
__device__ float g_energy[BB][SS];
__device__ float g_alpha[BB][SS];
__device__ unsigned g_fl[GRID * 8];
__device__ unsigned g_pf[GRID * 8];

__device__ __forceinline__ float sig_fast(float x) {
    return __fdividef(1.f, 1.f + __expf(-x));
}
__device__ __forceinline__ float tanh_fast(float x) {
    float e = __expf(2.f * x);
    return 1.f - __fdividef(2.f, e + 1.f);
}
__device__ __forceinline__ void st_rel(unsigned* p, unsigned v) {
    asm volatile("st.release.gpu.global.u32 [%0],%1;" :: "l"(p), "r"(v) : "memory");
}
__device__ __forceinline__ unsigned ld_acq(const unsigned* p) {
    unsigned v;
    asm volatile("ld.acquire.gpu.global.u32 %0,[%1];" : "=r"(v) : "l"(p) : "memory");
    return v;
}
__device__ __forceinline__ void gbar(int bid, int tid, unsigned gen) {
    __syncthreads();
    if (tid == 0) st_rel(&g_fl[bid * 8], gen);
    if (tid < GRID) { while (ld_acq(&g_fl[tid * 8]) < gen) {} }
    __syncthreads();
}
__device__ __forceinline__ void pbar(int bid, int tid, unsigned gen) {
    __syncthreads();
    if (tid == 0) {
        st_rel(&g_pf[bid * 8], gen);
        while (ld_acq(&g_pf[(bid ^ 1) * 8]) < gen) {}
    }
    __syncthreads();
}
// L2-only async copy for mutable cross-SM activations
__device__ __forceinline__ void cpg(unsigned d, const void* s) {
    asm volatile("cp.async.cg.shared.global [%0],[%1],16;" :: "r"(d), "l"(s));
}
// L1-cached async copy for immutable weights
__device__ __forceinline__ void cpw(unsigned d, const void* s) {
    asm volatile("cp.async.ca.shared.global [%0],[%1],16;" :: "r"(d), "l"(s));
}
#define CPC asm volatile("cp.async.commit_group;" ::: "memory")
#define CPW1 asm volatile("cp.async.wait_group 1;" ::: "memory")
#define CPW0 asm volatile("cp.async.wait_group 0;" ::: "memory")

__global__ void k_init(const float* wi, const float* wh, const float* w1,
                       const float* w2, const float* lp, const float* dw,
                       const float* db, const float* aw) {
    int idx = blockIdx.x * blockDim.x + threadIdx.x;
    int stride = gridDim.x * blockDim.x;
    for (int i = idx; i < KGRU * 2048; i += stride) {
        int k = i >> 11, n = i & 2047, ch = n >> 2, g = n & 3;
        float v = 0.f;
        if (k < 592) {
            if (g == 0) v = wi[ch * 592 + k];
            else if (g == 1) v = wi[(512 + ch) * 592 + k];
            else if (g == 2) v = wi[(1024 + ch) * 592 + k];
        } else {
            int kk = k - 592;
            if (g == 0) v = wh[ch * 512 + kk];
            else if (g == 1) v = wh[(512 + ch) * 512 + kk];
            else if (g == 3) v = wh[(1024 + ch) * 512 + kk];
        }
        g_wT[k][n] = v;
    }
    for (int i = idx; i < CC * CC; i += stride) {
        int k = i >> 9, c = i & 511;
        g_w1T[k][c] = w1[c * CC + k];
    }
    for (int i = idx; i < CC * 176; i += stride) {
        int k = i / 176, c = i % 176;
        g_w2T[k][c] = (c < 168) ? w2[c * CC + k] : 0.f;
    }
    for (int i = idx; i < 256 * 20; i += stride) {
        int c = i / 20, j = i % 20;
        float v = 0.f;
        if (j < 8) v = lp[c * 8 + j];
        else if (j < 16) v = dw[c * 8 + (j - 8)];
        else if (j == 16) v = db[c];
        else if (j == 17) v = aw[c];
        g_sp[c][j] = v;
    }
    for (int i = idx; i < 512 * 64; i += stride) g_xT[0][592 + i / 64][i % 64] = 0.f;
    for (int i = idx; i < GRID * 8; i += stride) { g_fl[i] = 0u; g_pf[i] = 0u; }
}

// small GEMM: dst = act(X^T @ W + bias); X is [512][64] k-major, 4 cols/block.
__device__ __forceinline__ void gemm_ne(const float* __restrict__ X,
                                        const float* __restrict__ W, int wstride,
                                        int c0, const float* __restrict__ bias,
                                        float* __restrict__ dst, int dcs, int dbs,
                                        int act, float* sm, int tid) {
    float* xs = sm;            // [2][32][64] = 4096
    float* ws = sm + 4096;     // [2][32][4]  = 256
    unsigned xu = (unsigned)__cvta_generic_to_shared(xs);
    unsigned wu = (unsigned)__cvta_generic_to_shared(ws);
    int kz = tid >> 6, r = tid & 63, ty = r >> 2, tx = r & 3;
    float a0 = 0.f, a1 = 0.f, a2 = 0.f, a3 = 0.f;

    if (tid < 512)
        cpg(xu + (unsigned)(((tid >> 4) * 64 + (tid & 15) * 4) * 4),
            &X[(size_t)(tid >> 4) * 64 + (tid & 15) * 4]);
    else if (tid < 544)
        cpw(wu + (unsigned)(((tid - 512) * 4) * 4),
            &W[(size_t)(tid - 512) * wstride + c0]);
    CPC;
    for (int ch = 0; ch < 16; ch++) {
        if (ch < 15) {
            int kc = (ch + 1) * 32, nb = (ch + 1) & 1;
            if (tid < 512)
                cpg(xu + (unsigned)((nb * 2048 + (tid >> 4) * 64 + (tid & 15) * 4) * 4),
                    &X[(size_t)(kc + (tid >> 4)) * 64 + (tid & 15) * 4]);
            else if (tid < 544)
                cpw(wu + (unsigned)((nb * 128 + (tid - 512) * 4) * 4),
                    &W[(size_t)(kc + tid - 512) * wstride + c0]);
            CPC;
            CPW1;
        } else CPW0;
        __syncthreads();
        const float* xb = xs + (ch & 1) * 2048;
        const float* wb = ws + (ch & 1) * 128;
        #pragma unroll
        for (int kk = 0; kk < 2; kk++) {
            int k = kz * 2 + kk;
            float4 xv = *(const float4*)&xb[k * 64 + ty * 4];
            float wv = wb[k * 4 + tx];
            a0 = fmaf(xv.x, wv, a0); a1 = fmaf(xv.y, wv, a1);
            a2 = fmaf(xv.z, wv, a2); a3 = fmaf(xv.w, wv, a3);
        }
        __syncthreads();
    }
    float* red = sm;  // [16][64][4]
    red[kz * 256 + (ty * 4 + 0) * 4 + tx] = a0;
    red[kz * 256 + (ty * 4 + 1) * 4 + tx] = a1;
    red[kz * 256 + (ty * 4 + 2) * 4 + tx] = a2;
    red[kz * 256 + (ty * 4 + 3) * 4 + tx] = a3;
    __syncthreads();
    if (tid < 256) {
        int b = tid >> 2, c4 = tid & 3;
        float v = 0.f;
        #pragma unroll
        for (int z = 0; z < 16; z++) v += red[z * 256 + b * 4 + c4];
        int c = c0 + c4;
        if (bias) v += bias[c];
        if (act) v = tanh_fast(v);
        dst[(size_t)c * dcs + (size_t)b * dbs] = v;
    }
}

__global__ void __launch_bounds__(NTHR)
k_persist(const float* __restrict__ enc, const float* __restrict__ gt,
          const float* __restrict__ mask,
          const float* __restrict__ bi, const float* __restrict__ bh,
          const float* __restrict__ b1,
          const float* __restrict__ lw, const float* __restrict__ prior,
          float* __restrict__ out) {
    __shared__ __align__(16) float sm[9216];
    int bid = blockIdx.x, tid = threadIdx.x;
    int lane = tid & 31, wrp = tid >> 5;

    for (int t = 0;; t++) {
        int buf = t & 1, nbuf = buf ^ 1;
        if (t > 0) pbar(bid, tid, (unsigned)t);

        // ===== Phase A: softmax(energy) -> alpha, out[t-1], frame+prev ========
        {
            int b = bid >> 1, half = bid & 1;
            float* s_al  = sm;          // 256
            float* s_mx  = sm + 256;    // 8
            float* s_sm2 = sm + 288;    // 8
            float* s_pt  = sm + 512;    // 1024

            float a = 0.f, e = 0.f;
            if (t == 0) {
                if (tid < 256) a = (tid == 0) ? 1.f : 0.f;
            } else if (tid < 256) {
                e = __ldcg(&g_energy[b][tid]);
                float m = e;
                #pragma unroll
                for (int o = 16; o; o >>= 1) m = fmaxf(m, __shfl_xor_sync(0xffffffffu, m, o));
                if (lane == 0) s_mx[wrp] = m;
            }
            __syncthreads();
            if (t > 0 && tid < 256) {
                float bm = s_mx[0];
                #pragma unroll
                for (int i = 1; i < 8; i++) bm = fmaxf(bm, s_mx[i]);
                float p = __expf(e - bm);
                float ws = p;
                #pragma unroll
                for (int o = 16; o; o >>= 1) ws += __shfl_xor_sync(0xffffffffu, ws, o);
                if (lane == 0) s_sm2[wrp] = ws;
                a = p;
            }
            __syncthreads();
            if (tid < 256) {
                if (t > 0) {
                    float tot = 0.f;
                    #pragma unroll
                    for (int i = 0; i < 8; i++) tot += s_sm2[i];
                    a = __fdividef(a, tot);
                    if (half == 0) out[((size_t)b * TT + (t - 1)) * SS + tid] = a;
                }
                s_al[tid] = a;
                if (half == 0) g_alpha[b][tid] = a;
            }
            __syncthreads();
            if (t == TT) break;

            if (half == 0 && tid < HH)
                g_xT[buf][tid][b] = gt[((size_t)b * TT + t) * HH + tid];

            int col = tid & 255, slab = tid >> 8;   // 4 slabs of 64 s
            const float* ep = enc + ((size_t)b * SS + slab * 64) * 512 + half * 256 + col;
            float acc = 0.f;
            #pragma unroll 4
            for (int s = 0; s < 64; s++)
                acc = fmaf(s_al[slab * 64 + s], ep[(size_t)s * 512], acc);
            s_pt[tid] = acc;
            __syncthreads();
            if (tid < 256)
                g_xT[buf][HH + half * 256 + tid][b] =
                    s_pt[tid] + s_pt[256 + tid] + s_pt[512 + tid] + s_pt[768 + tid];
        }
        gbar(bid, tid, (unsigned)t * 4u + 1u);

        // ===== Phase B: GRU GEMM 32b x 32c x 1104k + fused gates ==============
        {
            int cg = bid >> 1, bt = bid & 1, b0 = bt * 32, c0 = cg * 32;
            float* xs = sm;          // [2][48][32]
            float* ws = sm + 3072;   // [2][48][32]
            unsigned xu = (unsigned)__cvta_generic_to_shared(xs);
            unsigned wu = (unsigned)__cvta_generic_to_shared(ws);
            int kz = tid >> 6, r = tid & 63, ty = r >> 3, tx = r & 7;
            float acc[4][4];
            #pragma unroll
            for (int i = 0; i < 4; i++)
                #pragma unroll
                for (int j = 0; j < 4; j++) acc[i][j] = 0.f;

            if (tid < 384)
                cpg(xu + (unsigned)(((tid >> 3) * 32 + (tid & 7) * 4) * 4),
                    &g_xT[buf][tid >> 3][b0 + (tid & 7) * 4]);
            else if (tid >= 512 && tid < 896) {
                int u = tid - 512;
                cpw(wu + (unsigned)(((u >> 3) * 32 + (u & 7) * 4) * 4),
                    &g_wT[u >> 3][c0 + (u & 7) * 4]);
            }
            CPC;
            for (int ch = 0; ch < 23; ch++) {
                if (ch < 22) {
                    int kc = (ch + 1) * 48, nb = (ch + 1) & 1;
                    if (tid < 384)
                        cpg(xu + (unsigned)((nb * 1536 + (tid >> 3) * 32 + (tid & 7) * 4) * 4),
                            &g_xT[buf][kc + (tid >> 3)][b0 + (tid & 7) * 4]);
                    else if (tid >= 512 && tid < 896) {
                        int u = tid - 512;
                        cpw(wu + (unsigned)((nb * 1536 + (u >> 3) * 32 + (u & 7) * 4) * 4),
                            &g_wT[kc + (u >> 3)][c0 + (u & 7) * 4]);
                    }
                    CPC;
                    CPW1;
                } else CPW0;
                __syncthreads();
                const float* xb = xs + (ch & 1) * 1536;
                const float* wb = ws + (ch & 1) * 1536;
                #pragma unroll
                for (int kk = 0; kk < 3; kk++) {
                    int k = kz * 3 + kk;
                    float4 xv = *(const float4*)&xb[k * 32 + ty * 4];
                    float4 wv = *(const float4*)&wb[k * 32 + tx * 4];
                    acc[0][0] = fmaf(xv.x, wv.x, acc[0][0]);
                    acc[0][1] = fmaf(xv.x, wv.y, acc[0][1]);
                    acc[0][2] = fmaf(xv.x, wv.z, acc[0][2]);
                    acc[0][3] = fmaf(xv.x, wv.w, acc[0][3]);
                    acc[1][0] = fmaf(xv.y, wv.x, acc[1][0]);
                    acc[1][1] = fmaf(xv.y, wv.y, acc[1][1]);
                    acc[1][2] = fmaf(xv.y, wv.z, acc[1][2]);
                    acc[1][3] = fmaf(xv.y, wv.w, acc[1][3]);
                    acc[2][0] = fmaf(xv.z, wv.x, acc[2][0]);
                    acc[2][1] = fmaf(xv.z, wv.y, acc[2][1]);
                    acc[2][2] = fmaf(xv.z, wv.z, acc[2][2]);
                    acc[2][3] = fmaf(xv.z, wv.w, acc[2][3]);
                    acc[3][0] = fmaf(xv.w, wv.x, acc[3][0]);
                    acc[3][1] = fmaf(xv.w, wv.y, acc[3][1]);
                    acc[3][2] = fmaf(xv.w, wv.z, acc[3][2]);
                    acc[3][3] = fmaf(xv.w, wv.w, acc[3][3]);
                }
                __syncthreads();
            }
            float* red = sm;  // [8][32][32]
            if (kz >= 8) {
                #pragma unroll
                for (int i = 0; i < 4; i++)
                    *(float4*)&red[(kz - 8) * 1024 + (ty * 4 + i) * 32 + tx * 4] =
                        make_float4(acc[i][0], acc[i][1], acc[i][2], acc[i][3]);
            }
            __syncthreads();
            if (kz < 8) {
                #pragma unroll
                for (int i = 0; i < 4; i++) {
                    float4 v = *(const float4*)&red[kz * 1024 + (ty * 4 + i) * 32 + tx * 4];
                    acc[i][0] += v.x; acc[i][1] += v.y; acc[i][2] += v.z; acc[i][3] += v.w;
                }
            }
            __syncthreads();
            if (kz < 8) {
                #pragma unroll
                for (int i = 0; i < 4; i++)
                    *(float4*)&red[kz * 1024 + (ty * 4 + i) * 32 + tx * 4] =
                        make_float4(acc[i][0], acc[i][1], acc[i][2], acc[i][3]);
            }
            __syncthreads();
            if (tid < 256) {
                int bl = tid & 31, chn = tid >> 5;
                float G[4] = {0.f, 0.f, 0.f, 0.f};
                #pragma unroll
                for (int z = 0; z < 8; z++) {
                    float4 v = *(const float4*)&red[z * 1024 + bl * 32 + chn * 4];
                    G[0] += v.x; G[1] += v.y; G[2] += v.z; G[3] += v.w;
                }
                int ch2 = cg * 8 + chn, bb2 = b0 + bl;
                float qold = __ldcg(&g_xT[buf][592 + ch2][bb2]);
                float rg = sig_fast(G[0] + bi[ch2] + bh[ch2]);
                float zg = sig_fast(G[1] + bi[512 + ch2] + bh[512 + ch2]);
                float ng = tanh_fast(G[2] + bi[1024 + ch2] + rg * (G[3] + bh[1024 + ch2]));
                g_xT[nbuf][592 + ch2][bb2] = (1.f - zg) * ng + zg * qold;
            }
        }
        gbar(bid, tid, (unsigned)t * 4u + 2u);

        // ===== Phase D: t1T = tanh(q @ w1^T + b1), 4 cols/block ===============
        gemm_ne(&g_xT[nbuf][592][0], &g_w1T[0][0], 512, bid * 4, b1,
                &g_t1T[0][0], 64, 1, 1, sm, tid);
        gbar(bid, tid, (unsigned)t * 4u + 3u);

        // ===== Phase E: dk = t1 @ w2^T, 4 cols/block (44 active) ==============
        if (bid < 44)
            gemm_ne(&g_t1T[0][0], &g_w2T[0][0], 176, bid * 4, (const float*)0,
                    &g_dk[0][0], 1, 176, 0, sm, tid);
        gbar(bid, tid, (unsigned)t * 4u + 4u);

        // ===== Phase F: convs + score + energy =================================
        {
            int b = bid >> 1, half = bid & 1, s0 = half * 128;
            float* s_a   = sm;          // 148 (pad 160)
            float* s_lw  = sm + 160;    // 168
            float* s_dkk = sm + 336;    // 168 (pad to 512)
            float* s_ft  = sm + 512;    // 128*16
            float* s_pri = sm + 2560;   // 128
            float* s_sp  = sm + 2688;   // 256*20
            float* s_ps  = sm + 7808;   // 8*128

            if (tid < 148) {
                int s = s0 - 10 + tid;
                s_a[tid] = (s >= 0 && s < SS) ? __ldcg(&g_alpha[b][s]) : 0.f;
            }
            if (tid >= 160 && tid < 328) s_lw[tid - 160] = lw[tid - 160];
            if (tid >= 328 && tid < 496) s_dkk[tid - 328] = __ldcg(&g_dk[b][tid - 328]);
            #pragma unroll
            for (int it = 0; it < 5; it++)
                s_sp[tid + it * 1024] = ((const float*)g_sp)[tid + it * 1024];
            __syncthreads();

            #pragma unroll
            for (int it = 0; it < 2; it++) {
                int u = tid + it * 1024;
                int l = u & 15, si = u >> 4;
                const float* wv = (l < 8) ? &s_lw[l * 21] : &s_dkk[(l - 8) * 21];
                float a = 0.f;
                #pragma unroll
                for (int k = 0; k < 21; k++) a = fmaf(s_a[si + k], wv[k], a);
                s_ft[si * 16 + l] = a;
            }
            if (tid < 128) {
                float a = 0.f;
                #pragma unroll
                for (int k = 0; k < 11; k++) a = fmaf(s_a[tid + k], prior[k], a);
                s_pri[tid] = a;
            }
            __syncthreads();

            int si = tid & 127, sl = tid >> 7;   // 8 slabs x 32 channels
            float4 f0 = *(const float4*)&s_ft[si * 16];
            float4 f1 = *(const float4*)&s_ft[si * 16 + 4];
            float4 f2 = *(const float4*)&s_ft[si * 16 + 8];
            float4 f3 = *(const float4*)&s_ft[si * 16 + 12];
            float part = 0.f;
            for (int c = sl * 32; c < sl * 32 + 32; c++) {
                const float* P = &s_sp[c * 20];
                float4 p0 = *(const float4*)P, p1 = *(const float4*)(P + 4);
                float4 p2 = *(const float4*)(P + 8), p3 = *(const float4*)(P + 12);
                float sc = P[16];
                sc = fmaf(p0.x, f0.x, sc); sc = fmaf(p0.y, f0.y, sc);
                sc = fmaf(p0.z, f0.z, sc); sc = fmaf(p0.w, f0.w, sc);
                sc = fmaf(p1.x, f1.x, sc); sc = fmaf(p1.y, f1.y, sc);
                sc = fmaf(p1.z, f1.z, sc); sc = fmaf(p1.w, f1.w, sc);
                sc = fmaf(p2.x, f2.x, sc); sc = fmaf(p2.y, f2.y, sc);
                sc = fmaf(p2.z, f2.z, sc); sc = fmaf(p2.w, f2.w, sc);
                sc = fmaf(p3.x, f3.x, sc); sc = fmaf(p3.y, f3.y, sc);
                sc = fmaf(p3.z, f3.z, sc); sc = fmaf(p3.w, f3.w, sc);
                part = fmaf(P[17], tanh_fast(sc), part);
            }
            s_ps[sl * 128 + si] = part;
            __syncthreads();
            if (tid < 128) {
                float e = 0.f;
                #pragma unroll
                for (int i = 0; i < 8; i++) e += s_ps[i * 128 + tid];
                e += __logf(s_pri[tid] + 1e-5f);
                int s = s0 + tid;
                e = (mask[b * SS + s] > 0.f) ? e : -INFINITY;
                g_energy[b][s] = e;
            }
        }
    }
}

extern "C" void kernel_launch(void* const* d_in, const int* in_sizes, int n_in,
                              void* d_out, int out_size) {
    const float* enc   = (const float*)d_in[0];
    const float* mask  = (const float*)d_in[1];
    const float* gt    = (const float*)d_in[2];
    const float* wi    = (const float*)d_in[3];
    const float* wh    = (const float*)d_in[4];
    const float* bi    = (const float*)d_in[5];
    const float* bh    = (const float*)d_in[6];
    const float* lw    = (const float*)d_in[7];
    const float* lp    = (const float*)d_in[8];
    const float* w1    = (const float*)d_in[9];
    const float* b1    = (const float*)d_in[10];
    const float* w2    = (const float*)d_in[11];
    const float* dw    = (const float*)d_in[12];
    const float* db    = (const float*)d_in[13];
    const float* aw    = (const float*)d_in[14];
    const float* prior = (const float*)d_in[15];
    float* out = (float*)d_out;

    k_init<<<512, 256>>>(wi, wh, w1, w2, lp, dw, db, aw);
    k_persist<<<GRID, NTHR>>>(enc, gt, mask, bi, bh, b1, lw, prior, out);
}

// round 10
// speedup vs baseline: 1.6722x; 1.0136x over previous
#include <cuda_runtime.h>
#include <math.h>

#define BB 64
#define SS 256
#define HH 80
#define TT 600
#define CC 512
#define KP 1152
#define GRID 128
#define NTHR 1024

__device__ float g_xT[2][KP][BB];     // rows: [0,80) frame, [80,592) prev, [592,1104) q, pad
__device__ float g_wT[KP][2048];      // k-major, col n = ch*4+gate, pad rows zero
__device__ float g_w1T[CC][CC];
__device__ float g_w2T[CC][176];
__device__ float g_t1T[CC][BB];
__device__ float g_dk[BB][176];
__device__ float g_sp[256][20];
__device__ float g_energy[BB][SS];
__device__ float g_alpha[BB][SS];
__device__ unsigned g_fl[GRID * 8];
__device__ unsigned g_pf[GRID * 8];

__device__ __forceinline__ float sig_fast(float x) {
    return __fdividef(1.f, 1.f + __expf(-x));
}
__device__ __forceinline__ float tanh_fast(float x) {
    float e = __expf(2.f * x);
    return 1.f - __fdividef(2.f, e + 1.f);
}
__device__ __forceinline__ void st_rel(unsigned* p, unsigned v) {
    asm volatile("st.release.gpu.global.u32 [%0],%1;" :: "l"(p), "r"(v) : "memory");
}
__device__ __forceinline__ unsigned ld_acq(const unsigned* p) {
    unsigned v;
    asm volatile("ld.acquire.gpu.global.u32 %0,[%1];" : "=r"(v) : "l"(p) : "memory");
    return v;
}
__device__ __forceinline__ void gbar(int bid, int tid, unsigned gen) {
    __syncthreads();
    if (tid == 0) st_rel(&g_fl[bid * 8], gen);
    if (tid < GRID) { while (ld_acq(&g_fl[tid * 8]) < gen) {} }
    __syncthreads();
}
__device__ __forceinline__ void pbar(int bid, int tid, unsigned gen) {
    __syncthreads();
    if (tid == 0) {
        st_rel(&g_pf[bid * 8], gen);
        while (ld_acq(&g_pf[(bid ^ 1) * 8]) < gen) {}
    }
    __syncthreads();
}
__device__ __forceinline__ void cpg(unsigned d, const void* s) {
    asm volatile("cp.async.cg.shared.global [%0],[%1],16;" :: "r"(d), "l"(s));
}
__device__ __forceinline__ void cpw(unsigned d, const void* s) {
    asm volatile("cp.async.ca.shared.global [%0],[%1],16;" :: "r"(d), "l"(s));
}
#define CPC asm volatile("cp.async.commit_group;" ::: "memory")
#define CPW1 asm volatile("cp.async.wait_group 1;" ::: "memory")
#define CPW0 asm volatile("cp.async.wait_group 0;" ::: "memory")

__global__ void k_init(const float* wi, const float* wh, const float* w1,
                       const float* w2, const float* lp, const float* dw,
                       const float* db, const float* aw) {
    int idx = blockIdx.x * blockDim.x + threadIdx.x;
    int stride = gridDim.x * blockDim.x;
    for (int i = idx; i < KP * 2048; i += stride) {
        int k = i >> 11, n = i & 2047, ch = n >> 2, g = n & 3;
        float v = 0.f;
        if (k < 592) {
            if (g == 0) v = wi[ch * 592 + k];
            else if (g == 1) v = wi[(512 + ch) * 592 + k];
            else if (g == 2) v = wi[(1024 + ch) * 592 + k];
        } else if (k < 1104) {
            int kk = k - 592;
            if (g == 0) v = wh[ch * 512 + kk];
            else if (g == 1) v = wh[(512 + ch) * 512 + kk];
            else if (g == 3) v = wh[(1024 + ch) * 512 + kk];
        }
        g_wT[k][n] = v;
    }
    for (int i = idx; i < CC * CC; i += stride) {
        int k = i >> 9, c = i & 511;
        g_w1T[k][c] = w1[c * CC + k];
    }
    for (int i = idx; i < CC * 176; i += stride) {
        int k = i / 176, c = i % 176;
        g_w2T[k][c] = (c < 168) ? w2[c * CC + k] : 0.f;
    }
    for (int i = idx; i < 256 * 20; i += stride) {
        int c = i / 20, j = i % 20;
        float v = 0.f;
        if (j < 8) v = lp[c * 8 + j];
        else if (j < 16) v = dw[c * 8 + (j - 8)];
        else if (j == 16) v = db[c];
        else if (j == 17) v = aw[c];
        g_sp[c][j] = v;
    }
    // zero q rows (buf0) and pad rows (both bufs)
    for (int i = idx; i < 512 * 64; i += stride) g_xT[0][592 + i / 64][i % 64] = 0.f;
    for (int i = idx; i < 48 * 64 * 2; i += stride) {
        int bf = i / (48 * 64), r = (i / 64) % 48, b = i % 64;
        g_xT[bf][1104 + r][b] = 0.f;
    }
    for (int i = idx; i < GRID * 8; i += stride) { g_fl[i] = 0u; g_pf[i] = 0u; }
}

// small GEMM: dst = act(X^T @ W + bias); X [512][64] k-major, 4 cols/block.
// 16 chunks of 32 k, 3-stage cp.async, ONE sync per chunk.
__device__ __forceinline__ void gemm_ne(const float* __restrict__ X,
                                        const float* __restrict__ W, int wstride,
                                        int c0, const float* __restrict__ bias,
                                        float* __restrict__ dst, int dcs, int dbs,
                                        int act, float* sm, int tid) {
    float* xs = sm;            // 3 x 2048
    float* ws = sm + 6144;     // 3 x 128
    unsigned xu = (unsigned)__cvta_generic_to_shared(xs);
    unsigned wu = (unsigned)__cvta_generic_to_shared(ws);
    int kz = tid >> 6, r = tid & 63, ty = r >> 2, tx = r & 3;
    float a0 = 0.f, a1 = 0.f, a2 = 0.f, a3 = 0.f;

    #pragma unroll
    for (int pg = 0; pg < 2; pg++) {
        if (tid < 512)
            cpg(xu + (unsigned)((pg * 2048 + (tid >> 4) * 64 + (tid & 15) * 4) * 4),
                &X[(size_t)(pg * 32 + (tid >> 4)) * 64 + (tid & 15) * 4]);
        else if (tid < 544)
            cpw(wu + (unsigned)((pg * 128 + (tid - 512) * 4) * 4),
                &W[(size_t)(pg * 32 + tid - 512) * wstride + c0]);
        CPC;
    }
    for (int ch = 0; ch < 16; ch++) {
        if (ch < 15) CPW1; else CPW0;
        __syncthreads();
        if (ch + 2 < 16) {
            int kc = (ch + 2) * 32, st = (ch + 2) % 3;
            if (tid < 512)
                cpg(xu + (unsigned)((st * 2048 + (tid >> 4) * 64 + (tid & 15) * 4) * 4),
                    &X[(size_t)(kc + (tid >> 4)) * 64 + (tid & 15) * 4]);
            else if (tid < 544)
                cpw(wu + (unsigned)((st * 128 + (tid - 512) * 4) * 4),
                    &W[(size_t)(kc + tid - 512) * wstride + c0]);
            CPC;
        }
        const float* xb = xs + (ch % 3) * 2048;
        const float* wb = ws + (ch % 3) * 128;
        #pragma unroll
        for (int kk = 0; kk < 2; kk++) {
            int k = kz * 2 + kk;
            float4 xv = *(const float4*)&xb[k * 64 + ty * 4];
            float wv = wb[k * 4 + tx];
            a0 = fmaf(xv.x, wv, a0); a1 = fmaf(xv.y, wv, a1);
            a2 = fmaf(xv.z, wv, a2); a3 = fmaf(xv.w, wv, a3);
        }
    }
    __syncthreads();
    float* red = sm;  // [16][64][4]
    red[kz * 256 + (ty * 4 + 0) * 4 + tx] = a0;
    red[kz * 256 + (ty * 4 + 1) * 4 + tx] = a1;
    red[kz * 256 + (ty * 4 + 2) * 4 + tx] = a2;
    red[kz * 256 + (ty * 4 + 3) * 4 + tx] = a3;
    __syncthreads();
    if (tid < 256) {
        int b = tid >> 2, c4 = tid & 3;
        float v = 0.f;
        #pragma unroll
        for (int z = 0; z < 16; z++) v += red[z * 256 + b * 4 + c4];
        int c = c0 + c4;
        if (bias) v += bias[c];
        if (act) v = tanh_fast(v);
        dst[(size_t)c * dcs + (size_t)b * dbs] = v;
    }
}

__global__ void __launch_bounds__(NTHR)
k_persist(const float* __restrict__ enc, const float* __restrict__ gt,
          const float* __restrict__ mask,
          const float* __restrict__ bi, const float* __restrict__ bh,
          const float* __restrict__ b1,
          const float* __restrict__ lw, const float* __restrict__ prior,
          float* __restrict__ out) {
    extern __shared__ __align__(16) float sm[];
    int bid = blockIdx.x, tid = threadIdx.x;
    int lane = tid & 31, wrp = tid >> 5;

    for (int t = 0;; t++) {
        int buf = t & 1, nbuf = buf ^ 1;
        if (t > 0) pbar(bid, tid, (unsigned)t);

        // ===== Phase A: softmax(energy) -> alpha, out[t-1], frame+prev ========
        {
            int b = bid >> 1, half = bid & 1;
            float* s_al  = sm;          // 256
            float* s_mx  = sm + 256;    // 8
            float* s_sm2 = sm + 288;    // 8
            float* s_pt  = sm + 512;    // 1024

            float a = 0.f, e = 0.f;
            if (t == 0) {
                if (tid < 256) a = (tid == 0) ? 1.f : 0.f;
            } else if (tid < 256) {
                e = __ldcg(&g_energy[b][tid]);
                float m = e;
                #pragma unroll
                for (int o = 16; o; o >>= 1) m = fmaxf(m, __shfl_xor_sync(0xffffffffu, m, o));
                if (lane == 0) s_mx[wrp] = m;
            }
            __syncthreads();
            if (t > 0 && tid < 256) {
                float bm = s_mx[0];
                #pragma unroll
                for (int i = 1; i < 8; i++) bm = fmaxf(bm, s_mx[i]);
                float p = __expf(e - bm);
                float ws = p;
                #pragma unroll
                for (int o = 16; o; o >>= 1) ws += __shfl_xor_sync(0xffffffffu, ws, o);
                if (lane == 0) s_sm2[wrp] = ws;
                a = p;
            }
            __syncthreads();
            if (tid < 256) {
                if (t > 0) {
                    float tot = 0.f;
                    #pragma unroll
                    for (int i = 0; i < 8; i++) tot += s_sm2[i];
                    a = __fdividef(a, tot);
                    if (half == 0) out[((size_t)b * TT + (t - 1)) * SS + tid] = a;
                }
                s_al[tid] = a;
                if (half == 0) g_alpha[b][tid] = a;
            }
            __syncthreads();
            if (t == TT) break;

            if (half == 0 && tid < HH)
                g_xT[buf][tid][b] = gt[((size_t)b * TT + t) * HH + tid];

            int col = tid & 255, slab = tid >> 8;
            const float* ep = enc + ((size_t)b * SS + slab * 64) * 512 + half * 256 + col;
            float acc = 0.f;
            #pragma unroll 4
            for (int s = 0; s < 64; s++)
                acc = fmaf(s_al[slab * 64 + s], ep[(size_t)s * 512], acc);
            s_pt[tid] = acc;
            __syncthreads();
            if (tid < 256)
                g_xT[buf][HH + half * 256 + tid][b] =
                    s_pt[tid] + s_pt[256 + tid] + s_pt[512 + tid] + s_pt[768 + tid];
        }
        gbar(bid, tid, (unsigned)t * 4u + 1u);

        // ===== Phase B: GRU GEMM 32b x 32c x 1152k + fused gates ==============
        {
            int cg = bid >> 1, bt = bid & 1, b0 = bt * 32, c0 = cg * 32;
            float* xs = sm;          // 3 x 2048
            float* ws = sm + 6144;   // 3 x 2048
            unsigned xu = (unsigned)__cvta_generic_to_shared(xs);
            unsigned wu = (unsigned)__cvta_generic_to_shared(ws);
            int kz = tid >> 6, r = tid & 63, ty = r >> 3, tx = r & 7;
            float acc[4][4];
            #pragma unroll
            for (int i = 0; i < 4; i++)
                #pragma unroll
                for (int j = 0; j < 4; j++) acc[i][j] = 0.f;

            #pragma unroll
            for (int pg = 0; pg < 2; pg++) {
                if (tid < 512)
                    cpg(xu + (unsigned)((pg * 2048 + (tid >> 3) * 32 + (tid & 7) * 4) * 4),
                        &g_xT[buf][pg * 64 + (tid >> 3)][b0 + (tid & 7) * 4]);
                else {
                    int u = tid - 512;
                    cpw(wu + (unsigned)((pg * 2048 + (u >> 3) * 32 + (u & 7) * 4) * 4),
                        &g_wT[pg * 64 + (u >> 3)][c0 + (u & 7) * 4]);
                }
                CPC;
            }
            for (int ch = 0; ch < 18; ch++) {
                if (ch < 17) CPW1; else CPW0;
                __syncthreads();
                if (ch + 2 < 18) {
                    int kc = (ch + 2) * 64, st = (ch + 2) % 3;
                    if (tid < 512)
                        cpg(xu + (unsigned)((st * 2048 + (tid >> 3) * 32 + (tid & 7) * 4) * 4),
                            &g_xT[buf][kc + (tid >> 3)][b0 + (tid & 7) * 4]);
                    else {
                        int u = tid - 512;
                        cpw(wu + (unsigned)((st * 2048 + (u >> 3) * 32 + (u & 7) * 4) * 4),
                            &g_wT[kc + (u >> 3)][c0 + (u & 7) * 4]);
                    }
                    CPC;
                }
                const float* xb = xs + (ch % 3) * 2048;
                const float* wb = ws + (ch % 3) * 2048;
                #pragma unroll
                for (int kk = 0; kk < 4; kk++) {
                    int k = kz * 4 + kk;
                    float4 xv = *(const float4*)&xb[k * 32 + ty * 4];
                    float4 wv = *(const float4*)&wb[k * 32 + tx * 4];
                    acc[0][0] = fmaf(xv.x, wv.x, acc[0][0]);
                    acc[0][1] = fmaf(xv.x, wv.y, acc[0][1]);
                    acc[0][2] = fmaf(xv.x, wv.z, acc[0][2]);
                    acc[0][3] = fmaf(xv.x, wv.w, acc[0][3]);
                    acc[1][0] = fmaf(xv.y, wv.x, acc[1][0]);
                    acc[1][1] = fmaf(xv.y, wv.y, acc[1][1]);
                    acc[1][2] = fmaf(xv.y, wv.z, acc[1][2]);
                    acc[1][3] = fmaf(xv.y, wv.w, acc[1][3]);
                    acc[2][0] = fmaf(xv.z, wv.x, acc[2][0]);
                    acc[2][1] = fmaf(xv.z, wv.y, acc[2][1]);
                    acc[2][2] = fmaf(xv.z, wv.z, acc[2][2]);
                    acc[2][3] = fmaf(xv.z, wv.w, acc[2][3]);
                    acc[3][0] = fmaf(xv.w, wv.x, acc[3][0]);
                    acc[3][1] = fmaf(xv.w, wv.y, acc[3][1]);
                    acc[3][2] = fmaf(xv.w, wv.z, acc[3][2]);
                    acc[3][3] = fmaf(xv.w, wv.w, acc[3][3]);
                }
            }
            __syncthreads();
            float* red = sm;  // [8][32][32]
            if (kz >= 8) {
                #pragma unroll
                for (int i = 0; i < 4; i++)
                    *(float4*)&red[(kz - 8) * 1024 + (ty * 4 + i) * 32 + tx * 4] =
                        make_float4(acc[i][0], acc[i][1], acc[i][2], acc[i][3]);
            }
            __syncthreads();
            if (kz < 8) {
                #pragma unroll
                for (int i = 0; i < 4; i++) {
                    float4 v = *(const float4*)&red[kz * 1024 + (ty * 4 + i) * 32 + tx * 4];
                    acc[i][0] += v.x; acc[i][1] += v.y; acc[i][2] += v.z; acc[i][3] += v.w;
                }
            }
            __syncthreads();
            if (kz < 8) {
                #pragma unroll
                for (int i = 0; i < 4; i++)
                    *(float4*)&red[kz * 1024 + (ty * 4 + i) * 32 + tx * 4] =
                        make_float4(acc[i][0], acc[i][1], acc[i][2], acc[i][3]);
            }
            __syncthreads();
            if (tid < 256) {
                int bl = tid & 31, chn = tid >> 5;
                float G[4] = {0.f, 0.f, 0.f, 0.f};
                #pragma unroll
                for (int z = 0; z < 8; z++) {
                    float4 v = *(const float4*)&red[z * 1024 + bl * 32 + chn * 4];
                    G[0] += v.x; G[1] += v.y; G[2] += v.z; G[3] += v.w;
                }
                int ch2 = cg * 8 + chn, bb2 = b0 + bl;
                float qold = __ldcg(&g_xT[buf][592 + ch2][bb2]);
                float rg = sig_fast(G[0] + bi[ch2] + bh[ch2]);
                float zg = sig_fast(G[1] + bi[512 + ch2] + bh[512 + ch2]);
                float ng = tanh_fast(G[2] + bi[1024 + ch2] + rg * (G[3] + bh[1024 + ch2]));
                g_xT[nbuf][592 + ch2][bb2] = (1.f - zg) * ng + zg * qold;
            }
        }
        gbar(bid, tid, (unsigned)t * 4u + 2u);

        // ===== Phase D: t1T = tanh(q @ w1^T + b1), 4 cols/block ===============
        gemm_ne(&g_xT[nbuf][592][0], &g_w1T[0][0], 512, bid * 4, b1,
                &g_t1T[0][0], 64, 1, 1, sm, tid);
        gbar(bid, tid, (unsigned)t * 4u + 3u);

        // ===== Phase E: dk = t1 @ w2^T, 4 cols/block (44 active) ==============
        if (bid < 44)
            gemm_ne(&g_t1T[0][0], &g_w2T[0][0], 176, bid * 4, (const float*)0,
                    &g_dk[0][0], 1, 176, 0, sm, tid);
        gbar(bid, tid, (unsigned)t * 4u + 4u);

        // ===== Phase F: convs + score + energy =================================
        {
            int b = bid >> 1, half = bid & 1, s0 = half * 128;
            float* s_a   = sm;          // 148 (pad 160)
            float* s_lw  = sm + 160;    // 168
            float* s_dkk = sm + 336;    // 168 (pad to 512)
            float* s_ft  = sm + 512;    // 128*16
            float* s_pri = sm + 2560;   // 128
            float* s_sp  = sm + 2688;   // 256*20
            float* s_ps  = sm + 7808;   // 8*128

            if (tid < 148) {
                int s = s0 - 10 + tid;
                s_a[tid] = (s >= 0 && s < SS) ? __ldcg(&g_alpha[b][s]) : 0.f;
            }
            if (tid >= 160 && tid < 328) s_lw[tid - 160] = lw[tid - 160];
            if (tid >= 328 && tid < 496) s_dkk[tid - 328] = __ldcg(&g_dk[b][tid - 328]);
            #pragma unroll
            for (int it = 0; it < 5; it++)
                s_sp[tid + it * 1024] = ((const float*)g_sp)[tid + it * 1024];
            __syncthreads();

            #pragma unroll
            for (int it = 0; it < 2; it++) {
                int u = tid + it * 1024;
                int l = u & 15, si = u >> 4;
                const float* wv = (l < 8) ? &s_lw[l * 21] : &s_dkk[(l - 8) * 21];
                float a = 0.f;
                #pragma unroll
                for (int k = 0; k < 21; k++) a = fmaf(s_a[si + k], wv[k], a);
                s_ft[si * 16 + l] = a;
            }
            if (tid < 128) {
                float a = 0.f;
                #pragma unroll
                for (int k = 0; k < 11; k++) a = fmaf(s_a[tid + k], prior[k], a);
                s_pri[tid] = a;
            }
            __syncthreads();

            int si = tid & 127, sl = tid >> 7;
            float4 f0 = *(const float4*)&s_ft[si * 16];
            float4 f1 = *(const float4*)&s_ft[si * 16 + 4];
            float4 f2 = *(const float4*)&s_ft[si * 16 + 8];
            float4 f3 = *(const float4*)&s_ft[si * 16 + 12];
            float part = 0.f;
            for (int c = sl * 32; c < sl * 32 + 32; c++) {
                const float* P = &s_sp[c * 20];
                float4 p0 = *(const float4*)P, p1 = *(const float4*)(P + 4);
                float4 p2 = *(const float4*)(P + 8), p3 = *(const float4*)(P + 12);
                float sc = P[16];
                sc = fmaf(p0.x, f0.x, sc); sc = fmaf(p0.y, f0.y, sc);
                sc = fmaf(p0.z, f0.z, sc); sc = fmaf(p0.w, f0.w, sc);
                sc = fmaf(p1.x, f1.x, sc); sc = fmaf(p1.y, f1.y, sc);
                sc = fmaf(p1.z, f1.z, sc); sc = fmaf(p1.w, f1.w, sc);
                sc = fmaf(p2.x, f2.x, sc); sc = fmaf(p2.y, f2.y, sc);
                sc = fmaf(p2.z, f2.z, sc); sc = fmaf(p2.w, f2.w, sc);
                sc = fmaf(p3.x, f3.x, sc); sc = fmaf(p3.y, f3.y, sc);
                sc = fmaf(p3.z, f3.z, sc); sc = fmaf(p3.w, f3.w, sc);
                part = fmaf(P[17], tanh_fast(sc), part);
            }
            s_ps[sl * 128 + si] = part;
            __syncthreads();
            if (tid < 128) {
                float e = 0.f;
                #pragma unroll
                for (int i = 0; i < 8; i++) e += s_ps[i * 128 + tid];
                e += __logf(s_pri[tid] + 1e-5f);
                int s = s0 + tid;
                e = (mask[b * SS + s] > 0.f) ? e : -INFINITY;
                g_energy[b][s] = e;
            }
        }
    }
}

extern "C" void kernel_launch(void* const* d_in, const int* in_sizes, int n_in,
                              void* d_out, int out_size) {
    const float* enc   = (const float*)d_in[0];
    const float* mask  = (const float*)d_in[1];
    const float* gt    = (const float*)d_in[2];
    const float* wi    = (const float*)d_in[3];
    const float* wh    = (const float*)d_in[4];
    const float* bi    = (const float*)d_in[5];
    const float* bh    = (const float*)d_in[6];
    const float* lw    = (const float*)d_in[7];
    const float* lp    = (const float*)d_in[8];
    const float* w1    = (const float*)d_in[9];
    const float* b1    = (const float*)d_in[10];
    const float* w2    = (const float*)d_in[11];
    const float* dw    = (const float*)d_in[12];
    const float* db    = (const float*)d_in[13];
    const float* aw    = (const float*)d_in[14];
    const float* prior = (const float*)d_in[15];
    float* out = (float*)d_out;

    static int cfg_done = 0;
    if (!cfg_done) {
        cudaFuncSetAttribute(k_persist, cudaFuncAttributeMaxDynamicSharedMemorySize, 65536);
        cfg_done = 1;
    }
    k_init<<<512, 256>>>(wi, wh, w1, w2, lp, dw, db, aw);
    k_persist<<<GRID, NTHR, 65536>>>(enc, gt, mask, bi, bh, b1, lw, prior, out);
}

// round 11
// speedup vs baseline: 1.9569x; 1.1702x over previous
#include <cuda_runtime.h>
#include <cuda_bf16.h>
#include <math.h>

#define BB 64
#define SS 256
#define HH 80
#define TT 600
#define CC 512
#define KP 1152
#define K2 576
#define GRID 128
#define NTHR 1024

__device__ __nv_bfloat16 g_xh[2][K2][128];   // [buf][k>>1][b*2+(k&1)] hi
__device__ __nv_bfloat16 g_xl[2][K2][128];   // lo
__device__ __nv_bfloat16 g_wph[K2][4096];    // [k>>1][n*2+(k&1)] hi, n = ch*4+gate
__device__ __nv_bfloat16 g_wpl[K2][4096];    // lo
__device__ float g_qf[CC][BB];               // fp32 GRU state (for D + qold)
__device__ float g_w1T[CC][CC];
__device__ float g_w2T[CC][176];
__device__ float g_t1T[CC][BB];
__device__ float g_dk[BB][176];
__device__ float g_sp[256][20];
__device__ float g_energy[BB][SS];
__device__ float g_alpha[BB][SS];
__device__ unsigned g_fl[GRID * 8];
__device__ unsigned g_pf[GRID * 8];

__device__ __forceinline__ float sig_fast(float x) {
    return __fdividef(1.f, 1.f + __expf(-x));
}
__device__ __forceinline__ float tanh_fast(float x) {
    float e = __expf(2.f * x);
    return 1.f - __fdividef(2.f, e + 1.f);
}
__device__ __forceinline__ void st_rel(unsigned* p, unsigned v) {
    asm volatile("st.release.gpu.global.u32 [%0],%1;" :: "l"(p), "r"(v) : "memory");
}
__device__ __forceinline__ unsigned ld_acq(const unsigned* p) {
    unsigned v;
    asm volatile("ld.acquire.gpu.global.u32 %0,[%1];" : "=r"(v) : "l"(p) : "memory");
    return v;
}
__device__ __forceinline__ void gbar(int bid, int tid, unsigned gen) {
    __syncthreads();
    if (tid == 0) st_rel(&g_fl[bid * 8], gen);
    if (tid < GRID) { while (ld_acq(&g_fl[tid * 8]) < gen) {} }
    __syncthreads();
}
__device__ __forceinline__ void pbar(int bid, int tid, unsigned gen) {
    __syncthreads();
    if (tid == 0) {
        st_rel(&g_pf[bid * 8], gen);
        while (ld_acq(&g_pf[(bid ^ 1) * 8]) < gen) {}
    }
    __syncthreads();
}
__device__ __forceinline__ void cpg(unsigned d, const void* s) {
    asm volatile("cp.async.cg.shared.global [%0],[%1],16;" :: "r"(d), "l"(s));
}
__device__ __forceinline__ void cpw(unsigned d, const void* s) {
    asm volatile("cp.async.ca.shared.global [%0],[%1],16;" :: "r"(d), "l"(s));
}
#define CPC asm volatile("cp.async.commit_group;" ::: "memory")
#define CPW1 asm volatile("cp.async.wait_group 1;" ::: "memory")
#define CPW0 asm volatile("cp.async.wait_group 0;" ::: "memory")

__device__ __forceinline__ void mma_bf16(float& c0, float& c1, float& c2, float& c3,
                                         unsigned a0, unsigned a1, unsigned a2, unsigned a3,
                                         unsigned b0, unsigned b1) {
    asm volatile("mma.sync.aligned.m16n8k16.row.col.f32.bf16.bf16.f32 "
                 "{%0,%1,%2,%3},{%4,%5,%6,%7},{%8,%9},{%0,%1,%2,%3};"
                 : "+f"(c0), "+f"(c1), "+f"(c2), "+f"(c3)
                 : "r"(a0), "r"(a1), "r"(a2), "r"(a3), "r"(b0), "r"(b1));
}

__global__ void k_init(const float* wi, const float* wh, const float* w1,
                       const float* w2, const float* lp, const float* dw,
                       const float* db, const float* aw) {
    int idx = blockIdx.x * blockDim.x + threadIdx.x;
    int stride = gridDim.x * blockDim.x;
    for (int i = idx; i < K2 * 4096; i += stride) {
        int k2 = i >> 12, np = i & 4095, n = np >> 1, p = np & 1, k = k2 * 2 + p;
        int ch = n >> 2, g = n & 3;
        float v = 0.f;
        if (k < 592) {
            if (g == 0) v = wi[ch * 592 + k];
            else if (g == 1) v = wi[(512 + ch) * 592 + k];
            else if (g == 2) v = wi[(1024 + ch) * 592 + k];
        } else if (k < 1104) {
            int kk = k - 592;
            if (g == 0) v = wh[ch * 512 + kk];
            else if (g == 1) v = wh[(512 + ch) * 512 + kk];
            else if (g == 3) v = wh[(1024 + ch) * 512 + kk];
        }
        __nv_bfloat16 h = __float2bfloat16(v);
        g_wph[k2][np] = h;
        g_wpl[k2][np] = __float2bfloat16(v - __bfloat162float(h));
    }
    for (int i = idx; i < 2 * K2 * 128; i += stride) {
        ((__nv_bfloat16*)g_xh)[i] = __float2bfloat16(0.f);
        ((__nv_bfloat16*)g_xl)[i] = __float2bfloat16(0.f);
    }
    for (int i = idx; i < CC * BB; i += stride) ((float*)g_qf)[i] = 0.f;
    for (int i = idx; i < CC * CC; i += stride) {
        int k = i >> 9, c = i & 511;
        g_w1T[k][c] = w1[c * CC + k];
    }
    for (int i = idx; i < CC * 176; i += stride) {
        int k = i / 176, c = i % 176;
        g_w2T[k][c] = (c < 168) ? w2[c * CC + k] : 0.f;
    }
    for (int i = idx; i < 256 * 20; i += stride) {
        int c = i / 20, j = i % 20;
        float v = 0.f;
        if (j < 8) v = lp[c * 8 + j];
        else if (j < 16) v = dw[c * 8 + (j - 8)];
        else if (j == 16) v = db[c];
        else if (j == 17) v = aw[c];
        g_sp[c][j] = v;
    }
    for (int i = idx; i < GRID * 8; i += stride) { g_fl[i] = 0u; g_pf[i] = 0u; }
}

__device__ __forceinline__ void st_pair(int buf, int k, int b, float v) {
    __nv_bfloat16 h = __float2bfloat16(v);
    g_xh[buf][k >> 1][b * 2 + (k & 1)] = h;
    g_xl[buf][k >> 1][b * 2 + (k & 1)] = __float2bfloat16(v - __bfloat162float(h));
}

// small GEMM: dst = act(X^T @ W + bias); X [512][64] f32 k-major, 4 cols/block.
__device__ __forceinline__ void gemm_ne(const float* __restrict__ X,
                                        const float* __restrict__ W, int wstride,
                                        int c0, const float* __restrict__ bias,
                                        float* __restrict__ dst, int dcs, int dbs,
                                        int act, float* sm, int tid) {
    float* xs = sm;
    float* ws = sm + 6144;
    unsigned xu = (unsigned)__cvta_generic_to_shared(xs);
    unsigned wu = (unsigned)__cvta_generic_to_shared(ws);
    int kz = tid >> 6, r = tid & 63, ty = r >> 2, tx = r & 3;
    float a0 = 0.f, a1 = 0.f, a2 = 0.f, a3 = 0.f;
    #pragma unroll
    for (int pg = 0; pg < 2; pg++) {
        if (tid < 512)
            cpg(xu + (unsigned)((pg * 2048 + (tid >> 4) * 64 + (tid & 15) * 4) * 4),
                &X[(size_t)(pg * 32 + (tid >> 4)) * 64 + (tid & 15) * 4]);
        else if (tid < 544)
            cpw(wu + (unsigned)((pg * 128 + (tid - 512) * 4) * 4),
                &W[(size_t)(pg * 32 + tid - 512) * wstride + c0]);
        CPC;
    }
    for (int ch = 0; ch < 16; ch++) {
        if (ch < 15) CPW1; else CPW0;
        __syncthreads();
        if (ch + 2 < 16) {
            int kc = (ch + 2) * 32, st = (ch + 2) % 3;
            if (tid < 512)
                cpg(xu + (unsigned)((st * 2048 + (tid >> 4) * 64 + (tid & 15) * 4) * 4),
                    &X[(size_t)(kc + (tid >> 4)) * 64 + (tid & 15) * 4]);
            else if (tid < 544)
                cpw(wu + (unsigned)((st * 128 + (tid - 512) * 4) * 4),
                    &W[(size_t)(kc + tid - 512) * wstride + c0]);
            CPC;
        }
        const float* xb = xs + (ch % 3) * 2048;
        const float* wb = ws + (ch % 3) * 128;
        #pragma unroll
        for (int kk = 0; kk < 2; kk++) {
            int k = kz * 2 + kk;
            float4 xv = *(const float4*)&xb[k * 64 + ty * 4];
            float wv = wb[k * 4 + tx];
            a0 = fmaf(xv.x, wv, a0); a1 = fmaf(xv.y, wv, a1);
            a2 = fmaf(xv.z, wv, a2); a3 = fmaf(xv.w, wv, a3);
        }
    }
    __syncthreads();
    float* red = sm;
    red[kz * 256 + (ty * 4 + 0) * 4 + tx] = a0;
    red[kz * 256 + (ty * 4 + 1) * 4 + tx] = a1;
    red[kz * 256 + (ty * 4 + 2) * 4 + tx] = a2;
    red[kz * 256 + (ty * 4 + 3) * 4 + tx] = a3;
    __syncthreads();
    if (tid < 256) {
        int b = tid >> 2, c4 = tid & 3;
        float v = 0.f;
        #pragma unroll
        for (int z = 0; z < 16; z++) v += red[z * 256 + b * 4 + c4];
        int c = c0 + c4;
        if (bias) v += bias[c];
        if (act) v = tanh_fast(v);
        dst[(size_t)c * dcs + (size_t)b * dbs] = v;
    }
}

__global__ void __launch_bounds__(NTHR)
k_persist(const float* __restrict__ enc, const float* __restrict__ gt,
          const float* __restrict__ mask,
          const float* __restrict__ bi, const float* __restrict__ bh,
          const float* __restrict__ b1,
          const float* __restrict__ lw, const float* __restrict__ prior,
          float* __restrict__ out) {
    extern __shared__ __align__(16) float sm[];
    int bid = blockIdx.x, tid = threadIdx.x;
    int lane = tid & 31, wrp = tid >> 5;

    for (int t = 0;; t++) {
        int buf = t & 1, nbuf = buf ^ 1;
        if (t > 0) pbar(bid, tid, (unsigned)t);

        // ===== Phase A =====
        {
            int b = bid >> 1, half = bid & 1;
            float* s_al  = sm;
            float* s_mx  = sm + 256;
            float* s_sm2 = sm + 288;
            float* s_pt  = sm + 512;

            float a = 0.f, e = 0.f;
            if (t == 0) {
                if (tid < 256) a = (tid == 0) ? 1.f : 0.f;
            } else if (tid < 256) {
                e = __ldcg(&g_energy[b][tid]);
                float m = e;
                #pragma unroll
                for (int o = 16; o; o >>= 1) m = fmaxf(m, __shfl_xor_sync(0xffffffffu, m, o));
                if (lane == 0) s_mx[wrp] = m;
            }
            __syncthreads();
            if (t > 0 && tid < 256) {
                float bm = s_mx[0];
                #pragma unroll
                for (int i = 1; i < 8; i++) bm = fmaxf(bm, s_mx[i]);
                float p = __expf(e - bm);
                float ws = p;
                #pragma unroll
                for (int o = 16; o; o >>= 1) ws += __shfl_xor_sync(0xffffffffu, ws, o);
                if (lane == 0) s_sm2[wrp] = ws;
                a = p;
            }
            __syncthreads();
            if (tid < 256) {
                if (t > 0) {
                    float tot = 0.f;
                    #pragma unroll
                    for (int i = 0; i < 8; i++) tot += s_sm2[i];
                    a = __fdividef(a, tot);
                    if (half == 0) out[((size_t)b * TT + (t - 1)) * SS + tid] = a;
                }
                s_al[tid] = a;
                if (half == 0) g_alpha[b][tid] = a;
            }
            __syncthreads();
            if (t == TT) break;

            if (half == 0 && tid < HH)
                st_pair(buf, tid, b, gt[((size_t)b * TT + t) * HH + tid]);

            int col = tid & 255, slab = tid >> 8;
            const float* ep = enc + ((size_t)b * SS + slab * 64) * 512 + half * 256 + col;
            float acc = 0.f;
            #pragma unroll 4
            for (int s = 0; s < 64; s++)
                acc = fmaf(s_al[slab * 64 + s], ep[(size_t)s * 512], acc);
            s_pt[tid] = acc;
            __syncthreads();
            if (tid < 256) {
                float v = s_pt[tid] + s_pt[256 + tid] + s_pt[512 + tid] + s_pt[768 + tid];
                st_pair(buf, HH + half * 256 + tid, b, v);
            }
        }
        gbar(bid, tid, (unsigned)t * 4u + 1u);

        // ===== Phase B: GRU GEMM via bf16 hi/lo mma + fused gates =====
        {
            int cg = bid >> 1, bt = bid & 1, b0 = bt * 32, c0 = cg * 32;
            char* smc = (char*)sm;
            const int RS = 160, TSZ = 32 * RS, BUF = 4 * TSZ;  // 5120, 20480
            unsigned sbase = (unsigned)__cvta_generic_to_shared(smc);
            int row = (tid >> 3) & 31, seg = tid & 7, grp = tid >> 8;

            int wid2 = tid >> 5;
            int kz = wid2 & 3, tile = wid2 >> 2;
            int mi = tile & 1, ni = tile >> 1;
            int gid = lane >> 2, tig = lane & 3;
            int arow = (kz * 8 + tig) * RS;
            int aoff = arow + (mi * 16 + gid) * 4;
            int boff = arow + (ni * 8 + gid) * 4;
            float c0r = 0.f, c1r = 0.f, c2r = 0.f, c3r = 0.f;

            #pragma unroll
            for (int pg = 0; pg < 2; pg++) {
                int kc2 = pg * 32;
                unsigned dst = sbase + (unsigned)(pg * BUF + grp * TSZ + row * RS + seg * 16);
                const char* src;
                if (grp == 0) src = (const char*)&g_xh[buf][kc2 + row][0] + b0 * 4 + seg * 16;
                else if (grp == 1) src = (const char*)&g_xl[buf][kc2 + row][0] + b0 * 4 + seg * 16;
                else if (grp == 2) src = (const char*)&g_wph[kc2 + row][0] + c0 * 4 + seg * 16;
                else src = (const char*)&g_wpl[kc2 + row][0] + c0 * 4 + seg * 16;
                if (grp < 2) cpg(dst, src); else cpw(dst, src);
                CPC;
            }
            for (int ch = 0; ch < 18; ch++) {
                if (ch < 17) CPW1; else CPW0;
                __syncthreads();
                if (ch + 2 < 18) {
                    int kc2 = (ch + 2) * 32, st = (ch + 2) % 3;
                    unsigned dst = sbase + (unsigned)(st * BUF + grp * TSZ + row * RS + seg * 16);
                    const char* src;
                    if (grp == 0) src = (const char*)&g_xh[buf][kc2 + row][0] + b0 * 4 + seg * 16;
                    else if (grp == 1) src = (const char*)&g_xl[buf][kc2 + row][0] + b0 * 4 + seg * 16;
                    else if (grp == 2) src = (const char*)&g_wph[kc2 + row][0] + c0 * 4 + seg * 16;
                    else src = (const char*)&g_wpl[kc2 + row][0] + c0 * 4 + seg * 16;
                    if (grp < 2) cpg(dst, src); else cpw(dst, src);
                    CPC;
                }
                const char* tb = smc + (ch % 3) * BUF;
                unsigned ah0 = *(const unsigned*)(tb + aoff);
                unsigned ah1 = *(const unsigned*)(tb + aoff + 32);
                unsigned ah2 = *(const unsigned*)(tb + aoff + 640);
                unsigned ah3 = *(const unsigned*)(tb + aoff + 672);
                unsigned al0 = *(const unsigned*)(tb + TSZ + aoff);
                unsigned al1 = *(const unsigned*)(tb + TSZ + aoff + 32);
                unsigned al2 = *(const unsigned*)(tb + TSZ + aoff + 640);
                unsigned al3 = *(const unsigned*)(tb + TSZ + aoff + 672);
                unsigned bh0 = *(const unsigned*)(tb + 2 * TSZ + boff);
                unsigned bh1 = *(const unsigned*)(tb + 2 * TSZ + boff + 640);
                unsigned bl0 = *(const unsigned*)(tb + 3 * TSZ + boff);
                unsigned bl1 = *(const unsigned*)(tb + 3 * TSZ + boff + 640);
                mma_bf16(c0r, c1r, c2r, c3r, ah0, ah1, ah2, ah3, bh0, bh1);
                mma_bf16(c0r, c1r, c2r, c3r, ah0, ah1, ah2, ah3, bl0, bl1);
                mma_bf16(c0r, c1r, c2r, c3r, al0, al1, al2, al3, bh0, bh1);
            }
            __syncthreads();
            float* red = sm;  // [4][32][33]
            int ridx = kz * 1056 + (mi * 16 + gid) * 33 + ni * 8 + tig * 2;
            red[ridx] = c0r; red[ridx + 1] = c1r;
            red[ridx + 8 * 33] = c2r; red[ridx + 8 * 33 + 1] = c3r;
            __syncthreads();
            if (tid < 256) {
                int bl = tid & 31, chn = tid >> 5;
                float G[4];
                #pragma unroll
                for (int g = 0; g < 4; g++)
                    G[g] = red[bl * 33 + chn * 4 + g] + red[1056 + bl * 33 + chn * 4 + g]
                         + red[2112 + bl * 33 + chn * 4 + g] + red[3168 + bl * 33 + chn * 4 + g];
                int ch2 = cg * 8 + chn, bb2 = b0 + bl;
                float qold = __ldcg(&g_qf[ch2][bb2]);
                float rg = sig_fast(G[0] + bi[ch2] + bh[ch2]);
                float zg = sig_fast(G[1] + bi[512 + ch2] + bh[512 + ch2]);
                float ng = tanh_fast(G[2] + bi[1024 + ch2] + rg * (G[3] + bh[1024 + ch2]));
                float qn = (1.f - zg) * ng + zg * qold;
                g_qf[ch2][bb2] = qn;
                st_pair(nbuf, 592 + ch2, bb2, qn);
            }
        }
        gbar(bid, tid, (unsigned)t * 4u + 2u);

        // ===== Phase D =====
        gemm_ne(&g_qf[0][0], &g_w1T[0][0], 512, bid * 4, b1,
                &g_t1T[0][0], 64, 1, 1, sm, tid);
        gbar(bid, tid, (unsigned)t * 4u + 3u);

        // ===== Phase E =====
        if (bid < 44)
            gemm_ne(&g_t1T[0][0], &g_w2T[0][0], 176, bid * 4, (const float*)0,
                    &g_dk[0][0], 1, 176, 0, sm, tid);
        gbar(bid, tid, (unsigned)t * 4u + 4u);

        // ===== Phase F =====
        {
            int b = bid >> 1, half = bid & 1, s0 = half * 128;
            float* s_a   = sm;
            float* s_lw  = sm + 160;
            float* s_dkk = sm + 336;
            float* s_ft  = sm + 512;
            float* s_pri = sm + 2560;
            float* s_sp  = sm + 2688;
            float* s_ps  = sm + 7808;

            if (tid < 148) {
                int s = s0 - 10 + tid;
                s_a[tid] = (s >= 0 && s < SS) ? __ldcg(&g_alpha[b][s]) : 0.f;
            }
            if (tid >= 160 && tid < 328) s_lw[tid - 160] = lw[tid - 160];
            if (tid >= 328 && tid < 496) s_dkk[tid - 328] = __ldcg(&g_dk[b][tid - 328]);
            #pragma unroll
            for (int it = 0; it < 5; it++)
                s_sp[tid + it * 1024] = ((const float*)g_sp)[tid + it * 1024];
            __syncthreads();

            #pragma unroll
            for (int it = 0; it < 2; it++) {
                int u = tid + it * 1024;
                int l = u & 15, si = u >> 4;
                const float* wv = (l < 8) ? &s_lw[l * 21] : &s_dkk[(l - 8) * 21];
                float a = 0.f;
                #pragma unroll
                for (int k = 0; k < 21; k++) a = fmaf(s_a[si + k], wv[k], a);
                s_ft[si * 16 + l] = a;
            }
            if (tid < 128) {
                float a = 0.f;
                #pragma unroll
                for (int k = 0; k < 11; k++) a = fmaf(s_a[tid + k], prior[k], a);
                s_pri[tid] = a;
            }
            __syncthreads();

            int si = tid & 127, sl = tid >> 7;
            float4 f0 = *(const float4*)&s_ft[si * 16];
            float4 f1 = *(const float4*)&s_ft[si * 16 + 4];
            float4 f2 = *(const float4*)&s_ft[si * 16 + 8];
            float4 f3 = *(const float4*)&s_ft[si * 16 + 12];
            float part = 0.f;
            for (int c = sl * 32; c < sl * 32 + 32; c++) {
                const float* P = &s_sp[c * 20];
                float4 p0 = *(const float4*)P, p1 = *(const float4*)(P + 4);
                float4 p2 = *(const float4*)(P + 8), p3 = *(const float4*)(P + 12);
                float sc = P[16];
                sc = fmaf(p0.x, f0.x, sc); sc = fmaf(p0.y, f0.y, sc);
                sc = fmaf(p0.z, f0.z, sc); sc = fmaf(p0.w, f0.w, sc);
                sc = fmaf(p1.x, f1.x, sc); sc = fmaf(p1.y, f1.y, sc);
                sc = fmaf(p1.z, f1.z, sc); sc = fmaf(p1.w, f1.w, sc);
                sc = fmaf(p2.x, f2.x, sc); sc = fmaf(p2.y, f2.y, sc);
                sc = fmaf(p2.z, f2.z, sc); sc = fmaf(p2.w, f2.w, sc);
                sc = fmaf(p3.x, f3.x, sc); sc = fmaf(p3.y, f3.y, sc);
                sc = fmaf(p3.z, f3.z, sc); sc = fmaf(p3.w, f3.w, sc);
                part = fmaf(P[17], tanh_fast(sc), part);
            }
            s_ps[sl * 128 + si] = part;
            __syncthreads();
            if (tid < 128) {
                float e = 0.f;
                #pragma unroll
                for (int i = 0; i < 8; i++) e += s_ps[i * 128 + tid];
                e += __logf(s_pri[tid] + 1e-5f);
                int s = s0 + tid;
                e = (mask[b * SS + s] > 0.f) ? e : -INFINITY;
                g_energy[b][s] = e;
            }
        }
    }
}

extern "C" void kernel_launch(void* const* d_in, const int* in_sizes, int n_in,
                              void* d_out, int out_size) {
    const float* enc   = (const float*)d_in[0];
    const float* mask  = (const float*)d_in[1];
    const float* gt    = (const float*)d_in[2];
    const float* wi    = (const float*)d_in[3];
    const float* wh    = (const float*)d_in[4];
    const float* bi    = (const float*)d_in[5];
    const float* bh    = (const float*)d_in[6];
    const float* lw    = (const float*)d_in[7];
    const float* lp    = (const float*)d_in[8];
    const float* w1    = (const float*)d_in[9];
    const float* b1    = (const float*)d_in[10];
    const float* w2    = (const float*)d_in[11];
    const float* dw    = (const float*)d_in[12];
    const float* db    = (const float*)d_in[13];
    const float* aw    = (const float*)d_in[14];
    const float* prior = (const float*)d_in[15];
    float* out = (float*)d_out;

    static int cfg_done = 0;
    if (!cfg_done) {
        cudaFuncSetAttribute(k_persist, cudaFuncAttributeMaxDynamicSharedMemorySize, 65536);
        cfg_done = 1;
    }
    k_init<<<512, 256>>>(wi, wh, w1, w2, lp, dw, db, aw);
    k_persist<<<GRID, NTHR, 65536>>>(enc, gt, mask, bi, bh, b1, lw, prior, out);
}

// round 12
// speedup vs baseline: 2.1393x; 1.0932x over previous
#include <cuda_runtime.h>
#include <cuda_bf16.h>
#include <math.h>

#define BB 64
#define SS 256
#define HH 80
#define TT 600
#define CC 512
#define K2 576
#define GRID 128
#define NTHR 1024

__device__ __nv_bfloat16 g_xh[2][K2][128];   // [buf][k>>1][b*2+(k&1)] hi
__device__ __nv_bfloat16 g_xl[2][K2][128];   // lo
__device__ __nv_bfloat16 g_wph[K2][4096];    // GRU W hi, [k2][n*2+p], n=ch*4+gate
__device__ __nv_bfloat16 g_wpl[K2][4096];    // lo
__device__ __nv_bfloat16 g_w1p[2][256][1024];// [hi/lo][k2][c*2+p]
__device__ __nv_bfloat16 g_w2p[2][256][352];
__device__ __nv_bfloat16 g_t1p[2][256][128]; // [hi/lo][c>>1][b*2+(c&1)]
__device__ float g_qf[CC][BB];               // exact fp32 GRU state (qold)
__device__ float g_dk[BB][176];
__device__ float g_sp[256][20];
__device__ float g_energy[BB][SS];
__device__ float g_alpha[BB][SS];
__device__ unsigned g_fl[GRID * 8];
__device__ unsigned g_pf[GRID * 8];

__device__ __forceinline__ float sig_fast(float x) {
    return __fdividef(1.f, 1.f + __expf(-x));
}
__device__ __forceinline__ float tanh_fast(float x) {
    float e = __expf(2.f * x);
    return 1.f - __fdividef(2.f, e + 1.f);
}
__device__ __forceinline__ void st_rel(unsigned* p, unsigned v) {
    asm volatile("st.release.gpu.global.u32 [%0],%1;" :: "l"(p), "r"(v) : "memory");
}
__device__ __forceinline__ unsigned ld_acq(const unsigned* p) {
    unsigned v;
    asm volatile("ld.acquire.gpu.global.u32 %0,[%1];" : "=r"(v) : "l"(p) : "memory");
    return v;
}
__device__ __forceinline__ void gbar(int bid, int tid, unsigned gen) {
    __syncthreads();
    if (tid == 0) st_rel(&g_fl[bid * 8], gen);
    if (tid < GRID) { while (ld_acq(&g_fl[tid * 8]) < gen) {} }
    __syncthreads();
}
__device__ __forceinline__ void pbar(int bid, int tid, unsigned gen) {
    __syncthreads();
    if (tid == 0) {
        st_rel(&g_pf[bid * 8], gen);
        while (ld_acq(&g_pf[(bid ^ 1) * 8]) < gen) {}
    }
    __syncthreads();
}
__device__ __forceinline__ void cpg(unsigned d, const void* s) {
    asm volatile("cp.async.cg.shared.global [%0],[%1],16;" :: "r"(d), "l"(s));
}
__device__ __forceinline__ void cpw(unsigned d, const void* s) {
    asm volatile("cp.async.ca.shared.global [%0],[%1],16;" :: "r"(d), "l"(s));
}
#define CPC asm volatile("cp.async.commit_group;" ::: "memory")
#define CPW1 asm volatile("cp.async.wait_group 1;" ::: "memory")
#define CPW0 asm volatile("cp.async.wait_group 0;" ::: "memory")

__device__ __forceinline__ void mma_bf16(float& c0, float& c1, float& c2, float& c3,
                                         unsigned a0, unsigned a1, unsigned a2, unsigned a3,
                                         unsigned b0, unsigned b1) {
    asm volatile("mma.sync.aligned.m16n8k16.row.col.f32.bf16.bf16.f32 "
                 "{%0,%1,%2,%3},{%4,%5,%6,%7},{%8,%9},{%0,%1,%2,%3};"
                 : "+f"(c0), "+f"(c1), "+f"(c2), "+f"(c3)
                 : "r"(a0), "r"(a1), "r"(a2), "r"(a3), "r"(b0), "r"(b1));
}

__global__ void k_init(const float* wi, const float* wh, const float* w1,
                       const float* w2, const float* lp, const float* dw,
                       const float* db, const float* aw) {
    int idx = blockIdx.x * blockDim.x + threadIdx.x;
    int stride = gridDim.x * blockDim.x;
    for (int i = idx; i < K2 * 4096; i += stride) {
        int k2 = i >> 12, np = i & 4095, n = np >> 1, p = np & 1, k = k2 * 2 + p;
        int ch = n >> 2, g = n & 3;
        float v = 0.f;
        if (k < 592) {
            if (g == 0) v = wi[ch * 592 + k];
            else if (g == 1) v = wi[(512 + ch) * 592 + k];
            else if (g == 2) v = wi[(1024 + ch) * 592 + k];
        } else if (k < 1104) {
            int kk = k - 592;
            if (g == 0) v = wh[ch * 512 + kk];
            else if (g == 1) v = wh[(512 + ch) * 512 + kk];
            else if (g == 3) v = wh[(1024 + ch) * 512 + kk];
        }
        __nv_bfloat16 h = __float2bfloat16(v);
        g_wph[k2][np] = h;
        g_wpl[k2][np] = __float2bfloat16(v - __bfloat162float(h));
    }
    for (int i = idx; i < 256 * 1024; i += stride) {
        int k2 = i >> 10, np = i & 1023, c = np >> 1, p = np & 1, k = k2 * 2 + p;
        float v = w1[c * 512 + k];
        __nv_bfloat16 h = __float2bfloat16(v);
        g_w1p[0][k2][np] = h;
        g_w1p[1][k2][np] = __float2bfloat16(v - __bfloat162float(h));
    }
    for (int i = idx; i < 256 * 352; i += stride) {
        int k2 = i / 352, np = i % 352, c = np >> 1, p = np & 1, k = k2 * 2 + p;
        float v = (c < 168) ? w2[c * 512 + k] : 0.f;
        __nv_bfloat16 h = __float2bfloat16(v);
        g_w2p[0][k2][np] = h;
        g_w2p[1][k2][np] = __float2bfloat16(v - __bfloat162float(h));
    }
    for (int i = idx; i < 2 * K2 * 128; i += stride) {
        ((__nv_bfloat16*)g_xh)[i] = __float2bfloat16(0.f);
        ((__nv_bfloat16*)g_xl)[i] = __float2bfloat16(0.f);
    }
    for (int i = idx; i < CC * BB; i += stride) ((float*)g_qf)[i] = 0.f;
    for (int i = idx; i < 256 * 20; i += stride) {
        int c = i / 20, j = i % 20;
        float v = 0.f;
        if (j < 8) v = lp[c * 8 + j];
        else if (j < 16) v = dw[c * 8 + (j - 8)];
        else if (j == 16) v = db[c];
        else if (j == 17) v = aw[c];
        g_sp[c][j] = v;
    }
    for (int i = idx; i < GRID * 8; i += stride) { g_fl[i] = 0u; g_pf[i] = 0u; }
}

__device__ __forceinline__ void st_pair(int buf, int k, int b, float v) {
    __nv_bfloat16 h = __float2bfloat16(v);
    g_xh[buf][k >> 1][b * 2 + (k & 1)] = h;
    g_xl[buf][k >> 1][b * 2 + (k & 1)] = __float2bfloat16(v - __bfloat162float(h));
}

// bf16 hi/lo MMA GEMM, tile 32b x 16c, K=512 (8 chunks of 32 k2).
// mode 1: t1 = tanh(v + bias) -> g_t1p pairs.  mode 0: g_dk[b][c] = v.
__device__ __forceinline__ void mma16(const __nv_bfloat16* ah, const __nv_bfloat16* al,
                                      const __nv_bfloat16* wh, const __nv_bfloat16* wl,
                                      int wstride, int c0, int b0,
                                      const float* bias, int mode,
                                      float* sm, int tid) {
    char* smc = (char*)sm;
    const int BUF = 16384;
    unsigned sbase = (unsigned)__cvta_generic_to_shared(smc);
    int lane = tid & 31;
    int wid = tid >> 5;
    int kz = wid & 3, tile = wid >> 2;
    int mi = tile & 1, ni = tile >> 1;     // valid for wid<16
    int gid = lane >> 2, tig = lane & 3;
    int aoff = (kz * 8 + tig) * 160 + (mi * 16 + gid) * 4;
    int boff = 10240 + (kz * 8 + tig) * 96 + (ni * 8 + gid) * 4;
    float c0r = 0.f, c1r = 0.f, c2r = 0.f, c3r = 0.f;

    #pragma unroll
    for (int pg = 0; pg < 2; pg++) {
        int kc2 = pg * 32;
        if (tid < 512) {
            int grp = tid >> 8, row = (tid >> 3) & 31, seg = tid & 7;
            unsigned dst = sbase + (unsigned)(pg * BUF + grp * 5120 + row * 160 + seg * 16);
            const char* src = (const char*)(grp ? al : ah)
                            + (size_t)(kc2 + row) * 256 + b0 * 4 + seg * 16;
            cpg(dst, src);
        } else if (tid < 768) {
            int u = tid - 512, grp = u >> 7, row = (u >> 2) & 31, seg = u & 3;
            unsigned dst = sbase + (unsigned)(pg * BUF + 10240 + grp * 3072 + row * 96 + seg * 16);
            const char* src = (const char*)(grp ? wl : wh)
                            + (size_t)(kc2 + row) * wstride * 2 + c0 * 4 + seg * 16;
            cpw(dst, src);
        }
        CPC;
    }
    for (int ch = 0; ch < 8; ch++) {
        if (ch < 7) CPW1; else CPW0;
        __syncthreads();
        if (ch + 2 < 8) {
            int kc2 = (ch + 2) * 32, st = (ch + 2) % 3;
            if (tid < 512) {
                int grp = tid >> 8, row = (tid >> 3) & 31, seg = tid & 7;
                unsigned dst = sbase + (unsigned)(st * BUF + grp * 5120 + row * 160 + seg * 16);
                const char* src = (const char*)(grp ? al : ah)
                                + (size_t)(kc2 + row) * 256 + b0 * 4 + seg * 16;
                cpg(dst, src);
            } else if (tid < 768) {
                int u = tid - 512, grp = u >> 7, row = (u >> 2) & 31, seg = u & 3;
                unsigned dst = sbase + (unsigned)(st * BUF + 10240 + grp * 3072 + row * 96 + seg * 16);
                const char* src = (const char*)(grp ? wl : wh)
                                + (size_t)(kc2 + row) * wstride * 2 + c0 * 4 + seg * 16;
                cpw(dst, src);
            }
            CPC;
        }
        if (wid < 16) {
            const char* tb = smc + (ch % 3) * BUF;
            unsigned ah0 = *(const unsigned*)(tb + aoff);
            unsigned ah1 = *(const unsigned*)(tb + aoff + 32);
            unsigned ah2 = *(const unsigned*)(tb + aoff + 640);
            unsigned ah3 = *(const unsigned*)(tb + aoff + 672);
            unsigned al0 = *(const unsigned*)(tb + 5120 + aoff);
            unsigned al1 = *(const unsigned*)(tb + 5120 + aoff + 32);
            unsigned al2 = *(const unsigned*)(tb + 5120 + aoff + 640);
            unsigned al3 = *(const unsigned*)(tb + 5120 + aoff + 672);
            unsigned bh0 = *(const unsigned*)(tb + boff);
            unsigned bh1 = *(const unsigned*)(tb + boff + 384);
            unsigned bl0 = *(const unsigned*)(tb + 3072 + boff);
            unsigned bl1 = *(const unsigned*)(tb + 3072 + boff + 384);
            mma_bf16(c0r, c1r, c2r, c3r, ah0, ah1, ah2, ah3, bh0, bh1);
            mma_bf16(c0r, c1r, c2r, c3r, ah0, ah1, ah2, ah3, bl0, bl1);
            mma_bf16(c0r, c1r, c2r, c3r, al0, al1, al2, al3, bh0, bh1);
        }
    }
    __syncthreads();
    float* red = sm;  // [4][32][17]
    if (wid < 16) {
        int ridx = kz * 544 + (mi * 16 + gid) * 17 + ni * 8 + tig * 2;
        red[ridx] = c0r; red[ridx + 1] = c1r;
        red[ridx + 136] = c2r; red[ridx + 137] = c3r;
    }
    __syncthreads();
    if (tid < 512) {
        int bl = tid & 31, chn = tid >> 5;
        float v = red[bl * 17 + chn] + red[544 + bl * 17 + chn]
                + red[1088 + bl * 17 + chn] + red[1632 + bl * 17 + chn];
        int c = c0 + chn, b = b0 + bl;
        if (mode) {
            v = tanh_fast(v + bias[c]);
            __nv_bfloat16 h = __float2bfloat16(v);
            g_t1p[0][c >> 1][b * 2 + (c & 1)] = h;
            g_t1p[1][c >> 1][b * 2 + (c & 1)] = __float2bfloat16(v - __bfloat162float(h));
        } else {
            g_dk[b][c] = v;
        }
    }
}

__global__ void __launch_bounds__(NTHR)
k_persist(const float* __restrict__ enc, const float* __restrict__ gt,
          const float* __restrict__ mask,
          const float* __restrict__ bi, const float* __restrict__ bh,
          const float* __restrict__ b1,
          const float* __restrict__ lw, const float* __restrict__ prior,
          float* __restrict__ out) {
    extern __shared__ __align__(16) float sm[];
    int bid = blockIdx.x, tid = threadIdx.x;
    int lane = tid & 31, wrp = tid >> 5;

    for (int t = 0;; t++) {
        int buf = t & 1, nbuf = buf ^ 1;
        if (t > 0) pbar(bid, tid, (unsigned)t);

        // ===== Phase A =====
        {
            int b = bid >> 1, half = bid & 1;
            float* s_al  = sm;
            float* s_mx  = sm + 256;
            float* s_sm2 = sm + 288;
            float* s_pt  = sm + 512;

            float a = 0.f, e = 0.f;
            if (t == 0) {
                if (tid < 256) a = (tid == 0) ? 1.f : 0.f;
            } else if (tid < 256) {
                e = __ldcg(&g_energy[b][tid]);
                float m = e;
                #pragma unroll
                for (int o = 16; o; o >>= 1) m = fmaxf(m, __shfl_xor_sync(0xffffffffu, m, o));
                if (lane == 0) s_mx[wrp] = m;
            }
            __syncthreads();
            if (t > 0 && tid < 256) {
                float bm = s_mx[0];
                #pragma unroll
                for (int i = 1; i < 8; i++) bm = fmaxf(bm, s_mx[i]);
                float p = __expf(e - bm);
                float ws = p;
                #pragma unroll
                for (int o = 16; o; o >>= 1) ws += __shfl_xor_sync(0xffffffffu, ws, o);
                if (lane == 0) s_sm2[wrp] = ws;
                a = p;
            }
            __syncthreads();
            if (tid < 256) {
                if (t > 0) {
                    float tot = 0.f;
                    #pragma unroll
                    for (int i = 0; i < 8; i++) tot += s_sm2[i];
                    a = __fdividef(a, tot);
                    if (half == 0) out[((size_t)b * TT + (t - 1)) * SS + tid] = a;
                }
                s_al[tid] = a;
                if (half == 0) g_alpha[b][tid] = a;
            }
            __syncthreads();
            if (t == TT) break;

            if (half == 0 && tid < HH)
                st_pair(buf, tid, b, gt[((size_t)b * TT + t) * HH + tid]);

            int col = tid & 255, slab = tid >> 8;
            const float* ep = enc + ((size_t)b * SS + slab * 64) * 512 + half * 256 + col;
            float acc0 = 0.f, acc1 = 0.f;
            #pragma unroll 8
            for (int s = 0; s < 64; s += 2) {
                acc0 = fmaf(s_al[slab * 64 + s], ep[(size_t)s * 512], acc0);
                acc1 = fmaf(s_al[slab * 64 + s + 1], ep[(size_t)(s + 1) * 512], acc1);
            }
            s_pt[tid] = acc0 + acc1;
            __syncthreads();
            if (tid < 256) {
                float v = s_pt[tid] + s_pt[256 + tid] + s_pt[512 + tid] + s_pt[768 + tid];
                st_pair(buf, HH + half * 256 + tid, b, v);
            }
        }
        gbar(bid, tid, (unsigned)t * 4u + 1u);

        // ===== Phase B: GRU GEMM via bf16 hi/lo mma + fused gates =====
        {
            int cg = bid >> 1, bt = bid & 1, b0 = bt * 32, c0 = cg * 32;
            char* smc = (char*)sm;
            const int RS = 160, TSZ = 32 * RS, BUF = 4 * TSZ;
            unsigned sbase = (unsigned)__cvta_generic_to_shared(smc);
            int row = (tid >> 3) & 31, seg = tid & 7, grp = tid >> 8;

            int wid2 = tid >> 5;
            int kz = wid2 & 3, tile = wid2 >> 2;
            int mi = tile & 1, ni = tile >> 1;
            int gid = lane >> 2, tig = lane & 3;
            int arow = (kz * 8 + tig) * RS;
            int aoff = arow + (mi * 16 + gid) * 4;
            int boff = arow + (ni * 8 + gid) * 4;
            float c0r = 0.f, c1r = 0.f, c2r = 0.f, c3r = 0.f;

            #pragma unroll
            for (int pg = 0; pg < 2; pg++) {
                int kc2 = pg * 32;
                unsigned dst = sbase + (unsigned)(pg * BUF + grp * TSZ + row * RS + seg * 16);
                const char* src;
                if (grp == 0) src = (const char*)&g_xh[buf][kc2 + row][0] + b0 * 4 + seg * 16;
                else if (grp == 1) src = (const char*)&g_xl[buf][kc2 + row][0] + b0 * 4 + seg * 16;
                else if (grp == 2) src = (const char*)&g_wph[kc2 + row][0] + c0 * 4 + seg * 16;
                else src = (const char*)&g_wpl[kc2 + row][0] + c0 * 4 + seg * 16;
                if (grp < 2) cpg(dst, src); else cpw(dst, src);
                CPC;
            }
            for (int ch = 0; ch < 18; ch++) {
                if (ch < 17) CPW1; else CPW0;
                __syncthreads();
                if (ch + 2 < 18) {
                    int kc2 = (ch + 2) * 32, st = (ch + 2) % 3;
                    unsigned dst = sbase + (unsigned)(st * BUF + grp * TSZ + row * RS + seg * 16);
                    const char* src;
                    if (grp == 0) src = (const char*)&g_xh[buf][kc2 + row][0] + b0 * 4 + seg * 16;
                    else if (grp == 1) src = (const char*)&g_xl[buf][kc2 + row][0] + b0 * 4 + seg * 16;
                    else if (grp == 2) src = (const char*)&g_wph[kc2 + row][0] + c0 * 4 + seg * 16;
                    else src = (const char*)&g_wpl[kc2 + row][0] + c0 * 4 + seg * 16;
                    if (grp < 2) cpg(dst, src); else cpw(dst, src);
                    CPC;
                }
                const char* tb = smc + (ch % 3) * BUF;
                unsigned ah0 = *(const unsigned*)(tb + aoff);
                unsigned ah1 = *(const unsigned*)(tb + aoff + 32);
                unsigned ah2 = *(const unsigned*)(tb + aoff + 640);
                unsigned ah3 = *(const unsigned*)(tb + aoff + 672);
                unsigned al0 = *(const unsigned*)(tb + TSZ + aoff);
                unsigned al1 = *(const unsigned*)(tb + TSZ + aoff + 32);
                unsigned al2 = *(const unsigned*)(tb + TSZ + aoff + 640);
                unsigned al3 = *(const unsigned*)(tb + TSZ + aoff + 672);
                unsigned bh0 = *(const unsigned*)(tb + 2 * TSZ + boff);
                unsigned bh1 = *(const unsigned*)(tb + 2 * TSZ + boff + 640);
                unsigned bl0 = *(const unsigned*)(tb + 3 * TSZ + boff);
                unsigned bl1 = *(const unsigned*)(tb + 3 * TSZ + boff + 640);
                mma_bf16(c0r, c1r, c2r, c3r, ah0, ah1, ah2, ah3, bh0, bh1);
                mma_bf16(c0r, c1r, c2r, c3r, ah0, ah1, ah2, ah3, bl0, bl1);
                mma_bf16(c0r, c1r, c2r, c3r, al0, al1, al2, al3, bh0, bh1);
            }
            __syncthreads();
            float* red = sm;  // [4][32][33]
            int ridx = kz * 1056 + (mi * 16 + gid) * 33 + ni * 8 + tig * 2;
            red[ridx] = c0r; red[ridx + 1] = c1r;
            red[ridx + 8 * 33] = c2r; red[ridx + 8 * 33 + 1] = c3r;
            __syncthreads();
            if (tid < 256) {
                int bl = tid & 31, chn = tid >> 5;
                float G[4];
                #pragma unroll
                for (int g = 0; g < 4; g++)
                    G[g] = red[bl * 33 + chn * 4 + g] + red[1056 + bl * 33 + chn * 4 + g]
                         + red[2112 + bl * 33 + chn * 4 + g] + red[3168 + bl * 33 + chn * 4 + g];
                int ch2 = cg * 8 + chn, bb2 = b0 + bl;
                float qold = __ldcg(&g_qf[ch2][bb2]);
                float rg = sig_fast(G[0] + bi[ch2] + bh[ch2]);
                float zg = sig_fast(G[1] + bi[512 + ch2] + bh[512 + ch2]);
                float ng = tanh_fast(G[2] + bi[1024 + ch2] + rg * (G[3] + bh[1024 + ch2]));
                float qn = (1.f - zg) * ng + zg * qold;
                g_qf[ch2][bb2] = qn;
                st_pair(nbuf, 592 + ch2, bb2, qn);
            }
        }
        gbar(bid, tid, (unsigned)t * 4u + 2u);

        // ===== Phase D: t1 = tanh(q @ w1^T + b1) via MMA (64 blocks) =====
        if (bid < 64)
            mma16(&g_xh[nbuf][296][0], &g_xl[nbuf][296][0],
                  &g_w1p[0][0][0], &g_w1p[1][0][0], 1024,
                  (bid >> 1) * 16, (bid & 1) * 32, b1, 1, sm, tid);
        gbar(bid, tid, (unsigned)t * 4u + 3u);

        // ===== Phase E: dk = t1 @ w2^T via MMA (22 blocks) =====
        if (bid < 22)
            mma16(&g_t1p[0][0][0], &g_t1p[1][0][0],
                  &g_w2p[0][0][0], &g_w2p[1][0][0], 352,
                  (bid >> 1) * 16, (bid & 1) * 32, (const float*)0, 0, sm, tid);
        gbar(bid, tid, (unsigned)t * 4u + 4u);

        // ===== Phase F =====
        {
            int b = bid >> 1, half = bid & 1, s0 = half * 128;
            float* s_a   = sm;
            float* s_lw  = sm + 160;
            float* s_dkk = sm + 336;
            float* s_ft  = sm + 512;
            float* s_pri = sm + 2560;
            float* s_sp  = sm + 2688;
            float* s_ps  = sm + 7808;

            if (tid < 148) {
                int s = s0 - 10 + tid;
                s_a[tid] = (s >= 0 && s < SS) ? __ldcg(&g_alpha[b][s]) : 0.f;
            }
            if (tid >= 160 && tid < 328) s_lw[tid - 160] = lw[tid - 160];
            if (tid >= 328 && tid < 496) s_dkk[tid - 328] = __ldcg(&g_dk[b][tid - 328]);
            #pragma unroll
            for (int it = 0; it < 5; it++)
                s_sp[tid + it * 1024] = ((const float*)g_sp)[tid + it * 1024];
            __syncthreads();

            #pragma unroll
            for (int it = 0; it < 2; it++) {
                int u = tid + it * 1024;
                int l = u & 15, si = u >> 4;
                const float* wv = (l < 8) ? &s_lw[l * 21] : &s_dkk[(l - 8) * 21];
                float a = 0.f;
                #pragma unroll
                for (int k = 0; k < 21; k++) a = fmaf(s_a[si + k], wv[k], a);
                s_ft[si * 16 + l] = a;
            }
            if (tid < 128) {
                float a = 0.f;
                #pragma unroll
                for (int k = 0; k < 11; k++) a = fmaf(s_a[tid + k], prior[k], a);
                s_pri[tid] = a;
            }
            __syncthreads();

            int si = tid & 127, sl = tid >> 7;
            float4 f0 = *(const float4*)&s_ft[si * 16];
            float4 f1 = *(const float4*)&s_ft[si * 16 + 4];
            float4 f2 = *(const float4*)&s_ft[si * 16 + 8];
            float4 f3 = *(const float4*)&s_ft[si * 16 + 12];
            float part = 0.f;
            for (int c = sl * 32; c < sl * 32 + 32; c++) {
                const float* P = &s_sp[c * 20];
                float4 p0 = *(const float4*)P, p1 = *(const float4*)(P + 4);
                float4 p2 = *(const float4*)(P + 8), p3 = *(const float4*)(P + 12);
                float sc = P[16];
                sc = fmaf(p0.x, f0.x, sc); sc = fmaf(p0.y, f0.y, sc);
                sc = fmaf(p0.z, f0.z, sc); sc = fmaf(p0.w, f0.w, sc);
                sc = fmaf(p1.x, f1.x, sc); sc = fmaf(p1.y, f1.y, sc);
                sc = fmaf(p1.z, f1.z, sc); sc = fmaf(p1.w, f1.w, sc);
                sc = fmaf(p2.x, f2.x, sc); sc = fmaf(p2.y, f2.y, sc);
                sc = fmaf(p2.z, f2.z, sc); sc = fmaf(p2.w, f2.w, sc);
                sc = fmaf(p3.x, f3.x, sc); sc = fmaf(p3.y, f3.y, sc);
                sc = fmaf(p3.z, f3.z, sc); sc = fmaf(p3.w, f3.w, sc);
                part = fmaf(P[17], tanh_fast(sc), part);
            }
            s_ps[sl * 128 + si] = part;
            __syncthreads();
            if (tid < 128) {
                float e = 0.f;
                #pragma unroll
                for (int i = 0; i < 8; i++) e += s_ps[i * 128 + tid];
                e += __logf(s_pri[tid] + 1e-5f);
                int s = s0 + tid;
                e = (mask[b * SS + s] > 0.f) ? e : -INFINITY;
                g_energy[b][s] = e;
            }
        }
    }
}

extern "C" void kernel_launch(void* const* d_in, const int* in_sizes, int n_in,
                              void* d_out, int out_size) {
    const float* enc   = (const float*)d_in[0];
    const float* mask  = (const float*)d_in[1];
    const float* gt    = (const float*)d_in[2];
    const float* wi    = (const float*)d_in[3];
    const float* wh    = (const float*)d_in[4];
    const float* bi    = (const float*)d_in[5];
    const float* bh    = (const float*)d_in[6];
    const float* lw    = (const float*)d_in[7];
    const float* lp    = (const float*)d_in[8];
    const float* w1    = (const float*)d_in[9];
    const float* b1    = (const float*)d_in[10];
    const float* w2    = (const float*)d_in[11];
    const float* dw    = (const float*)d_in[12];
    const float* db    = (const float*)d_in[13];
    const float* aw    = (const float*)d_in[14];
    const float* prior = (const float*)d_in[15];
    float* out = (float*)d_out;

    static int cfg_done = 0;
    if (!cfg_done) {
        cudaFuncSetAttribute(k_persist, cudaFuncAttributeMaxDynamicSharedMemorySize, 65536);
        cfg_done = 1;
    }
    k_init<<<512, 256>>>(wi, wh, w1, w2, lp, dw, db, aw);
    k_persist<<<GRID, NTHR, 65536>>>(enc, gt, mask, bi, bh, b1, lw, prior, out);
}

// round 13
// speedup vs baseline: 2.2581x; 1.0555x over previous
#include <cuda_runtime.h>
#include <cuda_bf16.h>
#include <math.h>

#define BB 64
#define SS 256
#define HH 80
#define TT 600
#define CC 512
#define K2 576
#define GRID 128
#define NTHR 1024

__device__ __nv_bfloat16 g_xh[2][K2][128];
__device__ __nv_bfloat16 g_xl[2][K2][128];
__device__ __nv_bfloat16 g_wph[K2][4096];
__device__ __nv_bfloat16 g_wpl[K2][4096];
__device__ __nv_bfloat16 g_w1p[2][256][1024];
__device__ __nv_bfloat16 g_w2p[2][256][352];
__device__ __nv_bfloat16 g_t1p[2][256][128];
__device__ float g_qf[CC][BB];
__device__ float g_dk[BB][176];
__device__ float g_sp[256][20];
__device__ float g_energy[BB][SS];
__device__ float g_alpha[BB][SS];
__device__ unsigned g_fl[GRID * 8];
__device__ unsigned g_pf[GRID * 8];
__device__ unsigned g_df[GRID * 8];

__device__ __forceinline__ float sig_fast(float x) {
    return __fdividef(1.f, 1.f + __expf(-x));
}
__device__ __forceinline__ float tanh_fast(float x) {
    float e = __expf(2.f * x);
    return 1.f - __fdividef(2.f, e + 1.f);
}
__device__ __forceinline__ void st_rel(unsigned* p, unsigned v) {
    asm volatile("st.release.gpu.global.u32 [%0],%1;" :: "l"(p), "r"(v) : "memory");
}
__device__ __forceinline__ unsigned ld_acq(const unsigned* p) {
    unsigned v;
    asm volatile("ld.acquire.gpu.global.u32 %0,[%1];" : "=r"(v) : "l"(p) : "memory");
    return v;
}
__device__ __forceinline__ void gbar(int bid, int tid, unsigned gen) {
    __syncthreads();
    if (tid == 0) st_rel(&g_fl[bid * 8], gen);
    if (tid < GRID) { while (ld_acq(&g_fl[tid * 8]) < gen) {} }
    __syncthreads();
}
__device__ __forceinline__ void pbar(int bid, int tid, unsigned gen) {
    __syncthreads();
    if (tid == 0) {
        st_rel(&g_pf[bid * 8], gen);
        while (ld_acq(&g_pf[(bid ^ 1) * 8]) < gen) {}
    }
    __syncthreads();
}
__device__ __forceinline__ void cpg(unsigned d, const void* s) {
    asm volatile("cp.async.cg.shared.global [%0],[%1],16;" :: "r"(d), "l"(s));
}
__device__ __forceinline__ void cpw(unsigned d, const void* s) {
    asm volatile("cp.async.ca.shared.global [%0],[%1],16;" :: "r"(d), "l"(s));
}
#define CPC asm volatile("cp.async.commit_group;" ::: "memory")
#define CPW1 asm volatile("cp.async.wait_group 1;" ::: "memory")
#define CPW0 asm volatile("cp.async.wait_group 0;" ::: "memory")

__device__ __forceinline__ void mma_bf16(float& c0, float& c1, float& c2, float& c3,
                                         unsigned a0, unsigned a1, unsigned a2, unsigned a3,
                                         unsigned b0, unsigned b1) {
    asm volatile("mma.sync.aligned.m16n8k16.row.col.f32.bf16.bf16.f32 "
                 "{%0,%1,%2,%3},{%4,%5,%6,%7},{%8,%9},{%0,%1,%2,%3};"
                 : "+f"(c0), "+f"(c1), "+f"(c2), "+f"(c3)
                 : "r"(a0), "r"(a1), "r"(a2), "r"(a3), "r"(b0), "r"(b1));
}
// packed dual fp32 FMA: d = a*b + d
__device__ __forceinline__ void fma2(unsigned long long& d, unsigned long long a,
                                     unsigned long long b) {
    asm("fma.rn.f32x2 %0, %1, %2, %0;" : "+l"(d) : "l"(a), "l"(b));
}

__global__ void k_init(const float* wi, const float* wh, const float* w1,
                       const float* w2, const float* lp, const float* dw,
                       const float* db, const float* aw) {
    int idx = blockIdx.x * blockDim.x + threadIdx.x;
    int stride = gridDim.x * blockDim.x;
    for (int i = idx; i < K2 * 4096; i += stride) {
        int k2 = i >> 12, np = i & 4095, n = np >> 1, p = np & 1, k = k2 * 2 + p;
        int ch = n >> 2, g = n & 3;
        float v = 0.f;
        if (k < 592) {
            if (g == 0) v = wi[ch * 592 + k];
            else if (g == 1) v = wi[(512 + ch) * 592 + k];
            else if (g == 2) v = wi[(1024 + ch) * 592 + k];
        } else if (k < 1104) {
            int kk = k - 592;
            if (g == 0) v = wh[ch * 512 + kk];
            else if (g == 1) v = wh[(512 + ch) * 512 + kk];
            else if (g == 3) v = wh[(1024 + ch) * 512 + kk];
        }
        __nv_bfloat16 h = __float2bfloat16(v);
        g_wph[k2][np] = h;
        g_wpl[k2][np] = __float2bfloat16(v - __bfloat162float(h));
    }
    for (int i = idx; i < 256 * 1024; i += stride) {
        int k2 = i >> 10, np = i & 1023, c = np >> 1, p = np & 1, k = k2 * 2 + p;
        float v = w1[c * 512 + k];
        __nv_bfloat16 h = __float2bfloat16(v);
        g_w1p[0][k2][np] = h;
        g_w1p[1][k2][np] = __float2bfloat16(v - __bfloat162float(h));
    }
    for (int i = idx; i < 256 * 352; i += stride) {
        int k2 = i / 352, np = i % 352, c = np >> 1, p = np & 1, k = k2 * 2 + p;
        float v = (c < 168) ? w2[c * 512 + k] : 0.f;
        __nv_bfloat16 h = __float2bfloat16(v);
        g_w2p[0][k2][np] = h;
        g_w2p[1][k2][np] = __float2bfloat16(v - __bfloat162float(h));
    }
    for (int i = idx; i < 2 * K2 * 128; i += stride) {
        ((__nv_bfloat16*)g_xh)[i] = __float2bfloat16(0.f);
        ((__nv_bfloat16*)g_xl)[i] = __float2bfloat16(0.f);
    }
    for (int i = idx; i < CC * BB; i += stride) ((float*)g_qf)[i] = 0.f;
    for (int i = idx; i < 256 * 20; i += stride) {
        int c = i / 20, j = i % 20;
        float v = 0.f;
        if (j < 8) v = lp[c * 8 + j];
        else if (j < 16) v = dw[c * 8 + (j - 8)];
        else if (j == 16) v = db[c];
        else if (j == 17) v = aw[c];
        g_sp[c][j] = v;
    }
    for (int i = idx; i < GRID * 8; i += stride) {
        g_fl[i] = 0u; g_pf[i] = 0u; g_df[i] = 0u;
    }
}

__device__ __forceinline__ void st_pair(int buf, int k, int b, float v) {
    __nv_bfloat16 h = __float2bfloat16(v);
    g_xh[buf][k >> 1][b * 2 + (k & 1)] = h;
    g_xl[buf][k >> 1][b * 2 + (k & 1)] = __float2bfloat16(v - __bfloat162float(h));
}

// bf16 hi/lo MMA GEMM, tile 32b x 16c, K=512 (8 chunks of 32 k2).
__device__ __forceinline__ void mma16(const __nv_bfloat16* ah, const __nv_bfloat16* al,
                                      const __nv_bfloat16* wh, const __nv_bfloat16* wl,
                                      int wstride, int c0, int b0,
                                      const float* bias, int mode,
                                      float* sm, int tid) {
    char* smc = (char*)sm;
    const int BUF = 16384;
    unsigned sbase = (unsigned)__cvta_generic_to_shared(smc);
    int lane = tid & 31;
    int wid = tid >> 5;
    int kz = wid & 3, tile = wid >> 2;
    int mi = tile & 1, ni = tile >> 1;
    int gid = lane >> 2, tig = lane & 3;
    int aoff = (kz * 8 + tig) * 160 + (mi * 16 + gid) * 4;
    int boff = 10240 + (kz * 8 + tig) * 96 + (ni * 8 + gid) * 4;
    float c0r = 0.f, c1r = 0.f, c2r = 0.f, c3r = 0.f;

    #pragma unroll
    for (int pg = 0; pg < 2; pg++) {
        int kc2 = pg * 32;
        if (tid < 512) {
            int grp = tid >> 8, row = (tid >> 3) & 31, seg = tid & 7;
            unsigned dst = sbase + (unsigned)(pg * BUF + grp * 5120 + row * 160 + seg * 16);
            const char* src = (const char*)(grp ? al : ah)
                            + (size_t)(kc2 + row) * 256 + b0 * 4 + seg * 16;
            cpg(dst, src);
        } else if (tid < 768) {
            int u = tid - 512, grp = u >> 7, row = (u >> 2) & 31, seg = u & 3;
            unsigned dst = sbase + (unsigned)(pg * BUF + 10240 + grp * 3072 + row * 96 + seg * 16);
            const char* src = (const char*)(grp ? wl : wh)
                            + (size_t)(kc2 + row) * wstride * 2 + c0 * 4 + seg * 16;
            cpw(dst, src);
        }
        CPC;
    }
    for (int ch = 0; ch < 8; ch++) {
        if (ch < 7) CPW1; else CPW0;
        __syncthreads();
        if (ch + 2 < 8) {
            int kc2 = (ch + 2) * 32, st = (ch + 2) % 3;
            if (tid < 512) {
                int grp = tid >> 8, row = (tid >> 3) & 31, seg = tid & 7;
                unsigned dst = sbase + (unsigned)(st * BUF + grp * 5120 + row * 160 + seg * 16);
                const char* src = (const char*)(grp ? al : ah)
                                + (size_t)(kc2 + row) * 256 + b0 * 4 + seg * 16;
                cpg(dst, src);
            } else if (tid < 768) {
                int u = tid - 512, grp = u >> 7, row = (u >> 2) & 31, seg = u & 3;
                unsigned dst = sbase + (unsigned)(st * BUF + 10240 + grp * 3072 + row * 96 + seg * 16);
                const char* src = (const char*)(grp ? wl : wh)
                                + (size_t)(kc2 + row) * wstride * 2 + c0 * 4 + seg * 16;
                cpw(dst, src);
            }
            CPC;
        }
        if (wid < 16) {
            const char* tb = smc + (ch % 3) * BUF;
            unsigned ah0 = *(const unsigned*)(tb + aoff);
            unsigned ah1 = *(const unsigned*)(tb + aoff + 32);
            unsigned ah2 = *(const unsigned*)(tb + aoff + 640);
            unsigned ah3 = *(const unsigned*)(tb + aoff + 672);
            unsigned al0 = *(const unsigned*)(tb + 5120 + aoff);
            unsigned al1 = *(const unsigned*)(tb + 5120 + aoff + 32);
            unsigned al2 = *(const unsigned*)(tb + 5120 + aoff + 640);
            unsigned al3 = *(const unsigned*)(tb + 5120 + aoff + 672);
            unsigned bh0 = *(const unsigned*)(tb + boff);
            unsigned bh1 = *(const unsigned*)(tb + boff + 384);
            unsigned bl0 = *(const unsigned*)(tb + 3072 + boff);
            unsigned bl1 = *(const unsigned*)(tb + 3072 + boff + 384);
            mma_bf16(c0r, c1r, c2r, c3r, ah0, ah1, ah2, ah3, bh0, bh1);
            mma_bf16(c0r, c1r, c2r, c3r, ah0, ah1, ah2, ah3, bl0, bl1);
            mma_bf16(c0r, c1r, c2r, c3r, al0, al1, al2, al3, bh0, bh1);
        }
    }
    __syncthreads();
    float* red = sm;
    if (wid < 16) {
        int ridx = kz * 544 + (mi * 16 + gid) * 17 + ni * 8 + tig * 2;
        red[ridx] = c0r; red[ridx + 1] = c1r;
        red[ridx + 136] = c2r; red[ridx + 137] = c3r;
    }
    __syncthreads();
    if (tid < 512) {
        int bl = tid & 31, chn = tid >> 5;
        float v = red[bl * 17 + chn] + red[544 + bl * 17 + chn]
                + red[1088 + bl * 17 + chn] + red[1632 + bl * 17 + chn];
        int c = c0 + chn, b = b0 + bl;
        if (mode) {
            v = tanh_fast(v + bias[c]);
            __nv_bfloat16 h = __float2bfloat16(v);
            g_t1p[0][c >> 1][b * 2 + (c & 1)] = h;
            g_t1p[1][c >> 1][b * 2 + (c & 1)] = __float2bfloat16(v - __bfloat162float(h));
        } else {
            g_dk[b][c] = v;
        }
    }
}

__global__ void __launch_bounds__(NTHR)
k_persist(const float* __restrict__ enc, const float* __restrict__ gt,
          const float* __restrict__ mask,
          const float* __restrict__ bi, const float* __restrict__ bh,
          const float* __restrict__ b1,
          const float* __restrict__ lw, const float* __restrict__ prior,
          float* __restrict__ out) {
    extern __shared__ __align__(16) float sm[];
    int bid = blockIdx.x, tid = threadIdx.x;
    int lane = tid & 31, wrp = tid >> 5;

    for (int t = 0;; t++) {
        int buf = t & 1, nbuf = buf ^ 1;
        if (t > 0) pbar(bid, tid, (unsigned)t);

        // ===== Phase A =====
        {
            int b = bid >> 1, half = bid & 1;
            float* s_al  = sm;
            float* s_mx  = sm + 256;
            float* s_sm2 = sm + 288;
            float* s_pt  = sm + 512;

            float a = 0.f, e = 0.f;
            if (t == 0) {
                if (tid < 256) a = (tid == 0) ? 1.f : 0.f;
            } else if (tid < 256) {
                e = __ldcg(&g_energy[b][tid]);
                float m = e;
                #pragma unroll
                for (int o = 16; o; o >>= 1) m = fmaxf(m, __shfl_xor_sync(0xffffffffu, m, o));
                if (lane == 0) s_mx[wrp] = m;
            }
            __syncthreads();
            if (t > 0 && tid < 256) {
                float bm = s_mx[0];
                #pragma unroll
                for (int i = 1; i < 8; i++) bm = fmaxf(bm, s_mx[i]);
                float p = __expf(e - bm);
                float ws = p;
                #pragma unroll
                for (int o = 16; o; o >>= 1) ws += __shfl_xor_sync(0xffffffffu, ws, o);
                if (lane == 0) s_sm2[wrp] = ws;
                a = p;
            }
            __syncthreads();
            if (tid < 256) {
                if (t > 0) {
                    float tot = 0.f;
                    #pragma unroll
                    for (int i = 0; i < 8; i++) tot += s_sm2[i];
                    a = __fdividef(a, tot);
                    if (half == 0) out[((size_t)b * TT + (t - 1)) * SS + tid] = a;
                }
                s_al[tid] = a;
                if (half == 0) g_alpha[b][tid] = a;
            }
            __syncthreads();
            if (t == TT) break;

            if (half == 0 && tid < HH)
                st_pair(buf, tid, b, gt[((size_t)b * TT + t) * HH + tid]);

            int col = tid & 255, slab = tid >> 8;
            const float* ep = enc + ((size_t)b * SS + slab * 64) * 512 + half * 256 + col;
            float acc0 = 0.f, acc1 = 0.f;
            #pragma unroll 8
            for (int s = 0; s < 64; s += 2) {
                acc0 = fmaf(s_al[slab * 64 + s], __ldcg(&ep[(size_t)s * 512]), acc0);
                acc1 = fmaf(s_al[slab * 64 + s + 1], __ldcg(&ep[(size_t)(s + 1) * 512]), acc1);
            }
            s_pt[tid] = acc0 + acc1;
            __syncthreads();
            if (tid < 256) {
                float v = s_pt[tid] + s_pt[256 + tid] + s_pt[512 + tid] + s_pt[768 + tid];
                st_pair(buf, HH + half * 256 + tid, b, v);
            }
        }
        gbar(bid, tid, (unsigned)t * 4u + 1u);

        // ===== Phase B: GRU GEMM via bf16 hi/lo mma + fused gates =====
        {
            int cg = bid >> 1, bt = bid & 1, b0 = bt * 32, c0 = cg * 32;
            char* smc = (char*)sm;
            const int RS = 160, TSZ = 32 * RS, BUF = 4 * TSZ;
            unsigned sbase = (unsigned)__cvta_generic_to_shared(smc);
            int row = (tid >> 3) & 31, seg = tid & 7, grp = tid >> 8;

            int wid2 = tid >> 5;
            int kz = wid2 & 3, tile = wid2 >> 2;
            int mi = tile & 1, ni = tile >> 1;
            int gid = lane >> 2, tig = lane & 3;
            int arow = (kz * 8 + tig) * RS;
            int aoff = arow + (mi * 16 + gid) * 4;
            int boff = arow + (ni * 8 + gid) * 4;
            float c0r = 0.f, c1r = 0.f, c2r = 0.f, c3r = 0.f;

            #pragma unroll
            for (int pg = 0; pg < 2; pg++) {
                int kc2 = pg * 32;
                unsigned dst = sbase + (unsigned)(pg * BUF + grp * TSZ + row * RS + seg * 16);
                const char* src;
                if (grp == 0) src = (const char*)&g_xh[buf][kc2 + row][0] + b0 * 4 + seg * 16;
                else if (grp == 1) src = (const char*)&g_xl[buf][kc2 + row][0] + b0 * 4 + seg * 16;
                else if (grp == 2) src = (const char*)&g_wph[kc2 + row][0] + c0 * 4 + seg * 16;
                else src = (const char*)&g_wpl[kc2 + row][0] + c0 * 4 + seg * 16;
                if (grp < 2) cpg(dst, src); else cpw(dst, src);
                CPC;
            }
            for (int ch = 0; ch < 18; ch++) {
                if (ch < 17) CPW1; else CPW0;
                __syncthreads();
                if (ch + 2 < 18) {
                    int kc2 = (ch + 2) * 32, st = (ch + 2) % 3;
                    unsigned dst = sbase + (unsigned)(st * BUF + grp * TSZ + row * RS + seg * 16);
                    const char* src;
                    if (grp == 0) src = (const char*)&g_xh[buf][kc2 + row][0] + b0 * 4 + seg * 16;
                    else if (grp == 1) src = (const char*)&g_xl[buf][kc2 + row][0] + b0 * 4 + seg * 16;
                    else if (grp == 2) src = (const char*)&g_wph[kc2 + row][0] + c0 * 4 + seg * 16;
                    else src = (const char*)&g_wpl[kc2 + row][0] + c0 * 4 + seg * 16;
                    if (grp < 2) cpg(dst, src); else cpw(dst, src);
                    CPC;
                }
                const char* tb = smc + (ch % 3) * BUF;
                unsigned ah0 = *(const unsigned*)(tb + aoff);
                unsigned ah1 = *(const unsigned*)(tb + aoff + 32);
                unsigned ah2 = *(const unsigned*)(tb + aoff + 640);
                unsigned ah3 = *(const unsigned*)(tb + aoff + 672);
                unsigned al0 = *(const unsigned*)(tb + TSZ + aoff);
                unsigned al1 = *(const unsigned*)(tb + TSZ + aoff + 32);
                unsigned al2 = *(const unsigned*)(tb + TSZ + aoff + 640);
                unsigned al3 = *(const unsigned*)(tb + TSZ + aoff + 672);
                unsigned bh0 = *(const unsigned*)(tb + 2 * TSZ + boff);
                unsigned bh1 = *(const unsigned*)(tb + 2 * TSZ + boff + 640);
                unsigned bl0 = *(const unsigned*)(tb + 3 * TSZ + boff);
                unsigned bl1 = *(const unsigned*)(tb + 3 * TSZ + boff + 640);
                mma_bf16(c0r, c1r, c2r, c3r, ah0, ah1, ah2, ah3, bh0, bh1);
                mma_bf16(c0r, c1r, c2r, c3r, ah0, ah1, ah2, ah3, bl0, bl1);
                mma_bf16(c0r, c1r, c2r, c3r, al0, al1, al2, al3, bh0, bh1);
            }
            __syncthreads();
            float* red = sm;
            int ridx = kz * 1056 + (mi * 16 + gid) * 33 + ni * 8 + tig * 2;
            red[ridx] = c0r; red[ridx + 1] = c1r;
            red[ridx + 8 * 33] = c2r; red[ridx + 8 * 33 + 1] = c3r;
            __syncthreads();
            if (tid < 256) {
                int bl = tid & 31, chn = tid >> 5;
                float G[4];
                #pragma unroll
                for (int g = 0; g < 4; g++)
                    G[g] = red[bl * 33 + chn * 4 + g] + red[1056 + bl * 33 + chn * 4 + g]
                         + red[2112 + bl * 33 + chn * 4 + g] + red[3168 + bl * 33 + chn * 4 + g];
                int ch2 = cg * 8 + chn, bb2 = b0 + bl;
                float qold = __ldcg(&g_qf[ch2][bb2]);
                float rg = sig_fast(G[0] + bi[ch2] + bh[ch2]);
                float zg = sig_fast(G[1] + bi[512 + ch2] + bh[512 + ch2]);
                float ng = tanh_fast(G[2] + bi[1024 + ch2] + rg * (G[3] + bh[1024 + ch2]));
                float qn = (1.f - zg) * ng + zg * qold;
                g_qf[ch2][bb2] = qn;
                st_pair(nbuf, 592 + ch2, bb2, qn);
            }
        }
        gbar(bid, tid, (unsigned)t * 4u + 2u);

        // ===== Phase D+E fused: D on blocks 0-63, flags, E on blocks 0-21 =====
        if (bid < 64) {
            mma16(&g_xh[nbuf][296][0], &g_xl[nbuf][296][0],
                  &g_w1p[0][0][0], &g_w1p[1][0][0], 1024,
                  (bid >> 1) * 16, (bid & 1) * 32, b1, 1, sm, tid);
            __syncthreads();
            if (tid == 0) st_rel(&g_df[bid * 8], (unsigned)(t + 1));
            if (bid < 22) {
                if (tid < 64) { while (ld_acq(&g_df[tid * 8]) < (unsigned)(t + 1)) {} }
                __syncthreads();
                mma16(&g_t1p[0][0][0], &g_t1p[1][0][0],
                      &g_w2p[0][0][0], &g_w2p[1][0][0], 352,
                      (bid >> 1) * 16, (bid & 1) * 32, (const float*)0, 0, sm, tid);
            }
        }
        gbar(bid, tid, (unsigned)t * 4u + 3u);

        // ===== Phase F (f32x2 score loop) =====
        {
            int b = bid >> 1, half = bid & 1, s0 = half * 128;
            float* s_a   = sm;
            float* s_lw  = sm + 160;
            float* s_dkk = sm + 336;
            float* s_ft  = sm + 512;
            float* s_pri = sm + 2560;
            float* s_sp  = sm + 2688;
            float* s_ps  = sm + 7808;

            if (tid < 148) {
                int s = s0 - 10 + tid;
                s_a[tid] = (s >= 0 && s < SS) ? __ldcg(&g_alpha[b][s]) : 0.f;
            }
            if (tid >= 160 && tid < 328) s_lw[tid - 160] = lw[tid - 160];
            if (tid >= 328 && tid < 496) s_dkk[tid - 328] = __ldcg(&g_dk[b][tid - 328]);
            #pragma unroll
            for (int it = 0; it < 5; it++)
                s_sp[tid + it * 1024] = ((const float*)g_sp)[tid + it * 1024];
            __syncthreads();

            #pragma unroll
            for (int it = 0; it < 2; it++) {
                int u = tid + it * 1024;
                int l = u & 15, si = u >> 4;
                const float* wv = (l < 8) ? &s_lw[l * 21] : &s_dkk[(l - 8) * 21];
                float a = 0.f;
                #pragma unroll
                for (int k = 0; k < 21; k++) a = fmaf(s_a[si + k], wv[k], a);
                s_ft[si * 16 + l] = a;
            }
            if (tid < 128) {
                float a = 0.f;
                #pragma unroll
                for (int k = 0; k < 11; k++) a = fmaf(s_a[tid + k], prior[k], a);
                s_pri[tid] = a;
            }
            __syncthreads();

            int si = tid & 127, sl = tid >> 7;
            const ulonglong2* fp = (const ulonglong2*)&s_ft[si * 16];
            ulonglong2 f01 = fp[0], f23 = fp[1], f45 = fp[2], f67 = fp[3];
            float part = 0.f;
            for (int c = sl * 32; c < sl * 32 + 32; c++) {
                const float* P = &s_sp[c * 20];
                const ulonglong2* pp = (const ulonglong2*)P;
                ulonglong2 p01 = pp[0], p23 = pp[1], p45 = pp[2], p67 = pp[3];
                unsigned long long acc = (unsigned long long)__float_as_uint(P[16]);
                fma2(acc, p01.x, f01.x); fma2(acc, p01.y, f01.y);
                fma2(acc, p23.x, f23.x); fma2(acc, p23.y, f23.y);
                fma2(acc, p45.x, f45.x); fma2(acc, p45.y, f45.y);
                fma2(acc, p67.x, f67.x); fma2(acc, p67.y, f67.y);
                float sc = __uint_as_float((unsigned)acc) +
                           __uint_as_float((unsigned)(acc >> 32));
                part = fmaf(P[17], tanh_fast(sc), part);
            }
            s_ps[sl * 128 + si] = part;
            __syncthreads();
            if (tid < 128) {
                float e = 0.f;
                #pragma unroll
                for (int i = 0; i < 8; i++) e += s_ps[i * 128 + tid];
                e += __logf(s_pri[tid] + 1e-5f);
                int s = s0 + tid;
                e = (mask[b * SS + s] > 0.f) ? e : -INFINITY;
                g_energy[b][s] = e;
            }
        }
    }
}

extern "C" void kernel_launch(void* const* d_in, const int* in_sizes, int n_in,
                              void* d_out, int out_size) {
    const float* enc   = (const float*)d_in[0];
    const float* mask  = (const float*)d_in[1];
    const float* gt    = (const float*)d_in[2];
    const float* wi    = (const float*)d_in[3];
    const float* wh    = (const float*)d_in[4];
    const float* bi    = (const float*)d_in[5];
    const float* bh    = (const float*)d_in[6];
    const float* lw    = (const float*)d_in[7];
    const float* lp    = (const float*)d_in[8];
    const float* w1    = (const float*)d_in[9];
    const float* b1    = (const float*)d_in[10];
    const float* w2    = (const float*)d_in[11];
    const float* dw    = (const float*)d_in[12];
    const float* db    = (const float*)d_in[13];
    const float* aw    = (const float*)d_in[14];
    const float* prior = (const float*)d_in[15];
    float* out = (float*)d_out;

    static int cfg_done = 0;
    if (!cfg_done) {
        cudaFuncSetAttribute(k_persist, cudaFuncAttributeMaxDynamicSharedMemorySize, 65536);
        cfg_done = 1;
    }
    k_init<<<512, 256>>>(wi, wh, w1, w2, lp, dw, db, aw);
    k_persist<<<GRID, NTHR, 65536>>>(enc, gt, mask, bi, bh, b1, lw, prior, out);
}

// round 14
// speedup vs baseline: 2.3711x; 1.0500x over previous
#include <cuda_runtime.h>
#include <cuda_bf16.h>
#include <math.h>

#define BB 64
#define SS 256
#define HH 80
#define TT 600
#define CC 512
#define K2 576
#define GRID 128
#define NTHR 1024

__device__ __nv_bfloat16 g_xh[2][K2][128];
__device__ __nv_bfloat16 g_xl[2][K2][128];
__device__ __nv_bfloat16 g_wph[K2][4096];
__device__ __nv_bfloat16 g_wpl[K2][4096];
__device__ __nv_bfloat16 g_w1p[2][256][1024];
__device__ __nv_bfloat16 g_w2p[2][256][352];
__device__ __nv_bfloat16 g_t1p[2][256][128];
__device__ float g_qf[CC][BB];
__device__ float g_dk[BB][176];
__device__ float g_sp[256][20];
__device__ float g_energy[BB][SS];
__device__ float g_alpha[BB][SS];
__device__ unsigned g_pf[GRID * 8];
__device__ unsigned g_fa[GRID * 8];
__device__ unsigned g_fb[GRID * 8];
__device__ unsigned g_df[GRID * 8];
__device__ unsigned g_fe[GRID * 8];

__device__ __forceinline__ float sig_fast(float x) {
    return __fdividef(1.f, 1.f + __expf(-x));
}
__device__ __forceinline__ float tanh_fast(float x) {
    float e = __expf(2.f * x);
    return 1.f - __fdividef(2.f, e + 1.f);
}
__device__ __forceinline__ void st_rel(unsigned* p, unsigned v) {
    asm volatile("st.release.gpu.global.u32 [%0],%1;" :: "l"(p), "r"(v) : "memory");
}
__device__ __forceinline__ unsigned ld_acq(const unsigned* p) {
    unsigned v;
    asm volatile("ld.acquire.gpu.global.u32 %0,[%1];" : "=r"(v) : "l"(p) : "memory");
    return v;
}
__device__ __forceinline__ void pbar(int bid, int tid, unsigned gen) {
    __syncthreads();
    if (tid == 0) {
        st_rel(&g_pf[bid * 8], gen);
        while (ld_acq(&g_pf[(bid ^ 1) * 8]) < gen) {}
    }
    __syncthreads();
}
__device__ __forceinline__ void cpg(unsigned d, const void* s) {
    asm volatile("cp.async.cg.shared.global [%0],[%1],16;" :: "r"(d), "l"(s));
}
__device__ __forceinline__ void cpw(unsigned d, const void* s) {
    asm volatile("cp.async.ca.shared.global [%0],[%1],16;" :: "r"(d), "l"(s));
}
#define CPC asm volatile("cp.async.commit_group;" ::: "memory")
#define CPW1 asm volatile("cp.async.wait_group 1;" ::: "memory")
#define CPW0 asm volatile("cp.async.wait_group 0;" ::: "memory")

__device__ __forceinline__ void mma_bf16(float& c0, float& c1, float& c2, float& c3,
                                         unsigned a0, unsigned a1, unsigned a2, unsigned a3,
                                         unsigned b0, unsigned b1) {
    asm volatile("mma.sync.aligned.m16n8k16.row.col.f32.bf16.bf16.f32 "
                 "{%0,%1,%2,%3},{%4,%5,%6,%7},{%8,%9},{%0,%1,%2,%3};"
                 : "+f"(c0), "+f"(c1), "+f"(c2), "+f"(c3)
                 : "r"(a0), "r"(a1), "r"(a2), "r"(a3), "r"(b0), "r"(b1));
}
__device__ __forceinline__ void fma2(unsigned long long& d, unsigned long long a,
                                     unsigned long long b) {
    asm("fma.rn.f32x2 %0, %1, %2, %0;" : "+l"(d) : "l"(a), "l"(b));
}

__global__ void k_init(const float* wi, const float* wh, const float* w1,
                       const float* w2, const float* lp, const float* dw,
                       const float* db, const float* aw) {
    int idx = blockIdx.x * blockDim.x + threadIdx.x;
    int stride = gridDim.x * blockDim.x;
    for (int i = idx; i < K2 * 4096; i += stride) {
        int k2 = i >> 12, np = i & 4095, n = np >> 1, p = np & 1, k = k2 * 2 + p;
        int ch = n >> 2, g = n & 3;
        float v = 0.f;
        if (k < 592) {
            if (g == 0) v = wi[ch * 592 + k];
            else if (g == 1) v = wi[(512 + ch) * 592 + k];
            else if (g == 2) v = wi[(1024 + ch) * 592 + k];
        } else if (k < 1104) {
            int kk = k - 592;
            if (g == 0) v = wh[ch * 512 + kk];
            else if (g == 1) v = wh[(512 + ch) * 512 + kk];
            else if (g == 3) v = wh[(1024 + ch) * 512 + kk];
        }
        __nv_bfloat16 h = __float2bfloat16(v);
        g_wph[k2][np] = h;
        g_wpl[k2][np] = __float2bfloat16(v - __bfloat162float(h));
    }
    for (int i = idx; i < 256 * 1024; i += stride) {
        int k2 = i >> 10, np = i & 1023, c = np >> 1, p = np & 1, k = k2 * 2 + p;
        float v = w1[c * 512 + k];
        __nv_bfloat16 h = __float2bfloat16(v);
        g_w1p[0][k2][np] = h;
        g_w1p[1][k2][np] = __float2bfloat16(v - __bfloat162float(h));
    }
    for (int i = idx; i < 256 * 352; i += stride) {
        int k2 = i / 352, np = i % 352, c = np >> 1, p = np & 1, k = k2 * 2 + p;
        float v = (c < 168) ? w2[c * 512 + k] : 0.f;
        __nv_bfloat16 h = __float2bfloat16(v);
        g_w2p[0][k2][np] = h;
        g_w2p[1][k2][np] = __float2bfloat16(v - __bfloat162float(h));
    }
    for (int i = idx; i < 2 * K2 * 128; i += stride) {
        ((__nv_bfloat16*)g_xh)[i] = __float2bfloat16(0.f);
        ((__nv_bfloat16*)g_xl)[i] = __float2bfloat16(0.f);
    }
    for (int i = idx; i < CC * BB; i += stride) ((float*)g_qf)[i] = 0.f;
    for (int i = idx; i < 256 * 20; i += stride) {
        int c = i / 20, j = i % 20;
        float v = 0.f;
        if (j < 8) v = lp[c * 8 + j];
        else if (j < 16) v = dw[c * 8 + (j - 8)];
        else if (j == 16) v = db[c];
        else if (j == 17) v = aw[c];
        g_sp[c][j] = v;
    }
    for (int i = idx; i < GRID * 8; i += stride) {
        g_pf[i] = 0u; g_fa[i] = 0u; g_fb[i] = 0u; g_df[i] = 0u; g_fe[i] = 0u;
    }
}

__device__ __forceinline__ void st_pair(int buf, int k, int b, float v) {
    __nv_bfloat16 h = __float2bfloat16(v);
    g_xh[buf][k >> 1][b * 2 + (k & 1)] = h;
    g_xl[buf][k >> 1][b * 2 + (k & 1)] = __float2bfloat16(v - __bfloat162float(h));
}

// bf16 hi/lo MMA GEMM, tile 32b x 16c, K=512 (8 chunks of 32 k2).
__device__ __forceinline__ void mma16(const __nv_bfloat16* ah, const __nv_bfloat16* al,
                                      const __nv_bfloat16* wh, const __nv_bfloat16* wl,
                                      int wstride, int c0, int b0,
                                      const float* bias, int mode,
                                      float* sm, int tid) {
    char* smc = (char*)sm;
    const int BUF = 16384;
    unsigned sbase = (unsigned)__cvta_generic_to_shared(smc);
    int lane = tid & 31;
    int wid = tid >> 5;
    int kz = wid & 3, tile = wid >> 2;
    int mi = tile & 1, ni = tile >> 1;
    int gid = lane >> 2, tig = lane & 3;
    int aoff = (kz * 8 + tig) * 160 + (mi * 16 + gid) * 4;
    int boff = 10240 + (kz * 8 + tig) * 96 + (ni * 8 + gid) * 4;
    float c0r = 0.f, c1r = 0.f, c2r = 0.f, c3r = 0.f;

    #pragma unroll
    for (int pg = 0; pg < 2; pg++) {
        int kc2 = pg * 32;
        if (tid < 512) {
            int grp = tid >> 8, row = (tid >> 3) & 31, seg = tid & 7;
            unsigned dst = sbase + (unsigned)(pg * BUF + grp * 5120 + row * 160 + seg * 16);
            const char* src = (const char*)(grp ? al : ah)
                            + (size_t)(kc2 + row) * 256 + b0 * 4 + seg * 16;
            cpg(dst, src);
        } else if (tid < 768) {
            int u = tid - 512, grp = u >> 7, row = (u >> 2) & 31, seg = u & 3;
            unsigned dst = sbase + (unsigned)(pg * BUF + 10240 + grp * 3072 + row * 96 + seg * 16);
            const char* src = (const char*)(grp ? wl : wh)
                            + (size_t)(kc2 + row) * wstride * 2 + c0 * 4 + seg * 16;
            cpw(dst, src);
        }
        CPC;
    }
    for (int ch = 0; ch < 8; ch++) {
        if (ch < 7) CPW1; else CPW0;
        __syncthreads();
        if (ch + 2 < 8) {
            int kc2 = (ch + 2) * 32, st = (ch + 2) % 3;
            if (tid < 512) {
                int grp = tid >> 8, row = (tid >> 3) & 31, seg = tid & 7;
                unsigned dst = sbase + (unsigned)(st * BUF + grp * 5120 + row * 160 + seg * 16);
                const char* src = (const char*)(grp ? al : ah)
                                + (size_t)(kc2 + row) * 256 + b0 * 4 + seg * 16;
                cpg(dst, src);
            } else if (tid < 768) {
                int u = tid - 512, grp = u >> 7, row = (u >> 2) & 31, seg = u & 3;
                unsigned dst = sbase + (unsigned)(st * BUF + 10240 + grp * 3072 + row * 96 + seg * 16);
                const char* src = (const char*)(grp ? wl : wh)
                                + (size_t)(kc2 + row) * wstride * 2 + c0 * 4 + seg * 16;
                cpw(dst, src);
            }
            CPC;
        }
        if (wid < 16) {
            const char* tb = smc + (ch % 3) * BUF;
            unsigned ah0 = *(const unsigned*)(tb + aoff);
            unsigned ah1 = *(const unsigned*)(tb + aoff + 32);
            unsigned ah2 = *(const unsigned*)(tb + aoff + 640);
            unsigned ah3 = *(const unsigned*)(tb + aoff + 672);
            unsigned al0 = *(const unsigned*)(tb + 5120 + aoff);
            unsigned al1 = *(const unsigned*)(tb + 5120 + aoff + 32);
            unsigned al2 = *(const unsigned*)(tb + 5120 + aoff + 640);
            unsigned al3 = *(const unsigned*)(tb + 5120 + aoff + 672);
            unsigned bh0 = *(const unsigned*)(tb + boff);
            unsigned bh1 = *(const unsigned*)(tb + boff + 384);
            unsigned bl0 = *(const unsigned*)(tb + 3072 + boff);
            unsigned bl1 = *(const unsigned*)(tb + 3072 + boff + 384);
            mma_bf16(c0r, c1r, c2r, c3r, ah0, ah1, ah2, ah3, bh0, bh1);
            mma_bf16(c0r, c1r, c2r, c3r, ah0, ah1, ah2, ah3, bl0, bl1);
            mma_bf16(c0r, c1r, c2r, c3r, al0, al1, al2, al3, bh0, bh1);
        }
    }
    __syncthreads();
    float* red = sm;
    if (wid < 16) {
        int ridx = kz * 544 + (mi * 16 + gid) * 17 + ni * 8 + tig * 2;
        red[ridx] = c0r; red[ridx + 1] = c1r;
        red[ridx + 136] = c2r; red[ridx + 137] = c3r;
    }
    __syncthreads();
    if (tid < 512) {
        int bl = tid & 31, chn = tid >> 5;
        float v = red[bl * 17 + chn] + red[544 + bl * 17 + chn]
                + red[1088 + bl * 17 + chn] + red[1632 + bl * 17 + chn];
        int c = c0 + chn, b = b0 + bl;
        if (mode) {
            v = tanh_fast(v + bias[c]);
            __nv_bfloat16 h = __float2bfloat16(v);
            g_t1p[0][c >> 1][b * 2 + (c & 1)] = h;
            g_t1p[1][c >> 1][b * 2 + (c & 1)] = __float2bfloat16(v - __bfloat162float(h));
        } else {
            g_dk[b][c] = v;
        }
    }
}

__global__ void __launch_bounds__(NTHR)
k_persist(const float* __restrict__ enc, const float* __restrict__ gt,
          const float* __restrict__ mask,
          const float* __restrict__ bi, const float* __restrict__ bh,
          const float* __restrict__ b1,
          const float* __restrict__ lw, const float* __restrict__ prior,
          float* __restrict__ out) {
    extern __shared__ __align__(16) float sm[];
    int bid = blockIdx.x, tid = threadIdx.x;
    int lane = tid & 31, wrp = tid >> 5;

    for (int t = 0;; t++) {
        int buf = t & 1, nbuf = buf ^ 1;
        unsigned gen = (unsigned)(t + 1);
        if (t > 0) pbar(bid, tid, (unsigned)t);

        // ===== Phase A =====
        {
            int b = bid >> 1, half = bid & 1;
            float* s_al  = sm;
            float* s_mx  = sm + 256;
            float* s_sm2 = sm + 288;
            float* s_pt  = sm + 512;

            float a = 0.f, e = 0.f;
            if (t == 0) {
                if (tid < 256) a = (tid == 0) ? 1.f : 0.f;
            } else if (tid < 256) {
                e = __ldcg(&g_energy[b][tid]);
                float m = e;
                #pragma unroll
                for (int o = 16; o; o >>= 1) m = fmaxf(m, __shfl_xor_sync(0xffffffffu, m, o));
                if (lane == 0) s_mx[wrp] = m;
            }
            __syncthreads();
            if (t > 0 && tid < 256) {
                float bm = s_mx[0];
                #pragma unroll
                for (int i = 1; i < 8; i++) bm = fmaxf(bm, s_mx[i]);
                float p = __expf(e - bm);
                float ws = p;
                #pragma unroll
                for (int o = 16; o; o >>= 1) ws += __shfl_xor_sync(0xffffffffu, ws, o);
                if (lane == 0) s_sm2[wrp] = ws;
                a = p;
            }
            __syncthreads();
            if (tid < 256) {
                if (t > 0) {
                    float tot = 0.f;
                    #pragma unroll
                    for (int i = 0; i < 8; i++) tot += s_sm2[i];
                    a = __fdividef(a, tot);
                    if (half == 0) out[((size_t)b * TT + (t - 1)) * SS + tid] = a;
                }
                s_al[tid] = a;
                if (half == 0) g_alpha[b][tid] = a;
            }
            __syncthreads();
            if (t == TT) break;

            if (half == 0 && tid < HH)
                st_pair(buf, tid, b, gt[((size_t)b * TT + t) * HH + tid]);

            int col = tid & 255, slab = tid >> 8;
            const float* ep = enc + ((size_t)b * SS + slab * 64) * 512 + half * 256 + col;
            float acc0 = 0.f, acc1 = 0.f;
            #pragma unroll 8
            for (int s = 0; s < 64; s += 2) {
                acc0 = fmaf(s_al[slab * 64 + s], __ldcg(&ep[(size_t)s * 512]), acc0);
                acc1 = fmaf(s_al[slab * 64 + s + 1], __ldcg(&ep[(size_t)(s + 1) * 512]), acc1);
            }
            s_pt[tid] = acc0 + acc1;
            __syncthreads();
            if (tid < 256) {
                float v = s_pt[tid] + s_pt[256 + tid] + s_pt[512 + tid] + s_pt[768 + tid];
                st_pair(buf, HH + half * 256 + tid, b, v);
            }
        }
        __syncthreads();
        if (tid == 0) st_rel(&g_fa[bid * 8], gen);   // A done (this batch-column)

        // ===== Phase B: wait A flags of own batch-half, then GEMM + gates =====
        {
            int cg = bid >> 1, bt = bid & 1, b0 = bt * 32, c0 = cg * 32;
            if (tid < 64) { while (ld_acq(&g_fa[((bt << 6) + tid) * 8]) < gen) {} }
            __syncthreads();

            char* smc = (char*)sm;
            const int RS = 160, TSZ = 32 * RS, BUF = 4 * TSZ;
            unsigned sbase = (unsigned)__cvta_generic_to_shared(smc);
            int row = (tid >> 3) & 31, seg = tid & 7, grp = tid >> 8;

            int wid2 = tid >> 5;
            int kz = wid2 & 3, tile = wid2 >> 2;
            int mi = tile & 1, ni = tile >> 1;
            int gid = lane >> 2, tig = lane & 3;
            int arow = (kz * 8 + tig) * RS;
            int aoff = arow + (mi * 16 + gid) * 4;
            int boff = arow + (ni * 8 + gid) * 4;
            float c0r = 0.f, c1r = 0.f, c2r = 0.f, c3r = 0.f;

            #pragma unroll
            for (int pg = 0; pg < 2; pg++) {
                int kc2 = pg * 32;
                unsigned dst = sbase + (unsigned)(pg * BUF + grp * TSZ + row * RS + seg * 16);
                const char* src;
                if (grp == 0) src = (const char*)&g_xh[buf][kc2 + row][0] + b0 * 4 + seg * 16;
                else if (grp == 1) src = (const char*)&g_xl[buf][kc2 + row][0] + b0 * 4 + seg * 16;
                else if (grp == 2) src = (const char*)&g_wph[kc2 + row][0] + c0 * 4 + seg * 16;
                else src = (const char*)&g_wpl[kc2 + row][0] + c0 * 4 + seg * 16;
                if (grp < 2) cpg(dst, src); else cpw(dst, src);
                CPC;
            }
            for (int ch = 0; ch < 18; ch++) {
                if (ch < 17) CPW1; else CPW0;
                __syncthreads();
                if (ch + 2 < 18) {
                    int kc2 = (ch + 2) * 32, st = (ch + 2) % 3;
                    unsigned dst = sbase + (unsigned)(st * BUF + grp * TSZ + row * RS + seg * 16);
                    const char* src;
                    if (grp == 0) src = (const char*)&g_xh[buf][kc2 + row][0] + b0 * 4 + seg * 16;
                    else if (grp == 1) src = (const char*)&g_xl[buf][kc2 + row][0] + b0 * 4 + seg * 16;
                    else if (grp == 2) src = (const char*)&g_wph[kc2 + row][0] + c0 * 4 + seg * 16;
                    else src = (const char*)&g_wpl[kc2 + row][0] + c0 * 4 + seg * 16;
                    if (grp < 2) cpg(dst, src); else cpw(dst, src);
                    CPC;
                }
                const char* tb = smc + (ch % 3) * BUF;
                unsigned ah0 = *(const unsigned*)(tb + aoff);
                unsigned ah1 = *(const unsigned*)(tb + aoff + 32);
                unsigned ah2 = *(const unsigned*)(tb + aoff + 640);
                unsigned ah3 = *(const unsigned*)(tb + aoff + 672);
                unsigned al0 = *(const unsigned*)(tb + TSZ + aoff);
                unsigned al1 = *(const unsigned*)(tb + TSZ + aoff + 32);
                unsigned al2 = *(const unsigned*)(tb + TSZ + aoff + 640);
                unsigned al3 = *(const unsigned*)(tb + TSZ + aoff + 672);
                unsigned bh0 = *(const unsigned*)(tb + 2 * TSZ + boff);
                unsigned bh1 = *(const unsigned*)(tb + 2 * TSZ + boff + 640);
                unsigned bl0 = *(const unsigned*)(tb + 3 * TSZ + boff);
                unsigned bl1 = *(const unsigned*)(tb + 3 * TSZ + boff + 640);
                mma_bf16(c0r, c1r, c2r, c3r, ah0, ah1, ah2, ah3, bh0, bh1);
                mma_bf16(c0r, c1r, c2r, c3r, ah0, ah1, ah2, ah3, bl0, bl1);
                mma_bf16(c0r, c1r, c2r, c3r, al0, al1, al2, al3, bh0, bh1);
            }
            __syncthreads();
            float* red = sm;
            int ridx = kz * 1056 + (mi * 16 + gid) * 33 + ni * 8 + tig * 2;
            red[ridx] = c0r; red[ridx + 1] = c1r;
            red[ridx + 8 * 33] = c2r; red[ridx + 8 * 33 + 1] = c3r;
            __syncthreads();
            if (tid < 256) {
                int bl = tid & 31, chn = tid >> 5;
                float G[4];
                #pragma unroll
                for (int g = 0; g < 4; g++)
                    G[g] = red[bl * 33 + chn * 4 + g] + red[1056 + bl * 33 + chn * 4 + g]
                         + red[2112 + bl * 33 + chn * 4 + g] + red[3168 + bl * 33 + chn * 4 + g];
                int ch2 = cg * 8 + chn, bb2 = b0 + bl;
                float qold = __ldcg(&g_qf[ch2][bb2]);
                float rg = sig_fast(G[0] + bi[ch2] + bh[ch2]);
                float zg = sig_fast(G[1] + bi[512 + ch2] + bh[512 + ch2]);
                float ng = tanh_fast(G[2] + bi[1024 + ch2] + rg * (G[3] + bh[1024 + ch2]));
                float qn = (1.f - zg) * ng + zg * qold;
                g_qf[ch2][bb2] = qn;
                st_pair(nbuf, 592 + ch2, bb2, qn);
            }
        }
        __syncthreads();
        if (tid == 0) st_rel(&g_fb[bid * 8], gen);   // B done

        // ===== Phase D (blocks 0-63): wait B flags of own parity, then t1 =====
        if (bid < 64) {
            if (tid < 64) { while (ld_acq(&g_fb[((tid << 1) + (bid & 1)) * 8]) < gen) {} }
            __syncthreads();
            mma16(&g_xh[nbuf][296][0], &g_xl[nbuf][296][0],
                  &g_w1p[0][0][0], &g_w1p[1][0][0], 1024,
                  (bid >> 1) * 16, (bid & 1) * 32, b1, 1, sm, tid);
            __syncthreads();
            if (tid == 0) st_rel(&g_df[bid * 8], gen);
            // ===== Phase E (blocks 0-21): wait all D flags, then dk =====
            if (bid < 22) {
                if (tid < 64) { while (ld_acq(&g_df[tid * 8]) < gen) {} }
                __syncthreads();
                mma16(&g_t1p[0][0][0], &g_t1p[1][0][0],
                      &g_w2p[0][0][0], &g_w2p[1][0][0], 352,
                      (bid >> 1) * 16, (bid & 1) * 32, (const float*)0, 0, sm, tid);
                __syncthreads();
                if (tid == 0) st_rel(&g_fe[bid * 8], gen);
            }
        }

        // ===== Phase F: wait E flags of own half + pair's A flag =====
        {
            int b = bid >> 1, half = bid & 1, s0 = half * 128;
            int par = bid >> 6;   // batch-half parity of this block's b
            if (tid < 11) { while (ld_acq(&g_fe[((tid << 1) + par) * 8]) < gen) {} }
            else if (tid == 16) { while (ld_acq(&g_fa[(bid ^ 1) * 8]) < gen) {} }
            __syncthreads();

            float* s_a   = sm;
            float* s_lw  = sm + 160;
            float* s_dkk = sm + 336;
            float* s_ft  = sm + 512;
            float* s_pri = sm + 2560;
            float* s_sp  = sm + 2688;
            float* s_ps  = sm + 7808;

            if (tid < 148) {
                int s = s0 - 10 + tid;
                s_a[tid] = (s >= 0 && s < SS) ? __ldcg(&g_alpha[b][s]) : 0.f;
            }
            if (tid >= 160 && tid < 328) s_lw[tid - 160] = lw[tid - 160];
            if (tid >= 328 && tid < 496) s_dkk[tid - 328] = __ldcg(&g_dk[b][tid - 328]);
            #pragma unroll
            for (int it = 0; it < 5; it++)
                s_sp[tid + it * 1024] = ((const float*)g_sp)[tid + it * 1024];
            __syncthreads();

            #pragma unroll
            for (int it = 0; it < 2; it++) {
                int u = tid + it * 1024;
                int l = u & 15, si = u >> 4;
                const float* wv = (l < 8) ? &s_lw[l * 21] : &s_dkk[(l - 8) * 21];
                float a = 0.f;
                #pragma unroll
                for (int k = 0; k < 21; k++) a = fmaf(s_a[si + k], wv[k], a);
                s_ft[si * 16 + l] = a;
            }
            if (tid < 128) {
                float a = 0.f;
                #pragma unroll
                for (int k = 0; k < 11; k++) a = fmaf(s_a[tid + k], prior[k], a);
                s_pri[tid] = a;
            }
            __syncthreads();

            int si = tid & 127, sl = tid >> 7;
            const ulonglong2* fp = (const ulonglong2*)&s_ft[si * 16];
            ulonglong2 f01 = fp[0], f23 = fp[1], f45 = fp[2], f67 = fp[3];
            float part = 0.f;
            for (int c = sl * 32; c < sl * 32 + 32; c++) {
                const float* P = &s_sp[c * 20];
                const ulonglong2* pp = (const ulonglong2*)P;
                ulonglong2 p01 = pp[0], p23 = pp[1], p45 = pp[2], p67 = pp[3];
                unsigned long long acc = (unsigned long long)__float_as_uint(P[16]);
                fma2(acc, p01.x, f01.x); fma2(acc, p01.y, f01.y);
                fma2(acc, p23.x, f23.x); fma2(acc, p23.y, f23.y);
                fma2(acc, p45.x, f45.x); fma2(acc, p45.y, f45.y);
                fma2(acc, p67.x, f67.x); fma2(acc, p67.y, f67.y);
                float sc = __uint_as_float((unsigned)acc) +
                           __uint_as_float((unsigned)(acc >> 32));
                part = fmaf(P[17], tanh_fast(sc), part);
            }
            s_ps[sl * 128 + si] = part;
            __syncthreads();
            if (tid < 128) {
                float e = 0.f;
                #pragma unroll
                for (int i = 0; i < 8; i++) e += s_ps[i * 128 + tid];
                e += __logf(s_pri[tid] + 1e-5f);
                int s = s0 + tid;
                e = (mask[b * SS + s] > 0.f) ? e : -INFINITY;
                g_energy[b][s] = e;
            }
        }
    }
}

extern "C" void kernel_launch(void* const* d_in, const int* in_sizes, int n_in,
                              void* d_out, int out_size) {
    const float* enc   = (const float*)d_in[0];
    const float* mask  = (const float*)d_in[1];
    const float* gt    = (const float*)d_in[2];
    const float* wi    = (const float*)d_in[3];
    const float* wh    = (const float*)d_in[4];
    const float* bi    = (const float*)d_in[5];
    const float* bh    = (const float*)d_in[6];
    const float* lw    = (const float*)d_in[7];
    const float* lp    = (const float*)d_in[8];
    const float* w1    = (const float*)d_in[9];
    const float* b1    = (const float*)d_in[10];
    const float* w2    = (const float*)d_in[11];
    const float* dw    = (const float*)d_in[12];
    const float* db    = (const float*)d_in[13];
    const float* aw    = (const float*)d_in[14];
    const float* prior = (const float*)d_in[15];
    float* out = (float*)d_out;

    static int cfg_done = 0;
    if (!cfg_done) {
        cudaFuncSetAttribute(k_persist, cudaFuncAttributeMaxDynamicSharedMemorySize, 65536);
        cfg_done = 1;
    }
    k_init<<<512, 256>>>(wi, wh, w1, w2, lp, dw, db, aw);
    k_persist<<<GRID, NTHR, 65536>>>(enc, gt, mask, bi, bh, b1, lw, prior, out);
}

// round 15
// speedup vs baseline: 2.3942x; 1.0097x over previous
#include <cuda_runtime.h>
#include <cuda_bf16.h>
#include <math.h>

#define BB 64
#define SS 256
#define HH 80
#define TT 600
#define CC 512
#define K2 576
#define GRID 128
#define NTHR 1024

__device__ __nv_bfloat16 g_xh[2][K2][128];
__device__ __nv_bfloat16 g_xl[2][K2][128];
__device__ __nv_bfloat16 g_wph[K2][4096];
__device__ __nv_bfloat16 g_wpl[K2][4096];
__device__ __nv_bfloat16 g_w1p[2][256][1024];
__device__ __nv_bfloat16 g_w2p[2][256][352];
__device__ __nv_bfloat16 g_t1p[2][256][128];
__device__ float g_qf[CC][BB];
__device__ float g_dk[BB][176];
__device__ float g_sp[256][20];
__device__ float g_energy[BB][SS];
__device__ float g_alpha[BB][SS];
__device__ unsigned g_fa[GRID * 8];
__device__ unsigned g_fb[GRID * 8];
__device__ unsigned g_df[GRID * 8];
__device__ unsigned g_fe[GRID * 8];
__device__ unsigned g_ff[GRID * 8];

__device__ __forceinline__ float sig_fast(float x) {
    return __fdividef(1.f, 1.f + __expf(-x));
}
__device__ __forceinline__ float tanh_fast(float x) {
    float e = __expf(2.f * x);
    return 1.f - __fdividef(2.f, e + 1.f);
}
__device__ __forceinline__ void st_rel(unsigned* p, unsigned v) {
    asm volatile("st.release.gpu.global.u32 [%0],%1;" :: "l"(p), "r"(v) : "memory");
}
__device__ __forceinline__ unsigned ld_acq(const unsigned* p) {
    unsigned v;
    asm volatile("ld.acquire.gpu.global.u32 %0,[%1];" : "=r"(v) : "l"(p) : "memory");
    return v;
}
__device__ __forceinline__ void cpg(unsigned d, const void* s) {
    asm volatile("cp.async.cg.shared.global [%0],[%1],16;" :: "r"(d), "l"(s));
}
__device__ __forceinline__ void cpw(unsigned d, const void* s) {
    asm volatile("cp.async.ca.shared.global [%0],[%1],16;" :: "r"(d), "l"(s));
}
#define CPC asm volatile("cp.async.commit_group;" ::: "memory")
#define CPW1 asm volatile("cp.async.wait_group 1;" ::: "memory")
#define CPW0 asm volatile("cp.async.wait_group 0;" ::: "memory")

__device__ __forceinline__ void mma_bf16(float& c0, float& c1, float& c2, float& c3,
                                         unsigned a0, unsigned a1, unsigned a2, unsigned a3,
                                         unsigned b0, unsigned b1) {
    asm volatile("mma.sync.aligned.m16n8k16.row.col.f32.bf16.bf16.f32 "
                 "{%0,%1,%2,%3},{%4,%5,%6,%7},{%8,%9},{%0,%1,%2,%3};"
                 : "+f"(c0), "+f"(c1), "+f"(c2), "+f"(c3)
                 : "r"(a0), "r"(a1), "r"(a2), "r"(a3), "r"(b0), "r"(b1));
}
__device__ __forceinline__ void fma2(unsigned long long& d, unsigned long long a,
                                     unsigned long long b) {
    asm("fma.rn.f32x2 %0, %1, %2, %0;" : "+l"(d) : "l"(a), "l"(b));
}

__global__ void k_init(const float* wi, const float* wh, const float* w1,
                       const float* w2, const float* lp, const float* dw,
                       const float* db, const float* aw) {
    int idx = blockIdx.x * blockDim.x + threadIdx.x;
    int stride = gridDim.x * blockDim.x;
    for (int i = idx; i < K2 * 4096; i += stride) {
        int k2 = i >> 12, np = i & 4095, n = np >> 1, p = np & 1, k = k2 * 2 + p;
        int ch = n >> 2, g = n & 3;
        float v = 0.f;
        if (k < 592) {
            if (g == 0) v = wi[ch * 592 + k];
            else if (g == 1) v = wi[(512 + ch) * 592 + k];
            else if (g == 2) v = wi[(1024 + ch) * 592 + k];
        } else if (k < 1104) {
            int kk = k - 592;
            if (g == 0) v = wh[ch * 512 + kk];
            else if (g == 1) v = wh[(512 + ch) * 512 + kk];
            else if (g == 3) v = wh[(1024 + ch) * 512 + kk];
        }
        __nv_bfloat16 h = __float2bfloat16(v);
        g_wph[k2][np] = h;
        g_wpl[k2][np] = __float2bfloat16(v - __bfloat162float(h));
    }
    for (int i = idx; i < 256 * 1024; i += stride) {
        int k2 = i >> 10, np = i & 1023, c = np >> 1, p = np & 1, k = k2 * 2 + p;
        float v = w1[c * 512 + k];
        __nv_bfloat16 h = __float2bfloat16(v);
        g_w1p[0][k2][np] = h;
        g_w1p[1][k2][np] = __float2bfloat16(v - __bfloat162float(h));
    }
    for (int i = idx; i < 256 * 352; i += stride) {
        int k2 = i / 352, np = i % 352, c = np >> 1, p = np & 1, k = k2 * 2 + p;
        float v = (c < 168) ? w2[c * 512 + k] : 0.f;
        __nv_bfloat16 h = __float2bfloat16(v);
        g_w2p[0][k2][np] = h;
        g_w2p[1][k2][np] = __float2bfloat16(v - __bfloat162float(h));
    }
    for (int i = idx; i < 2 * K2 * 128; i += stride) {
        ((__nv_bfloat16*)g_xh)[i] = __float2bfloat16(0.f);
        ((__nv_bfloat16*)g_xl)[i] = __float2bfloat16(0.f);
    }
    for (int i = idx; i < CC * BB; i += stride) ((float*)g_qf)[i] = 0.f;
    for (int i = idx; i < 256 * 20; i += stride) {
        int c = i / 20, j = i % 20;
        float v = 0.f;
        if (j < 8) v = lp[c * 8 + j];
        else if (j < 16) v = dw[c * 8 + (j - 8)];
        else if (j == 16) v = db[c];
        else if (j == 17) v = aw[c];
        g_sp[c][j] = v;
    }
    for (int i = idx; i < GRID * 8; i += stride) {
        g_fa[i] = 0u; g_fb[i] = 0u; g_df[i] = 0u; g_fe[i] = 0u; g_ff[i] = 0u;
    }
}

__device__ __forceinline__ void st_pair(int buf, int k, int b, float v) {
    __nv_bfloat16 h = __float2bfloat16(v);
    g_xh[buf][k >> 1][b * 2 + (k & 1)] = h;
    g_xl[buf][k >> 1][b * 2 + (k & 1)] = __float2bfloat16(v - __bfloat162float(h));
}

// bf16 hi/lo MMA GEMM, tile 32b x 16c, K=512 (8 chunks of 32 k2).
__device__ __forceinline__ void mma16(const __nv_bfloat16* ah, const __nv_bfloat16* al,
                                      const __nv_bfloat16* wh, const __nv_bfloat16* wl,
                                      int wstride, int c0, int b0,
                                      const float* bias, int mode,
                                      float* sm, int tid) {
    char* smc = (char*)sm;
    const int BUF = 16384;
    unsigned sbase = (unsigned)__cvta_generic_to_shared(smc);
    int lane = tid & 31;
    int wid = tid >> 5;
    int kz = wid & 3, tile = wid >> 2;
    int mi = tile & 1, ni = tile >> 1;
    int gid = lane >> 2, tig = lane & 3;
    int aoff = (kz * 8 + tig) * 160 + (mi * 16 + gid) * 4;
    int boff = 10240 + (kz * 8 + tig) * 96 + (ni * 8 + gid) * 4;
    float c0r = 0.f, c1r = 0.f, c2r = 0.f, c3r = 0.f;

    #pragma unroll
    for (int pg = 0; pg < 2; pg++) {
        int kc2 = pg * 32;
        if (tid < 512) {
            int grp = tid >> 8, row = (tid >> 3) & 31, seg = tid & 7;
            unsigned dst = sbase + (unsigned)(pg * BUF + grp * 5120 + row * 160 + seg * 16);
            const char* src = (const char*)(grp ? al : ah)
                            + (size_t)(kc2 + row) * 256 + b0 * 4 + seg * 16;
            cpg(dst, src);
        } else if (tid < 768) {
            int u = tid - 512, grp = u >> 7, row = (u >> 2) & 31, seg = u & 3;
            unsigned dst = sbase + (unsigned)(pg * BUF + 10240 + grp * 3072 + row * 96 + seg * 16);
            const char* src = (const char*)(grp ? wl : wh)
                            + (size_t)(kc2 + row) * wstride * 2 + c0 * 4 + seg * 16;
            cpw(dst, src);
        }
        CPC;
    }
    for (int ch = 0; ch < 8; ch++) {
        if (ch < 7) CPW1; else CPW0;
        __syncthreads();
        if (ch + 2 < 8) {
            int kc2 = (ch + 2) * 32, st = (ch + 2) % 3;
            if (tid < 512) {
                int grp = tid >> 8, row = (tid >> 3) & 31, seg = tid & 7;
                unsigned dst = sbase + (unsigned)(st * BUF + grp * 5120 + row * 160 + seg * 16);
                const char* src = (const char*)(grp ? al : ah)
                                + (size_t)(kc2 + row) * 256 + b0 * 4 + seg * 16;
                cpg(dst, src);
            } else if (tid < 768) {
                int u = tid - 512, grp = u >> 7, row = (u >> 2) & 31, seg = u & 3;
                unsigned dst = sbase + (unsigned)(st * BUF + 10240 + grp * 3072 + row * 96 + seg * 16);
                const char* src = (const char*)(grp ? wl : wh)
                                + (size_t)(kc2 + row) * wstride * 2 + c0 * 4 + seg * 16;
                cpw(dst, src);
            }
            CPC;
        }
        if (wid < 16) {
            const char* tb = smc + (ch % 3) * BUF;
            unsigned ah0 = *(const unsigned*)(tb + aoff);
            unsigned ah1 = *(const unsigned*)(tb + aoff + 32);
            unsigned ah2 = *(const unsigned*)(tb + aoff + 640);
            unsigned ah3 = *(const unsigned*)(tb + aoff + 672);
            unsigned al0 = *(const unsigned*)(tb + 5120 + aoff);
            unsigned al1 = *(const unsigned*)(tb + 5120 + aoff + 32);
            unsigned al2 = *(const unsigned*)(tb + 5120 + aoff + 640);
            unsigned al3 = *(const unsigned*)(tb + 5120 + aoff + 672);
            unsigned bh0 = *(const unsigned*)(tb + boff);
            unsigned bh1 = *(const unsigned*)(tb + boff + 384);
            unsigned bl0 = *(const unsigned*)(tb + 3072 + boff);
            unsigned bl1 = *(const unsigned*)(tb + 3072 + boff + 384);
            mma_bf16(c0r, c1r, c2r, c3r, ah0, ah1, ah2, ah3, bh0, bh1);
            mma_bf16(c0r, c1r, c2r, c3r, ah0, ah1, ah2, ah3, bl0, bl1);
            mma_bf16(c0r, c1r, c2r, c3r, al0, al1, al2, al3, bh0, bh1);
        }
    }
    __syncthreads();
    float* red = sm;
    if (wid < 16) {
        int ridx = kz * 544 + (mi * 16 + gid) * 17 + ni * 8 + tig * 2;
        red[ridx] = c0r; red[ridx + 1] = c1r;
        red[ridx + 136] = c2r; red[ridx + 137] = c3r;
    }
    __syncthreads();
    if (tid < 512) {
        int bl = tid & 31, chn = tid >> 5;
        float v = red[bl * 17 + chn] + red[544 + bl * 17 + chn]
                + red[1088 + bl * 17 + chn] + red[1632 + bl * 17 + chn];
        int c = c0 + chn, b = b0 + bl;
        if (mode) {
            v = tanh_fast(v + bias[c]);
            __nv_bfloat16 h = __float2bfloat16(v);
            g_t1p[0][c >> 1][b * 2 + (c & 1)] = h;
            g_t1p[1][c >> 1][b * 2 + (c & 1)] = __float2bfloat16(v - __bfloat162float(h));
        } else {
            g_dk[b][c] = v;
        }
    }
}

__global__ void __launch_bounds__(NTHR)
k_persist(const float* __restrict__ enc, const float* __restrict__ gt,
          const float* __restrict__ mask,
          const float* __restrict__ bi, const float* __restrict__ bh,
          const float* __restrict__ b1,
          const float* __restrict__ lw, const float* __restrict__ prior,
          float* __restrict__ out) {
    extern __shared__ __align__(16) float sm[];
    int bid = blockIdx.x, tid = threadIdx.x;
    int lane = tid & 31, wrp = tid >> 5;

    for (int t = 0;; t++) {
        int buf = t & 1, nbuf = buf ^ 1;
        unsigned gen = (unsigned)(t + 1);

        // ===== Phase A: wait pair F(t-1) flags, then softmax + prev ==========
        {
            int b = bid >> 1, half = bid & 1;
            float* s_al  = sm;
            float* s_mx  = sm + 256;
            float* s_sm2 = sm + 288;
            float* s_pt  = sm + 512;

            if (t > 0) {
                if (tid < 2) { while (ld_acq(&g_ff[(bid ^ tid) * 8]) < (unsigned)t) {} }
                __syncthreads();
            }

            float a = 0.f, e = 0.f;
            if (t == 0) {
                if (tid < 256) a = (tid == 0) ? 1.f : 0.f;
            } else if (tid < 256) {
                e = __ldcg(&g_energy[b][tid]);
                float m = e;
                #pragma unroll
                for (int o = 16; o; o >>= 1) m = fmaxf(m, __shfl_xor_sync(0xffffffffu, m, o));
                if (lane == 0) s_mx[wrp] = m;
            }
            __syncthreads();
            if (t > 0 && tid < 256) {
                float bm = s_mx[0];
                #pragma unroll
                for (int i = 1; i < 8; i++) bm = fmaxf(bm, s_mx[i]);
                float p = __expf(e - bm);
                float ws = p;
                #pragma unroll
                for (int o = 16; o; o >>= 1) ws += __shfl_xor_sync(0xffffffffu, ws, o);
                if (lane == 0) s_sm2[wrp] = ws;
                a = p;
            }
            __syncthreads();
            if (tid < 256) {
                if (t > 0) {
                    float tot = 0.f;
                    #pragma unroll
                    for (int i = 0; i < 8; i++) tot += s_sm2[i];
                    a = __fdividef(a, tot);
                    if (half == 0) out[((size_t)b * TT + (t - 1)) * SS + tid] = a;
                }
                s_al[tid] = a;
                if (half == 0) g_alpha[b][tid] = a;
            }
            __syncthreads();
            if (t == TT) break;

            if (half == 0 && tid < HH)
                st_pair(buf, tid, b, gt[((size_t)b * TT + t) * HH + tid]);

            int col = tid & 255, slab = tid >> 8;
            const float* ep = enc + ((size_t)b * SS + slab * 64) * 512 + half * 256 + col;
            float acc0 = 0.f, acc1 = 0.f;
            #pragma unroll 8
            for (int s = 0; s < 64; s += 2) {
                acc0 = fmaf(s_al[slab * 64 + s], __ldcg(&ep[(size_t)s * 512]), acc0);
                acc1 = fmaf(s_al[slab * 64 + s + 1], __ldcg(&ep[(size_t)(s + 1) * 512]), acc1);
            }
            s_pt[tid] = acc0 + acc1;
            __syncthreads();
            if (tid < 256) {
                float v = s_pt[tid] + s_pt[256 + tid] + s_pt[512 + tid] + s_pt[768 + tid];
                st_pair(buf, HH + half * 256 + tid, b, v);
            }
        }
        __syncthreads();
        if (tid == 0) st_rel(&g_fa[bid * 8], gen);   // A done

        // ===== Phase B: early weight prefetch, wait A flags, GEMM + gates =====
        {
            int cg = bid >> 1, bt = bid & 1, b0 = bt * 32, c0 = cg * 32;
            char* smc = (char*)sm;
            const int RS = 160, TSZ = 32 * RS, BUF = 4 * TSZ;
            unsigned sbase = (unsigned)__cvta_generic_to_shared(smc);
            int row = (tid >> 3) & 31, seg = tid & 7, grp = tid >> 8;

            int wid2 = tid >> 5;
            int kz = wid2 & 3, tile = wid2 >> 2;
            int mi = tile & 1, ni = tile >> 1;
            int gid = lane >> 2, tig = lane & 3;
            int arow = (kz * 8 + tig) * RS;
            int aoff = arow + (mi * 16 + gid) * 4;
            int boff = arow + (ni * 8 + gid) * 4;
            float c0r = 0.f, c1r = 0.f, c2r = 0.f, c3r = 0.f;

            // weights (grp 2,3) do not depend on A flags -> prefetch first
            #pragma unroll
            for (int pg = 0; pg < 2; pg++) {
                int kc2 = pg * 32;
                if (grp >= 2) {
                    unsigned dst = sbase + (unsigned)(pg * BUF + grp * TSZ + row * RS + seg * 16);
                    const char* src = (grp == 2)
                        ? (const char*)&g_wph[kc2 + row][0] + c0 * 4 + seg * 16
                        : (const char*)&g_wpl[kc2 + row][0] + c0 * 4 + seg * 16;
                    cpw(dst, src);
                }
                CPC;
            }
            if (tid < 64) { while (ld_acq(&g_fa[((bt << 6) + tid) * 8]) < gen) {} }
            __syncthreads();
            #pragma unroll
            for (int pg = 0; pg < 2; pg++) {
                int kc2 = pg * 32;
                if (grp < 2) {
                    unsigned dst = sbase + (unsigned)(pg * BUF + grp * TSZ + row * RS + seg * 16);
                    const char* src = (grp == 0)
                        ? (const char*)&g_xh[buf][kc2 + row][0] + b0 * 4 + seg * 16
                        : (const char*)&g_xl[buf][kc2 + row][0] + b0 * 4 + seg * 16;
                    cpg(dst, src);
                }
                CPC;
            }
            for (int ch = 0; ch < 18; ch++) {
                if (ch < 17) CPW1; else CPW0;
                __syncthreads();
                if (ch + 2 < 18) {
                    int kc2 = (ch + 2) * 32, st = (ch + 2) % 3;
                    unsigned dst = sbase + (unsigned)(st * BUF + grp * TSZ + row * RS + seg * 16);
                    const char* src;
                    if (grp == 0) src = (const char*)&g_xh[buf][kc2 + row][0] + b0 * 4 + seg * 16;
                    else if (grp == 1) src = (const char*)&g_xl[buf][kc2 + row][0] + b0 * 4 + seg * 16;
                    else if (grp == 2) src = (const char*)&g_wph[kc2 + row][0] + c0 * 4 + seg * 16;
                    else src = (const char*)&g_wpl[kc2 + row][0] + c0 * 4 + seg * 16;
                    if (grp < 2) cpg(dst, src); else cpw(dst, src);
                    CPC;
                }
                const char* tb = smc + (ch % 3) * BUF;
                unsigned ah0 = *(const unsigned*)(tb + aoff);
                unsigned ah1 = *(const unsigned*)(tb + aoff + 32);
                unsigned ah2 = *(const unsigned*)(tb + aoff + 640);
                unsigned ah3 = *(const unsigned*)(tb + aoff + 672);
                unsigned al0 = *(const unsigned*)(tb + TSZ + aoff);
                unsigned al1 = *(const unsigned*)(tb + TSZ + aoff + 32);
                unsigned al2 = *(const unsigned*)(tb + TSZ + aoff + 640);
                unsigned al3 = *(const unsigned*)(tb + TSZ + aoff + 672);
                unsigned bh0 = *(const unsigned*)(tb + 2 * TSZ + boff);
                unsigned bh1 = *(const unsigned*)(tb + 2 * TSZ + boff + 640);
                unsigned bl0 = *(const unsigned*)(tb + 3 * TSZ + boff);
                unsigned bl1 = *(const unsigned*)(tb + 3 * TSZ + boff + 640);
                mma_bf16(c0r, c1r, c2r, c3r, ah0, ah1, ah2, ah3, bh0, bh1);
                mma_bf16(c0r, c1r, c2r, c3r, ah0, ah1, ah2, ah3, bl0, bl1);
                mma_bf16(c0r, c1r, c2r, c3r, al0, al1, al2, al3, bh0, bh1);
            }
            __syncthreads();
            float* red = sm;
            int ridx = kz * 1056 + (mi * 16 + gid) * 33 + ni * 8 + tig * 2;
            red[ridx] = c0r; red[ridx + 1] = c1r;
            red[ridx + 8 * 33] = c2r; red[ridx + 8 * 33 + 1] = c3r;
            __syncthreads();
            if (tid < 256) {
                int bl = tid & 31, chn = tid >> 5;
                float G[4];
                #pragma unroll
                for (int g = 0; g < 4; g++)
                    G[g] = red[bl * 33 + chn * 4 + g] + red[1056 + bl * 33 + chn * 4 + g]
                         + red[2112 + bl * 33 + chn * 4 + g] + red[3168 + bl * 33 + chn * 4 + g];
                int ch2 = cg * 8 + chn, bb2 = b0 + bl;
                float qold = __ldcg(&g_qf[ch2][bb2]);
                float rg = sig_fast(G[0] + bi[ch2] + bh[ch2]);
                float zg = sig_fast(G[1] + bi[512 + ch2] + bh[512 + ch2]);
                float ng = tanh_fast(G[2] + bi[1024 + ch2] + rg * (G[3] + bh[1024 + ch2]));
                float qn = (1.f - zg) * ng + zg * qold;
                g_qf[ch2][bb2] = qn;
                st_pair(nbuf, 592 + ch2, bb2, qn);
            }
        }
        __syncthreads();
        if (tid == 0) st_rel(&g_fb[bid * 8], gen);   // B done

        // ===== Phase D (blocks 0-63): wait B parity flags + E(t-1) flags ======
        if (bid < 64) {
            if (tid < 64) { while (ld_acq(&g_fb[((tid << 1) + (bid & 1)) * 8]) < gen) {} }
            else if (tid >= 64 && tid < 86) {
                while (ld_acq(&g_fe[(tid - 64) * 8]) < gen - 1u) {}  // t1p WAR guard
            }
            __syncthreads();
            mma16(&g_xh[nbuf][296][0], &g_xl[nbuf][296][0],
                  &g_w1p[0][0][0], &g_w1p[1][0][0], 1024,
                  (bid >> 1) * 16, (bid & 1) * 32, b1, 1, sm, tid);
            __syncthreads();
            if (tid == 0) st_rel(&g_df[bid * 8], gen);
            // ===== Phase E (blocks 0-21): wait all D flags =====
            if (bid < 22) {
                if (tid < 64) { while (ld_acq(&g_df[tid * 8]) < gen) {} }
                __syncthreads();
                mma16(&g_t1p[0][0][0], &g_t1p[1][0][0],
                      &g_w2p[0][0][0], &g_w2p[1][0][0], 352,
                      (bid >> 1) * 16, (bid & 1) * 32, (const float*)0, 0, sm, tid);
                __syncthreads();
                if (tid == 0) st_rel(&g_fe[bid * 8], gen);
            }
        }

        // ===== Phase F: constants first, then wait E + pair-A flags ===========
        {
            int b = bid >> 1, half = bid & 1, s0 = half * 128;
            int par = bid >> 6;
            float* s_a   = sm;
            float* s_lw  = sm + 160;
            float* s_dkk = sm + 336;
            float* s_ft  = sm + 512;
            float* s_pri = sm + 2560;
            float* s_sp  = sm + 2688;
            float* s_ps  = sm + 7808;

            if (tid >= 160 && tid < 328) s_lw[tid - 160] = lw[tid - 160];
            #pragma unroll
            for (int it = 0; it < 5; it++)
                s_sp[tid + it * 1024] = ((const float*)g_sp)[tid + it * 1024];
            if (tid < 11) { while (ld_acq(&g_fe[((tid << 1) + par) * 8]) < gen) {} }
            else if (tid == 16) { while (ld_acq(&g_fa[(bid ^ 1) * 8]) < gen) {} }
            __syncthreads();

            if (tid < 148) {
                int s = s0 - 10 + tid;
                s_a[tid] = (s >= 0 && s < SS) ? __ldcg(&g_alpha[b][s]) : 0.f;
            }
            if (tid >= 328 && tid < 496) s_dkk[tid - 328] = __ldcg(&g_dk[b][tid - 328]);
            __syncthreads();

            #pragma unroll
            for (int it = 0; it < 2; it++) {
                int u = tid + it * 1024;
                int l = u & 15, si = u >> 4;
                const float* wv = (l < 8) ? &s_lw[l * 21] : &s_dkk[(l - 8) * 21];
                float a = 0.f;
                #pragma unroll
                for (int k = 0; k < 21; k++) a = fmaf(s_a[si + k], wv[k], a);
                s_ft[si * 16 + l] = a;
            }
            if (tid < 128) {
                float a = 0.f;
                #pragma unroll
                for (int k = 0; k < 11; k++) a = fmaf(s_a[tid + k], prior[k], a);
                s_pri[tid] = a;
            }
            __syncthreads();

            int si = tid & 127, sl = tid >> 7;
            const ulonglong2* fp = (const ulonglong2*)&s_ft[si * 16];
            ulonglong2 f01 = fp[0], f23 = fp[1], f45 = fp[2], f67 = fp[3];
            float part = 0.f;
            for (int c = sl * 32; c < sl * 32 + 32; c++) {
                const float* P = &s_sp[c * 20];
                const ulonglong2* pp = (const ulonglong2*)P;
                ulonglong2 p01 = pp[0], p23 = pp[1], p45 = pp[2], p67 = pp[3];
                unsigned long long acc = (unsigned long long)__float_as_uint(P[16]);
                fma2(acc, p01.x, f01.x); fma2(acc, p01.y, f01.y);
                fma2(acc, p23.x, f23.x); fma2(acc, p23.y, f23.y);
                fma2(acc, p45.x, f45.x); fma2(acc, p45.y, f45.y);
                fma2(acc, p67.x, f67.x); fma2(acc, p67.y, f67.y);
                float sc = __uint_as_float((unsigned)acc) +
                           __uint_as_float((unsigned)(acc >> 32));
                part = fmaf(P[17], tanh_fast(sc), part);
            }
            s_ps[sl * 128 + si] = part;
            __syncthreads();
            if (tid < 128) {
                float e = 0.f;
                #pragma unroll
                for (int i = 0; i < 8; i++) e += s_ps[i * 128 + tid];
                e += __logf(s_pri[tid] + 1e-5f);
                int s = s0 + tid;
                e = (mask[b * SS + s] > 0.f) ? e : -INFINITY;
                g_energy[b][s] = e;
            }
        }
        __syncthreads();
        if (tid == 0) st_rel(&g_ff[bid * 8], gen);   // F done
    }
}

extern "C" void kernel_launch(void* const* d_in, const int* in_sizes, int n_in,
                              void* d_out, int out_size) {
    const float* enc   = (const float*)d_in[0];
    const float* mask  = (const float*)d_in[1];
    const float* gt    = (const float*)d_in[2];
    const float* wi    = (const float*)d_in[3];
    const float* wh    = (const float*)d_in[4];
    const float* bi    = (const float*)d_in[5];
    const float* bh    = (const float*)d_in[6];
    const float* lw    = (const float*)d_in[7];
    const float* lp    = (const float*)d_in[8];
    const float* w1    = (const float*)d_in[9];
    const float* b1    = (const float*)d_in[10];
    const float* w2    = (const float*)d_in[11];
    const float* dw    = (const float*)d_in[12];
    const float* db    = (const float*)d_in[13];
    const float* aw    = (const float*)d_in[14];
    const float* prior = (const float*)d_in[15];
    float* out = (float*)d_out;

    static int cfg_done = 0;
    if (!cfg_done) {
        cudaFuncSetAttribute(k_persist, cudaFuncAttributeMaxDynamicSharedMemorySize, 65536);
        cfg_done = 1;
    }
    k_init<<<512, 256>>>(wi, wh, w1, w2, lp, dw, db, aw);
    k_persist<<<GRID, NTHR, 65536>>>(enc, gt, mask, bi, bh, b1, lw, prior, out);
}

// round 16
// speedup vs baseline: 2.4666x; 1.0302x over previous
#include <cuda_runtime.h>
#include <cuda_bf16.h>
#include <math.h>

#define BB 64
#define SS 256
#define HH 80
#define TT 600
#define CC 512
#define K2 576
#define GRID 128
#define NTHR 1024

__device__ __nv_bfloat16 g_xh[2][K2][128];
__device__ __nv_bfloat16 g_xl[2][K2][128];
__device__ __nv_bfloat16 g_wph[K2][4096];
__device__ __nv_bfloat16 g_wpl[K2][4096];
__device__ __nv_bfloat16 g_w1p[2][256][1024];
__device__ __nv_bfloat16 g_w2p[2][256][352];
__device__ __nv_bfloat16 g_t1p[2][256][128];
__device__ float g_qf[CC][BB];
__device__ float g_dk[BB][176];
__device__ float g_sp[256][20];
__device__ float g_lf[BB][2][128][8];   // loc-conv feats (A -> F, same block)
__device__ float g_pri[BB][2][128];     // prior conv    (A -> F, same block)
__device__ float g_energy[BB][SS];
__device__ float g_alpha[BB][SS];
__device__ unsigned g_fa[GRID * 8];
__device__ unsigned g_fb[GRID * 8];
__device__ unsigned g_df[GRID * 8];
__device__ unsigned g_fe[GRID * 8];
__device__ unsigned g_ff[GRID * 8];

__device__ __forceinline__ float sig_fast(float x) {
    return __fdividef(1.f, 1.f + __expf(-x));
}
__device__ __forceinline__ float tanh_fast(float x) {
    float e = __expf(2.f * x);
    return 1.f - __fdividef(2.f, e + 1.f);
}
__device__ __forceinline__ float tanh_mufu(float x) {
    float r;
    asm("tanh.approx.f32 %0,%1;" : "=f"(r) : "f"(x));
    return r;
}
__device__ __forceinline__ void st_rel(unsigned* p, unsigned v) {
    asm volatile("st.release.gpu.global.u32 [%0],%1;" :: "l"(p), "r"(v) : "memory");
}
__device__ __forceinline__ unsigned ld_acq(const unsigned* p) {
    unsigned v;
    asm volatile("ld.acquire.gpu.global.u32 %0,[%1];" : "=r"(v) : "l"(p) : "memory");
    return v;
}
__device__ __forceinline__ void cpg(unsigned d, const void* s) {
    asm volatile("cp.async.cg.shared.global [%0],[%1],16;" :: "r"(d), "l"(s));
}
__device__ __forceinline__ void cpw(unsigned d, const void* s) {
    asm volatile("cp.async.ca.shared.global [%0],[%1],16;" :: "r"(d), "l"(s));
}
#define CPC asm volatile("cp.async.commit_group;" ::: "memory")
#define CPW1 asm volatile("cp.async.wait_group 1;" ::: "memory")
#define CPW0 asm volatile("cp.async.wait_group 0;" ::: "memory")

__device__ __forceinline__ void mma_bf16(float& c0, float& c1, float& c2, float& c3,
                                         unsigned a0, unsigned a1, unsigned a2, unsigned a3,
                                         unsigned b0, unsigned b1) {
    asm volatile("mma.sync.aligned.m16n8k16.row.col.f32.bf16.bf16.f32 "
                 "{%0,%1,%2,%3},{%4,%5,%6,%7},{%8,%9},{%0,%1,%2,%3};"
                 : "+f"(c0), "+f"(c1), "+f"(c2), "+f"(c3)
                 : "r"(a0), "r"(a1), "r"(a2), "r"(a3), "r"(b0), "r"(b1));
}
__device__ __forceinline__ void fma2(unsigned long long& d, unsigned long long a,
                                     unsigned long long b) {
    asm("fma.rn.f32x2 %0, %1, %2, %0;" : "+l"(d) : "l"(a), "l"(b));
}

__global__ void k_init(const float* wi, const float* wh, const float* w1,
                       const float* w2, const float* lp, const float* dw,
                       const float* db, const float* aw) {
    int idx = blockIdx.x * blockDim.x + threadIdx.x;
    int stride = gridDim.x * blockDim.x;
    for (int i = idx; i < K2 * 4096; i += stride) {
        int k2 = i >> 12, np = i & 4095, n = np >> 1, p = np & 1, k = k2 * 2 + p;
        int ch = n >> 2, g = n & 3;
        float v = 0.f;
        if (k < 592) {
            if (g == 0) v = wi[ch * 592 + k];
            else if (g == 1) v = wi[(512 + ch) * 592 + k];
            else if (g == 2) v = wi[(1024 + ch) * 592 + k];
        } else if (k < 1104) {
            int kk = k - 592;
            if (g == 0) v = wh[ch * 512 + kk];
            else if (g == 1) v = wh[(512 + ch) * 512 + kk];
            else if (g == 3) v = wh[(1024 + ch) * 512 + kk];
        }
        __nv_bfloat16 h = __float2bfloat16(v);
        g_wph[k2][np] = h;
        g_wpl[k2][np] = __float2bfloat16(v - __bfloat162float(h));
    }
    for (int i = idx; i < 256 * 1024; i += stride) {
        int k2 = i >> 10, np = i & 1023, c = np >> 1, p = np & 1, k = k2 * 2 + p;
        float v = w1[c * 512 + k];
        __nv_bfloat16 h = __float2bfloat16(v);
        g_w1p[0][k2][np] = h;
        g_w1p[1][k2][np] = __float2bfloat16(v - __bfloat162float(h));
    }
    for (int i = idx; i < 256 * 352; i += stride) {
        int k2 = i / 352, np = i % 352, c = np >> 1, p = np & 1, k = k2 * 2 + p;
        float v = (c < 168) ? w2[c * 512 + k] : 0.f;
        __nv_bfloat16 h = __float2bfloat16(v);
        g_w2p[0][k2][np] = h;
        g_w2p[1][k2][np] = __float2bfloat16(v - __bfloat162float(h));
    }
    for (int i = idx; i < 2 * K2 * 128; i += stride) {
        ((__nv_bfloat16*)g_xh)[i] = __float2bfloat16(0.f);
        ((__nv_bfloat16*)g_xl)[i] = __float2bfloat16(0.f);
    }
    for (int i = idx; i < CC * BB; i += stride) ((float*)g_qf)[i] = 0.f;
    for (int i = idx; i < 256 * 20; i += stride) {
        int c = i / 20, j = i % 20;
        float v = 0.f;
        if (j < 8) v = lp[c * 8 + j];
        else if (j < 16) v = dw[c * 8 + (j - 8)];
        else if (j == 16) v = db[c];
        else if (j == 17) v = aw[c];
        g_sp[c][j] = v;
    }
    for (int i = idx; i < GRID * 8; i += stride) {
        g_fa[i] = 0u; g_fb[i] = 0u; g_df[i] = 0u; g_fe[i] = 0u; g_ff[i] = 0u;
    }
}

__device__ __forceinline__ void st_pair(int buf, int k, int b, float v) {
    __nv_bfloat16 h = __float2bfloat16(v);
    g_xh[buf][k >> 1][b * 2 + (k & 1)] = h;
    g_xl[buf][k >> 1][b * 2 + (k & 1)] = __float2bfloat16(v - __bfloat162float(h));
}

// bf16 hi/lo MMA GEMM, tile 32b x 16c, K=512 (8 chunks of 32 k2).
__device__ __forceinline__ void mma16(const __nv_bfloat16* ah, const __nv_bfloat16* al,
                                      const __nv_bfloat16* wh, const __nv_bfloat16* wl,
                                      int wstride, int c0, int b0,
                                      const float* bias, int mode,
                                      float* sm, int tid) {
    char* smc = (char*)sm;
    const int BUF = 16384;
    unsigned sbase = (unsigned)__cvta_generic_to_shared(smc);
    int lane = tid & 31;
    int wid = tid >> 5;
    int kz = wid & 3, tile = wid >> 2;
    int mi = tile & 1, ni = tile >> 1;
    int gid = lane >> 2, tig = lane & 3;
    int aoff = (kz * 8 + tig) * 160 + (mi * 16 + gid) * 4;
    int boff = 10240 + (kz * 8 + tig) * 96 + (ni * 8 + gid) * 4;
    float c0r = 0.f, c1r = 0.f, c2r = 0.f, c3r = 0.f;

    #pragma unroll
    for (int pg = 0; pg < 2; pg++) {
        int kc2 = pg * 32;
        if (tid < 512) {
            int grp = tid >> 8, row = (tid >> 3) & 31, seg = tid & 7;
            unsigned dst = sbase + (unsigned)(pg * BUF + grp * 5120 + row * 160 + seg * 16);
            const char* src = (const char*)(grp ? al : ah)
                            + (size_t)(kc2 + row) * 256 + b0 * 4 + seg * 16;
            cpg(dst, src);
        } else if (tid < 768) {
            int u = tid - 512, grp = u >> 7, row = (u >> 2) & 31, seg = u & 3;
            unsigned dst = sbase + (unsigned)(pg * BUF + 10240 + grp * 3072 + row * 96 + seg * 16);
            const char* src = (const char*)(grp ? wl : wh)
                            + (size_t)(kc2 + row) * wstride * 2 + c0 * 4 + seg * 16;
            cpw(dst, src);
        }
        CPC;
    }
    for (int ch = 0; ch < 8; ch++) {
        if (ch < 7) CPW1; else CPW0;
        __syncthreads();
        if (ch + 2 < 8) {
            int kc2 = (ch + 2) * 32, st = (ch + 2) % 3;
            if (tid < 512) {
                int grp = tid >> 8, row = (tid >> 3) & 31, seg = tid & 7;
                unsigned dst = sbase + (unsigned)(st * BUF + grp * 5120 + row * 160 + seg * 16);
                const char* src = (const char*)(grp ? al : ah)
                                + (size_t)(kc2 + row) * 256 + b0 * 4 + seg * 16;
                cpg(dst, src);
            } else if (tid < 768) {
                int u = tid - 512, grp = u >> 7, row = (u >> 2) & 31, seg = u & 3;
                unsigned dst = sbase + (unsigned)(st * BUF + 10240 + grp * 3072 + row * 96 + seg * 16);
                const char* src = (const char*)(grp ? wl : wh)
                                + (size_t)(kc2 + row) * wstride * 2 + c0 * 4 + seg * 16;
                cpw(dst, src);
            }
            CPC;
        }
        if (wid < 16) {
            const char* tb = smc + (ch % 3) * BUF;
            unsigned ah0 = *(const unsigned*)(tb + aoff);
            unsigned ah1 = *(const unsigned*)(tb + aoff + 32);
            unsigned ah2 = *(const unsigned*)(tb + aoff + 640);
            unsigned ah3 = *(const unsigned*)(tb + aoff + 672);
            unsigned al0 = *(const unsigned*)(tb + 5120 + aoff);
            unsigned al1 = *(const unsigned*)(tb + 5120 + aoff + 32);
            unsigned al2 = *(const unsigned*)(tb + 5120 + aoff + 640);
            unsigned al3 = *(const unsigned*)(tb + 5120 + aoff + 672);
            unsigned bh0 = *(const unsigned*)(tb + boff);
            unsigned bh1 = *(const unsigned*)(tb + boff + 384);
            unsigned bl0 = *(const unsigned*)(tb + 3072 + boff);
            unsigned bl1 = *(const unsigned*)(tb + 3072 + boff + 384);
            mma_bf16(c0r, c1r, c2r, c3r, ah0, ah1, ah2, ah3, bh0, bh1);
            mma_bf16(c0r, c1r, c2r, c3r, ah0, ah1, ah2, ah3, bl0, bl1);
            mma_bf16(c0r, c1r, c2r, c3r, al0, al1, al2, al3, bh0, bh1);
        }
    }
    __syncthreads();
    float* red = sm;
    if (wid < 16) {
        int ridx = kz * 544 + (mi * 16 + gid) * 17 + ni * 8 + tig * 2;
        red[ridx] = c0r; red[ridx + 1] = c1r;
        red[ridx + 136] = c2r; red[ridx + 137] = c3r;
    }
    __syncthreads();
    if (tid < 512) {
        int bl = tid & 31, chn = tid >> 5;
        float v = red[bl * 17 + chn] + red[544 + bl * 17 + chn]
                + red[1088 + bl * 17 + chn] + red[1632 + bl * 17 + chn];
        int c = c0 + chn, b = b0 + bl;
        if (mode) {
            v = tanh_fast(v + bias[c]);
            __nv_bfloat16 h = __float2bfloat16(v);
            g_t1p[0][c >> 1][b * 2 + (c & 1)] = h;
            g_t1p[1][c >> 1][b * 2 + (c & 1)] = __float2bfloat16(v - __bfloat162float(h));
        } else {
            g_dk[b][c] = v;
        }
    }
}

__global__ void __launch_bounds__(NTHR)
k_persist(const float* __restrict__ enc, const float* __restrict__ gt,
          const float* __restrict__ mask,
          const float* __restrict__ bi, const float* __restrict__ bh,
          const float* __restrict__ b1,
          const float* __restrict__ lw, const float* __restrict__ prior,
          float* __restrict__ out) {
    extern __shared__ __align__(16) float sm[];
    int bid = blockIdx.x, tid = threadIdx.x;
    int lane = tid & 31, wrp = tid >> 5;

    for (int t = 0;; t++) {
        int buf = t & 1, nbuf = buf ^ 1;
        unsigned gen = (unsigned)(t + 1);

        // ===== Phase A: wait pair F(t-1), softmax, prev, loc-conv + prior =====
        {
            int b = bid >> 1, half = bid & 1;
            float* s_al  = sm;
            float* s_mx  = sm + 256;
            float* s_sm2 = sm + 288;
            float* s_pt  = sm + 512;

            if (t > 0) {
                if (tid < 2) { while (ld_acq(&g_ff[(bid ^ tid) * 8]) < (unsigned)t) {} }
                __syncthreads();
            }

            float a = 0.f, e = 0.f;
            if (t == 0) {
                if (tid < 256) a = (tid == 0) ? 1.f : 0.f;
            } else if (tid < 256) {
                e = __ldcg(&g_energy[b][tid]);
                float m = e;
                #pragma unroll
                for (int o = 16; o; o >>= 1) m = fmaxf(m, __shfl_xor_sync(0xffffffffu, m, o));
                if (lane == 0) s_mx[wrp] = m;
            }
            __syncthreads();
            if (t > 0 && tid < 256) {
                float bm = s_mx[0];
                #pragma unroll
                for (int i = 1; i < 8; i++) bm = fmaxf(bm, s_mx[i]);
                float p = __expf(e - bm);
                float ws = p;
                #pragma unroll
                for (int o = 16; o; o >>= 1) ws += __shfl_xor_sync(0xffffffffu, ws, o);
                if (lane == 0) s_sm2[wrp] = ws;
                a = p;
            }
            __syncthreads();
            if (tid < 256) {
                if (t > 0) {
                    float tot = 0.f;
                    #pragma unroll
                    for (int i = 0; i < 8; i++) tot += s_sm2[i];
                    a = __fdividef(a, tot);
                    if (half == 0) out[((size_t)b * TT + (t - 1)) * SS + tid] = a;
                }
                s_al[tid] = a;
                if (half == 0) g_alpha[b][tid] = a;
            }
            __syncthreads();
            if (t == TT) break;

            if (half == 0 && tid < HH)
                st_pair(buf, tid, b, gt[((size_t)b * TT + t) * HH + tid]);

            // loc-conv feats + prior for this block's F half (same-block handoff)
            {
                int si = tid >> 3, l = tid & 7;
                int sg = half * 128 + si;
                const float* wv = lw + l * 21;
                float acc = 0.f;
                #pragma unroll
                for (int k = 0; k < 21; k++) {
                    int ix = sg - 10 + k;
                    float av = (ix >= 0 && ix < 256) ? s_al[ix] : 0.f;
                    acc = fmaf(av, wv[k], acc);
                }
                g_lf[b][half][si][l] = acc;
                if (tid < 128) {
                    int sg2 = half * 128 + tid;
                    float pr = 0.f;
                    #pragma unroll
                    for (int k = 0; k < 11; k++) {
                        int ix = sg2 - 10 + k;
                        float av = (ix >= 0) ? s_al[ix] : 0.f;
                        pr = fmaf(av, prior[k], pr);
                    }
                    g_pri[b][half][tid] = pr;
                }
            }

            int col = tid & 255, slab = tid >> 8;
            const float* ep = enc + ((size_t)b * SS + slab * 64) * 512 + half * 256 + col;
            float acc0 = 0.f, acc1 = 0.f;
            #pragma unroll 8
            for (int s = 0; s < 64; s += 2) {
                acc0 = fmaf(s_al[slab * 64 + s], __ldcg(&ep[(size_t)s * 512]), acc0);
                acc1 = fmaf(s_al[slab * 64 + s + 1], __ldcg(&ep[(size_t)(s + 1) * 512]), acc1);
            }
            s_pt[tid] = acc0 + acc1;
            __syncthreads();
            if (tid < 256) {
                float v = s_pt[tid] + s_pt[256 + tid] + s_pt[512 + tid] + s_pt[768 + tid];
                st_pair(buf, HH + half * 256 + tid, b, v);
            }
        }
        __syncthreads();
        if (tid == 0) st_rel(&g_fa[bid * 8], gen);   // A done

        // ===== Phase B: early weight prefetch, wait A flags, GEMM + gates =====
        {
            int cg = bid >> 1, bt = bid & 1, b0 = bt * 32, c0 = cg * 32;
            char* smc = (char*)sm;
            const int RS = 160, TSZ = 32 * RS, BUF = 4 * TSZ;
            unsigned sbase = (unsigned)__cvta_generic_to_shared(smc);
            int row = (tid >> 3) & 31, seg = tid & 7, grp = tid >> 8;

            int wid2 = tid >> 5;
            int kz = wid2 & 3, tile = wid2 >> 2;
            int mi = tile & 1, ni = tile >> 1;
            int gid = lane >> 2, tig = lane & 3;
            int arow = (kz * 8 + tig) * RS;
            int aoff = arow + (mi * 16 + gid) * 4;
            int boff = arow + (ni * 8 + gid) * 4;
            float c0r = 0.f, c1r = 0.f, c2r = 0.f, c3r = 0.f;

            #pragma unroll
            for (int pg = 0; pg < 2; pg++) {
                int kc2 = pg * 32;
                if (grp >= 2) {
                    unsigned dst = sbase + (unsigned)(pg * BUF + grp * TSZ + row * RS + seg * 16);
                    const char* src = (grp == 2)
                        ? (const char*)&g_wph[kc2 + row][0] + c0 * 4 + seg * 16
                        : (const char*)&g_wpl[kc2 + row][0] + c0 * 4 + seg * 16;
                    cpw(dst, src);
                }
                CPC;
            }
            if (tid < 64) { while (ld_acq(&g_fa[((bt << 6) + tid) * 8]) < gen) {} }
            __syncthreads();
            #pragma unroll
            for (int pg = 0; pg < 2; pg++) {
                int kc2 = pg * 32;
                if (grp < 2) {
                    unsigned dst = sbase + (unsigned)(pg * BUF + grp * TSZ + row * RS + seg * 16);
                    const char* src = (grp == 0)
                        ? (const char*)&g_xh[buf][kc2 + row][0] + b0 * 4 + seg * 16
                        : (const char*)&g_xl[buf][kc2 + row][0] + b0 * 4 + seg * 16;
                    cpg(dst, src);
                }
                CPC;
            }
            for (int ch = 0; ch < 18; ch++) {
                if (ch < 17) CPW1; else CPW0;
                __syncthreads();
                if (ch + 2 < 18) {
                    int kc2 = (ch + 2) * 32, st = (ch + 2) % 3;
                    unsigned dst = sbase + (unsigned)(st * BUF + grp * TSZ + row * RS + seg * 16);
                    const char* src;
                    if (grp == 0) src = (const char*)&g_xh[buf][kc2 + row][0] + b0 * 4 + seg * 16;
                    else if (grp == 1) src = (const char*)&g_xl[buf][kc2 + row][0] + b0 * 4 + seg * 16;
                    else if (grp == 2) src = (const char*)&g_wph[kc2 + row][0] + c0 * 4 + seg * 16;
                    else src = (const char*)&g_wpl[kc2 + row][0] + c0 * 4 + seg * 16;
                    if (grp < 2) cpg(dst, src); else cpw(dst, src);
                    CPC;
                }
                const char* tb = smc + (ch % 3) * BUF;
                unsigned ah0 = *(const unsigned*)(tb + aoff);
                unsigned ah1 = *(const unsigned*)(tb + aoff + 32);
                unsigned ah2 = *(const unsigned*)(tb + aoff + 640);
                unsigned ah3 = *(const unsigned*)(tb + aoff + 672);
                unsigned al0 = *(const unsigned*)(tb + TSZ + aoff);
                unsigned al1 = *(const unsigned*)(tb + TSZ + aoff + 32);
                unsigned al2 = *(const unsigned*)(tb + TSZ + aoff + 640);
                unsigned al3 = *(const unsigned*)(tb + TSZ + aoff + 672);
                unsigned bh0 = *(const unsigned*)(tb + 2 * TSZ + boff);
                unsigned bh1 = *(const unsigned*)(tb + 2 * TSZ + boff + 640);
                unsigned bl0 = *(const unsigned*)(tb + 3 * TSZ + boff);
                unsigned bl1 = *(const unsigned*)(tb + 3 * TSZ + boff + 640);
                mma_bf16(c0r, c1r, c2r, c3r, ah0, ah1, ah2, ah3, bh0, bh1);
                mma_bf16(c0r, c1r, c2r, c3r, ah0, ah1, ah2, ah3, bl0, bl1);
                mma_bf16(c0r, c1r, c2r, c3r, al0, al1, al2, al3, bh0, bh1);
            }
            __syncthreads();
            float* red = sm;
            int ridx = kz * 1056 + (mi * 16 + gid) * 33 + ni * 8 + tig * 2;
            red[ridx] = c0r; red[ridx + 1] = c1r;
            red[ridx + 8 * 33] = c2r; red[ridx + 8 * 33 + 1] = c3r;
            __syncthreads();
            if (tid < 256) {
                int bl = tid & 31, chn = tid >> 5;
                float G[4];
                #pragma unroll
                for (int g = 0; g < 4; g++)
                    G[g] = red[bl * 33 + chn * 4 + g] + red[1056 + bl * 33 + chn * 4 + g]
                         + red[2112 + bl * 33 + chn * 4 + g] + red[3168 + bl * 33 + chn * 4 + g];
                int ch2 = cg * 8 + chn, bb2 = b0 + bl;
                float qold = __ldcg(&g_qf[ch2][bb2]);
                float rg = sig_fast(G[0] + bi[ch2] + bh[ch2]);
                float zg = sig_fast(G[1] + bi[512 + ch2] + bh[512 + ch2]);
                float ng = tanh_fast(G[2] + bi[1024 + ch2] + rg * (G[3] + bh[1024 + ch2]));
                float qn = (1.f - zg) * ng + zg * qold;
                g_qf[ch2][bb2] = qn;
                st_pair(nbuf, 592 + ch2, bb2, qn);
            }
        }
        __syncthreads();
        if (tid == 0) st_rel(&g_fb[bid * 8], gen);   // B done

        // ===== Phase D (blocks 0-63): wait B parity flags + E(t-1) flags ======
        if (bid < 64) {
            if (tid < 64) { while (ld_acq(&g_fb[((tid << 1) + (bid & 1)) * 8]) < gen) {} }
            else if (tid >= 64 && tid < 86) {
                while (ld_acq(&g_fe[(tid - 64) * 8]) < gen - 1u) {}
            }
            __syncthreads();
            mma16(&g_xh[nbuf][296][0], &g_xl[nbuf][296][0],
                  &g_w1p[0][0][0], &g_w1p[1][0][0], 1024,
                  (bid >> 1) * 16, (bid & 1) * 32, b1, 1, sm, tid);
            __syncthreads();
            if (tid == 0) st_rel(&g_df[bid * 8], gen);
            if (bid < 22) {
                if (tid < 64) { while (ld_acq(&g_df[tid * 8]) < gen) {} }
                __syncthreads();
                mma16(&g_t1p[0][0][0], &g_t1p[1][0][0],
                      &g_w2p[0][0][0], &g_w2p[1][0][0], 352,
                      (bid >> 1) * 16, (bid & 1) * 32, (const float*)0, 0, sm, tid);
                __syncthreads();
                if (tid == 0) st_rel(&g_fe[bid * 8], gen);
            }
        }

        // ===== Phase F: dyn conv + score (tanh.approx) + energy ===============
        {
            int b = bid >> 1, half = bid & 1, s0 = half * 128;
            int par = bid >> 6;
            float* s_a   = sm;
            float* s_dkk = sm + 160;
            float* s_ft  = sm + 512;
            float* s_pri = sm + 2560;
            float* s_sp  = sm + 2688;
            float* s_ps  = sm + 7808;

            // preload constants + own-block A outputs (program order, same SM)
            #pragma unroll
            for (int it = 0; it < 5; it++)
                s_sp[tid + it * 1024] = ((const float*)g_sp)[tid + it * 1024];
            {
                int si = tid >> 3, l = tid & 7;
                s_ft[si * 16 + l] = g_lf[b][half][si][l];
            }
            if (tid < 128) s_pri[tid] = g_pri[b][half][tid];
            if (tid < 11) { while (ld_acq(&g_fe[((tid << 1) + par) * 8]) < gen) {} }
            else if (tid == 16) { while (ld_acq(&g_fa[(bid ^ 1) * 8]) < gen) {} }
            __syncthreads();

            if (tid < 148) {
                int s = s0 - 10 + tid;
                s_a[tid] = (s >= 0 && s < SS) ? __ldcg(&g_alpha[b][s]) : 0.f;
            }
            if (tid >= 328 && tid < 496) s_dkk[tid - 328] = __ldcg(&g_dk[b][tid - 328]);
            __syncthreads();

            {
                int si = tid >> 3, l = tid & 7;
                const float* wv = &s_dkk[l * 21];
                float a = 0.f;
                #pragma unroll
                for (int k = 0; k < 21; k++) a = fmaf(s_a[si + k], wv[k], a);
                s_ft[si * 16 + 8 + l] = a;
            }
            __syncthreads();

            int si = tid & 127, sl = tid >> 7;
            const ulonglong2* fp = (const ulonglong2*)&s_ft[si * 16];
            ulonglong2 f01 = fp[0], f23 = fp[1], f45 = fp[2], f67 = fp[3];
            float part = 0.f;
            for (int c = sl * 32; c < sl * 32 + 32; c++) {
                const float* P = &s_sp[c * 20];
                const ulonglong2* pp = (const ulonglong2*)P;
                ulonglong2 p01 = pp[0], p23 = pp[1], p45 = pp[2], p67 = pp[3];
                unsigned long long acc = (unsigned long long)__float_as_uint(P[16]);
                fma2(acc, p01.x, f01.x); fma2(acc, p01.y, f01.y);
                fma2(acc, p23.x, f23.x); fma2(acc, p23.y, f23.y);
                fma2(acc, p45.x, f45.x); fma2(acc, p45.y, f45.y);
                fma2(acc, p67.x, f67.x); fma2(acc, p67.y, f67.y);
                float sc = __uint_as_float((unsigned)acc) +
                           __uint_as_float((unsigned)(acc >> 32));
                part = fmaf(P[17], tanh_mufu(sc), part);
            }
            s_ps[sl * 128 + si] = part;
            __syncthreads();
            if (tid < 128) {
                float e = 0.f;
                #pragma unroll
                for (int i = 0; i < 8; i++) e += s_ps[i * 128 + tid];
                e += __logf(s_pri[tid] + 1e-5f);
                int s = s0 + tid;
                e = (mask[b * SS + s] > 0.f) ? e : -INFINITY;
                g_energy[b][s] = e;
            }
        }
        __syncthreads();
        if (tid == 0) st_rel(&g_ff[bid * 8], gen);   // F done
    }
}

extern "C" void kernel_launch(void* const* d_in, const int* in_sizes, int n_in,
                              void* d_out, int out_size) {
    const float* enc   = (const float*)d_in[0];
    const float* mask  = (const float*)d_in[1];
    const float* gt    = (const float*)d_in[2];
    const float* wi    = (const float*)d_in[3];
    const float* wh    = (const float*)d_in[4];
    const float* bi    = (const float*)d_in[5];
    const float* bh    = (const float*)d_in[6];
    const float* lw    = (const float*)d_in[7];
    const float* lp    = (const float*)d_in[8];
    const float* w1    = (const float*)d_in[9];
    const float* b1    = (const float*)d_in[10];
    const float* w2    = (const float*)d_in[11];
    const float* dw    = (const float*)d_in[12];
    const float* db    = (const float*)d_in[13];
    const float* aw    = (const float*)d_in[14];
    const float* prior = (const float*)d_in[15];
    float* out = (float*)d_out;

    static int cfg_done = 0;
    if (!cfg_done) {
        cudaFuncSetAttribute(k_persist, cudaFuncAttributeMaxDynamicSharedMemorySize, 65536);
        cfg_done = 1;
    }
    k_init<<<512, 256>>>(wi, wh, w1, w2, lp, dw, db, aw);
    k_persist<<<GRID, NTHR, 65536>>>(enc, gt, mask, bi, bh, b1, lw, prior, out);
}